// round 8
// baseline (speedup 1.0000x reference)
#include <cuda_runtime.h>
#include <cuda_bf16.h>
#include <cuda_fp16.h>
#include <cstdint>
#include <math.h>

#define NN 30000
#define EE 480000
#define F_IN 100
#define HID 64
#define HEADS 4
#define NCLS 47
#define HC 256           // HEADS*HID
#define L2OUT 188        // HEADS*NCLS
#define NP2 256          // padded pack width layer2 (188 + 47 -> 256)
#define K0P 128          // padded K for layer 0 (100 -> 128)
#define NBLK 118         // ceil(NN/256)

// ---------------- scratch ----------------
__device__ __align__(16) float g_h[(size_t)NN * HC];
__device__ __align__(16) float g_skip[(size_t)NN * HC];
__device__ __align__(16) float g_agg[(size_t)NN * HC];
__device__ __align__(16) float g_als[(size_t)NN * HEADS];
__device__ __align__(16) float g_ald[(size_t)NN * HEADS];
__device__ float g_bnsum[2 * HC];
// half-split activations
__device__ __align__(16) __half g_xh[(size_t)NN * K0P];
__device__ __align__(16) __half g_xl[(size_t)NN * K0P];
__device__ __align__(16) __half g_ah[(size_t)NN * HC];
__device__ __align__(16) __half g_al2[(size_t)NN * HC];
// half-split transposed weights [n][k]
__device__ __align__(16) __half g_b0h[512 * K0P];
__device__ __align__(16) __half g_b0l[512 * K0P];
__device__ __align__(16) __half g_b1h[512 * HC];
__device__ __align__(16) __half g_b1l[512 * HC];
__device__ __align__(16) __half g_b2h[NP2 * HC];
__device__ __align__(16) __half g_b2l[NP2 * HC];
// CSR
__device__ int g_cnt[NN];
__device__ int g_part[NN];
__device__ int g_bsum[NBLK];
__device__ int g_rowptr[NN + 1];
__device__ int g_cursor[NN];
__device__ int g_csrc[EE];

__device__ __forceinline__ float lrelu(float x) { return x > 0.f ? x : 0.2f * x; }

__device__ __forceinline__ void split2(float v, __half& hi, __half& lo) {
    hi = __float2half_rn(v);
    lo = __float2half_rn(v - __half2float(hi));
}

// ---------------- convert x to padded hi/lo halves ----------------
__global__ void convert_x(const float* __restrict__ x, __half* __restrict__ xh,
                          __half* __restrict__ xl)
{
    int idx = blockIdx.x * 256 + threadIdx.x;
    if (idx >= NN * K0P) return;
    int n = idx >> 7, c = idx & (K0P - 1);
    float v = (c < F_IN) ? x[n * F_IN + c] : 0.f;
    __half hi, lo; split2(v, hi, lo);
    xh[idx] = hi; xl[idx] = lo;
}

// ---------------- pack weights -> transposed hi/lo halves ----------------
__global__ void pack_weights(const float* __restrict__ w0, const float* __restrict__ sw0,
                             const float* __restrict__ w1, const float* __restrict__ sw1,
                             const float* __restrict__ w2, const float* __restrict__ sw2,
                             __half* __restrict__ b0h, __half* __restrict__ b0l,
                             __half* __restrict__ b1h, __half* __restrict__ b1l,
                             __half* __restrict__ b2h, __half* __restrict__ b2l)
{
    int tid = blockIdx.x * blockDim.x + threadIdx.x;
    int stride = gridDim.x * blockDim.x;
    for (int i = tid; i < 512 * K0P; i += stride) {
        int n = i >> 7, k = i & (K0P - 1);
        float v = 0.f;
        if (k < F_IN) v = (n < HC) ? w0[k * HC + n] : sw0[k * HC + (n - HC)];
        __half hi, lo; split2(v, hi, lo);
        b0h[i] = hi; b0l[i] = lo;
    }
    for (int i = tid; i < 512 * HC; i += stride) {
        int n = i >> 8, k = i & (HC - 1);
        float v = (n < HC) ? w1[k * HC + n] : sw1[k * HC + (n - HC)];
        __half hi, lo; split2(v, hi, lo);
        b1h[i] = hi; b1l[i] = lo;
    }
    for (int i = tid; i < NP2 * HC; i += stride) {
        int n = i >> 8, k = i & (HC - 1);
        float v = 0.f;
        if (n < L2OUT) v = w2[k * L2OUT + n];
        else if (n < L2OUT + NCLS) v = sw2[k * NCLS + (n - L2OUT)];
        __half hi, lo; split2(v, hi, lo);
        b2h[i] = hi; b2l[i] = lo;
    }
}

// ---------------- CSR build ----------------
__global__ void count_kernel(const int* __restrict__ dst, int* __restrict__ cnt)
{
    int e = blockIdx.x * blockDim.x + threadIdx.x;
    if (e < EE) atomicAdd(&cnt[dst[e]], 1);
}

__global__ void scan_blocks(const int* __restrict__ cnt, int* __restrict__ part,
                            int* __restrict__ bsum)
{
    int t = threadIdx.x;
    int i = blockIdx.x * 256 + t;
    int lane = t & 31, wid = t >> 5;
    int v = (i < NN) ? cnt[i] : 0;
    int x = v;
#pragma unroll
    for (int off = 1; off < 32; off <<= 1) {
        int y = __shfl_up_sync(0xffffffffu, x, off);
        if (lane >= off) x += y;
    }
    __shared__ int wsum[8];
    if (lane == 31) wsum[wid] = x;
    __syncthreads();
    if (wid == 0 && lane < 8) {
        int w = wsum[lane];
#pragma unroll
        for (int off = 1; off < 8; off <<= 1) {
            int y = __shfl_up_sync(0xffu, w, off);
            if (lane >= off) w += y;
        }
        wsum[lane] = w;
    }
    __syncthreads();
    int base = (wid > 0) ? wsum[wid - 1] : 0;
    int incl = x + base;
    if (i < NN) part[i] = incl - v;
    if (t == 255) bsum[blockIdx.x] = incl;
}

__global__ void scan_totals(int* __restrict__ bsum)
{
    int t = threadIdx.x;
    int lane = t & 31, wid = t >> 5;
    int v = (t < NBLK) ? bsum[t] : 0;
    int x = v;
#pragma unroll
    for (int off = 1; off < 32; off <<= 1) {
        int y = __shfl_up_sync(0xffffffffu, x, off);
        if (lane >= off) x += y;
    }
    __shared__ int wsum[4];
    if (lane == 31) wsum[wid] = x;
    __syncthreads();
    if (wid == 0 && lane < 4) {
        int w = wsum[lane];
#pragma unroll
        for (int off = 1; off < 4; off <<= 1) {
            int y = __shfl_up_sync(0xfu, w, off);
            if (lane >= off) w += y;
        }
        wsum[lane] = w;
    }
    __syncthreads();
    int base = (wid > 0) ? wsum[wid - 1] : 0;
    if (t < NBLK) bsum[t] = x + base - v;
}

__global__ void scan_add(const int* __restrict__ part, const int* __restrict__ bsum,
                         int* __restrict__ rowptr, int* __restrict__ cursor)
{
    int i = blockIdx.x * 256 + threadIdx.x;
    if (i < NN) {
        int r = part[i] + bsum[i >> 8];
        rowptr[i] = r;
        cursor[i] = r;
    }
    if (i == NN) rowptr[NN] = EE;
}

__global__ void fill_kernel(const int* __restrict__ src, const int* __restrict__ dst,
                            int* __restrict__ cursor, int* __restrict__ csrc)
{
    int e = blockIdx.x * blockDim.x + threadIdx.x;
    if (e >= EE) return;
    int d = dst[e];
    int pos = atomicAdd(&cursor[d], 1);
    csrc[pos] = src[e];
}

// ---------------- tensor-core GEMM: cp.async + ldmatrix + double buffer ------
#define BM 128
#define BN 128
#define BKK 32
#define BKP 40          // padded K stride in halves (80B rows, conflict-free ldmatrix)
#define OAH 0
#define OAL 5120
#define OBH 10240
#define OBL 15360
#define STGH 20480      // halves per stage
#define SMEM_GEMM (2 * STGH * 2)   // bytes

__device__ __forceinline__ void mma16816(float* d, const unsigned* a, const unsigned* b)
{
    asm volatile(
        "mma.sync.aligned.m16n8k16.row.col.f32.f16.f16.f32 "
        "{%0,%1,%2,%3}, {%4,%5,%6,%7}, {%8,%9}, {%0,%1,%2,%3};"
        : "+f"(d[0]), "+f"(d[1]), "+f"(d[2]), "+f"(d[3])
        : "r"(a[0]), "r"(a[1]), "r"(a[2]), "r"(a[3]), "r"(b[0]), "r"(b[1]));
}

__device__ __forceinline__ void cp16(unsigned dst, const void* src, int sz)
{
    asm volatile("cp.async.ca.shared.global [%0], [%1], 16, %2;"
                 :: "r"(dst), "l"(src), "r"(sz));
}

__device__ __forceinline__ void ldm4(unsigned addr, unsigned& r0, unsigned& r1,
                                     unsigned& r2, unsigned& r3)
{
    asm volatile("ldmatrix.sync.aligned.m8n8.x4.shared.b16 {%0,%1,%2,%3}, [%4];"
                 : "=r"(r0), "=r"(r1), "=r"(r2), "=r"(r3) : "r"(addr));
}

__device__ __forceinline__ void issue_stage(
    unsigned sb, const __half* Ah, const __half* Al,
    const __half* Bh, const __half* Bl,
    int rowBlock, int colBlock, int M, int KA, int k0, int sr, int sk)
{
#pragma unroll
    for (int i = 0; i < 2; i++) {
        int row = sr + i * 64;
        int gr = rowBlock + row;
        int sz = (gr < M) ? 16 : 0;
        size_t off = (size_t)(sz ? gr : 0) * KA + k0 + sk;
        cp16(sb + (unsigned)(OAH + row * BKP + sk) * 2, Ah + off, sz);
        cp16(sb + (unsigned)(OAL + row * BKP + sk) * 2, Al + off, sz);
        int gc = colBlock + row;                    // Npack padded: always valid
        size_t boff = (size_t)gc * KA + k0 + sk;
        cp16(sb + (unsigned)(OBH + row * BKP + sk) * 2, Bh + boff, 16);
        cp16(sb + (unsigned)(OBL + row * BKP + sk) * 2, Bl + boff, 16);
    }
    asm volatile("cp.async.commit_group;");
}

__global__ __launch_bounds__(256, 2) void hgemm_split(
    const __half* __restrict__ Ah, const __half* __restrict__ Al,
    const __half* __restrict__ Bh, const __half* __restrict__ Bl,
    const float* __restrict__ sbias, float* __restrict__ hOut, float* __restrict__ skipOut,
    int M, int KA, int Npack, int splitH, int splitS)
{
    extern __shared__ __half sm[];
    unsigned smB = (unsigned)__cvta_generic_to_shared(sm);

    int tid = threadIdx.x;
    int lane = tid & 31, wid = tid >> 5;
    int rowBlock = blockIdx.y * BM;
    int colBlock = blockIdx.x * BN;
    int wm = (wid & 1) * 64;
    int wn = (wid >> 1) * 32;
    int gID = lane >> 2, tig = lane & 3;

    float acc[4][4][4];
#pragma unroll
    for (int mt = 0; mt < 4; mt++)
#pragma unroll
        for (int nt = 0; nt < 4; nt++)
#pragma unroll
            for (int r = 0; r < 4; r++) acc[mt][nt][r] = 0.f;

    int kIters = KA >> 5;
    int sr = tid >> 2;
    int sk = (tid & 3) * 8;

    int aRow = (lane & 15);
    int aCol = (lane & 16) >> 1;
    int bNrow = (lane & 7) + ((lane & 16) >> 1);
    int bCol = (lane & 8);

    issue_stage(smB, Ah, Al, Bh, Bl, rowBlock, colBlock, M, KA, 0, sr, sk);

    for (int it = 0; it < kIters; it++) {
        int cur = it & 1;
        if (it + 1 < kIters) {
            issue_stage(smB + (unsigned)(cur ^ 1) * STGH * 2, Ah, Al, Bh, Bl,
                        rowBlock, colBlock, M, KA, (it + 1) * BKK, sr, sk);
            asm volatile("cp.async.wait_group 1;");
        } else {
            asm volatile("cp.async.wait_group 0;");
        }
        __syncthreads();

        unsigned aHb = smB + (unsigned)cur * STGH * 2;
        unsigned aLb = aHb + OAL * 2;
        unsigned bHb = aHb + OBH * 2;
        unsigned bLb = aHb + OBL * 2;

#pragma unroll
        for (int ks = 0; ks < 2; ks++) {
            int kk = ks * 16;
            // load B fragments (hi + lo)
            unsigned bHf[8], bLf[8];
#pragma unroll
            for (int pair = 0; pair < 2; pair++) {
                int n = wn + pair * 16 + bNrow;
                unsigned off = (unsigned)(n * BKP + kk + bCol) * 2;
                ldm4(bHb + off, bHf[pair * 4 + 0], bHf[pair * 4 + 1],
                                bHf[pair * 4 + 2], bHf[pair * 4 + 3]);
                ldm4(bLb + off, bLf[pair * 4 + 0], bLf[pair * 4 + 1],
                                bLf[pair * 4 + 2], bLf[pair * 4 + 3]);
            }
            // load ALL A-hi fragments
            unsigned aHf[4][4];
#pragma unroll
            for (int mt = 0; mt < 4; mt++) {
                int r = wm + mt * 16 + aRow;
                unsigned off = (unsigned)(r * BKP + kk + aCol) * 2;
                ldm4(aHb + off, aHf[mt][0], aHf[mt][1], aHf[mt][2], aHf[mt][3]);
            }
            // pass 1: HH — 16 independent MMAs (acc reuse distance 16)
#pragma unroll
            for (int mt = 0; mt < 4; mt++)
#pragma unroll
                for (int nt = 0; nt < 4; nt++)
                    mma16816(acc[mt][nt], aHf[mt], &bHf[(nt >> 1) * 4 + (nt & 1) * 2]);
            // pass 2: HL
#pragma unroll
            for (int mt = 0; mt < 4; mt++)
#pragma unroll
                for (int nt = 0; nt < 4; nt++)
                    mma16816(acc[mt][nt], aHf[mt], &bLf[(nt >> 1) * 4 + (nt & 1) * 2]);
            // pass 3: LH — A-lo loaded lazily per mt (keeps regs under 128)
#pragma unroll
            for (int mt = 0; mt < 4; mt++) {
                int r = wm + mt * 16 + aRow;
                unsigned off = (unsigned)(r * BKP + kk + aCol) * 2;
                unsigned aLf[4];
                ldm4(aLb + off, aLf[0], aLf[1], aLf[2], aLf[3]);
#pragma unroll
                for (int nt = 0; nt < 4; nt++)
                    mma16816(acc[mt][nt], aLf, &bHf[(nt >> 1) * 4 + (nt & 1) * 2]);
            }
        }
        __syncthreads();
    }

    // epilogue: route to hOut / skipOut(+sbias)
#pragma unroll
    for (int mt = 0; mt < 4; mt++) {
        int gr0 = rowBlock + wm + mt * 16 + gID;
        int gr1 = gr0 + 8;
#pragma unroll
        for (int nt = 0; nt < 4; nt++) {
            int gc = colBlock + wn + nt * 8 + tig * 2;
#pragma unroll
            for (int half_ = 0; half_ < 2; half_++) {
                int gr = half_ ? gr1 : gr0;
                if (gr >= M) continue;
#pragma unroll
                for (int j = 0; j < 2; j++) {
                    int c = gc + j;
                    float v = acc[mt][nt][half_ * 2 + j];
                    if (c < splitH) {
                        hOut[(size_t)gr * splitH + c] = v;
                    } else if (c < splitH + splitS) {
                        int sc = c - splitH;
                        skipOut[(size_t)gr * splitS + sc] = v + sbias[sc];
                    }
                }
            }
        }
    }
}

// ---------------- attention logits ----------------
__global__ void al_kernel(const float* __restrict__ h, const float* __restrict__ a_s,
                          const float* __restrict__ a_d, float* __restrict__ als,
                          float* __restrict__ ald, int C)
{
    int w = (blockIdx.x * blockDim.x + threadIdx.x) >> 5;
    int lane = threadIdx.x & 31;
    if (w >= NN * HEADS) return;
    int n = w >> 2, hd = w & 3;
    const float* hp = h + (size_t)n * (HEADS * C) + hd * C;
    float ss = 0.f, sd = 0.f;
    for (int c = lane; c < C; c += 32) {
        float v = hp[c];
        ss = fmaf(v, a_s[hd * C + c], ss);
        sd = fmaf(v, a_d[hd * C + c], sd);
    }
#pragma unroll
    for (int o = 16; o; o >>= 1) {
        ss += __shfl_xor_sync(0xffffffffu, ss, o);
        sd += __shfl_xor_sync(0xffffffffu, sd, o);
    }
    if (lane == 0) { als[w] = ss; ald[w] = sd; }
}

// ---------------- fused GAT agg + bias + skip + BN-stats (layers 0/1) --------
__global__ __launch_bounds__(256) void gat_agg_kernel(
    const int* __restrict__ rowptr, const int* __restrict__ csrc,
    const float* __restrict__ h, const float* __restrict__ als,
    const float* __restrict__ ald, const float* __restrict__ bias,
    const float* __restrict__ skip, float* __restrict__ outp, float* __restrict__ sums)
{
    __shared__ float slabS[8][HC];
    __shared__ float slabQ[8][HC];
    int tid = threadIdx.x;
    int w = (blockIdx.x * 256 + tid) >> 5;
    int lane = tid & 31;
    int wid = tid >> 5;
    int head = lane >> 3;
    float ad = ald[w * 4 + head];
    int beg = rowptr[w], end = rowptr[w + 1];
    float4 acc0 = make_float4(0.f, 0.f, 0.f, 0.f);
    float4 acc1 = make_float4(0.f, 0.f, 0.f, 0.f);
    float den = 0.f;
    int i = beg;
    int lo2 = lane * 2;
    for (; i + 4 <= end; i += 4) {
        int s0 = csrc[i], s1 = csrc[i + 1], s2 = csrc[i + 2], s3 = csrc[i + 3];
        float A0 = als[s0 * 4 + head], A1 = als[s1 * 4 + head];
        float A2 = als[s2 * 4 + head], A3 = als[s3 * 4 + head];
        const float4* h0 = (const float4*)(h + (size_t)s0 * HC) + lo2;
        const float4* h1 = (const float4*)(h + (size_t)s1 * HC) + lo2;
        const float4* h2 = (const float4*)(h + (size_t)s2 * HC) + lo2;
        const float4* h3 = (const float4*)(h + (size_t)s3 * HC) + lo2;
        float4 x00 = h0[0], x01 = h0[1];
        float4 x10 = h1[0], x11 = h1[1];
        float4 x20 = h2[0], x21 = h2[1];
        float4 x30 = h3[0], x31 = h3[1];
        float e0 = expf(lrelu(A0 + ad));
        float e1 = expf(lrelu(A1 + ad));
        float e2 = expf(lrelu(A2 + ad));
        float e3 = expf(lrelu(A3 + ad));
        den += (e0 + e1) + (e2 + e3);
        acc0.x = fmaf(e0, x00.x, acc0.x); acc0.y = fmaf(e0, x00.y, acc0.y);
        acc0.z = fmaf(e0, x00.z, acc0.z); acc0.w = fmaf(e0, x00.w, acc0.w);
        acc1.x = fmaf(e0, x01.x, acc1.x); acc1.y = fmaf(e0, x01.y, acc1.y);
        acc1.z = fmaf(e0, x01.z, acc1.z); acc1.w = fmaf(e0, x01.w, acc1.w);
        acc0.x = fmaf(e1, x10.x, acc0.x); acc0.y = fmaf(e1, x10.y, acc0.y);
        acc0.z = fmaf(e1, x10.z, acc0.z); acc0.w = fmaf(e1, x10.w, acc0.w);
        acc1.x = fmaf(e1, x11.x, acc1.x); acc1.y = fmaf(e1, x11.y, acc1.y);
        acc1.z = fmaf(e1, x11.z, acc1.z); acc1.w = fmaf(e1, x11.w, acc1.w);
        acc0.x = fmaf(e2, x20.x, acc0.x); acc0.y = fmaf(e2, x20.y, acc0.y);
        acc0.z = fmaf(e2, x20.z, acc0.z); acc0.w = fmaf(e2, x20.w, acc0.w);
        acc1.x = fmaf(e2, x21.x, acc1.x); acc1.y = fmaf(e2, x21.y, acc1.y);
        acc1.z = fmaf(e2, x21.z, acc1.z); acc1.w = fmaf(e2, x21.w, acc1.w);
        acc0.x = fmaf(e3, x30.x, acc0.x); acc0.y = fmaf(e3, x30.y, acc0.y);
        acc0.z = fmaf(e3, x30.z, acc0.z); acc0.w = fmaf(e3, x30.w, acc0.w);
        acc1.x = fmaf(e3, x31.x, acc1.x); acc1.y = fmaf(e3, x31.y, acc1.y);
        acc1.z = fmaf(e3, x31.z, acc1.z); acc1.w = fmaf(e3, x31.w, acc1.w);
    }
    for (; i < end; i++) {
        int s = csrc[i];
        float e = expf(lrelu(als[s * 4 + head] + ad));
        den += e;
        const float4* hp = (const float4*)(h + (size_t)s * HC) + lo2;
        float4 v0 = hp[0], v1 = hp[1];
        acc0.x = fmaf(e, v0.x, acc0.x); acc0.y = fmaf(e, v0.y, acc0.y);
        acc0.z = fmaf(e, v0.z, acc0.z); acc0.w = fmaf(e, v0.w, acc0.w);
        acc1.x = fmaf(e, v1.x, acc1.x); acc1.y = fmaf(e, v1.y, acc1.y);
        acc1.z = fmaf(e, v1.z, acc1.z); acc1.w = fmaf(e, v1.w, acc1.w);
    }
    float inv = 1.f / (den + 1e-16f);
    int cbase = lane * 8;
    size_t obase = (size_t)w * HC + cbase;
    const float4* bp = (const float4*)(bias + cbase);
    const float4* sp = (const float4*)(skip + obase);
    float4 b0 = bp[0], b1 = bp[1];
    float4 s0 = sp[0], s1 = sp[1];
    float4 o0, o1;
    o0.x = fmaf(acc0.x, inv, b0.x + s0.x); o0.y = fmaf(acc0.y, inv, b0.y + s0.y);
    o0.z = fmaf(acc0.z, inv, b0.z + s0.z); o0.w = fmaf(acc0.w, inv, b0.w + s0.w);
    o1.x = fmaf(acc1.x, inv, b1.x + s1.x); o1.y = fmaf(acc1.y, inv, b1.y + s1.y);
    o1.z = fmaf(acc1.z, inv, b1.z + s1.z); o1.w = fmaf(acc1.w, inv, b1.w + s1.w);
    float4* op = (float4*)(outp + obase);
    op[0] = o0; op[1] = o1;

    // BN partials: per-warp exclusive slabs (no atomics), then one block reduce
    *(float4*)&slabS[wid][cbase] = o0;
    *(float4*)&slabS[wid][cbase + 4] = o1;
    float4 q0 = make_float4(o0.x * o0.x, o0.y * o0.y, o0.z * o0.z, o0.w * o0.w);
    float4 q1 = make_float4(o1.x * o1.x, o1.y * o1.y, o1.z * o1.z, o1.w * o1.w);
    *(float4*)&slabQ[wid][cbase] = q0;
    *(float4*)&slabQ[wid][cbase + 4] = q1;
    __syncthreads();
    float s = 0.f, q = 0.f;
#pragma unroll
    for (int ww = 0; ww < 8; ww++) { s += slabS[ww][tid]; q += slabQ[ww][tid]; }
    atomicAdd(&sums[tid], s);
    atomicAdd(&sums[HC + tid], q);
}

// ---------------- layer 2: agg + mean heads + bias + skip + log_softmax ------
__global__ __launch_bounds__(256) void gat_agg47_fused(
    const int* __restrict__ rowptr, const int* __restrict__ csrc,
    const float* __restrict__ h, const float4* __restrict__ als,
    const float4* __restrict__ ald, const float* __restrict__ b2,
    const float* __restrict__ skip47, float* __restrict__ outp)
{
    int w = (blockIdx.x * blockDim.x + threadIdx.x) >> 5;
    int lane = threadIdx.x & 31;
    if (w >= NN) return;
    float4 ad = ald[w];
    int beg = rowptr[w], end = rowptr[w + 1];
    float a0 = 0.f, a1 = 0.f, a2 = 0.f, a3 = 0.f;
    float c0 = 0.f, c1 = 0.f, c2 = 0.f, c3 = 0.f;
    float d0 = 0.f, d1 = 0.f, d2 = 0.f, d3 = 0.f;
    bool has2 = (lane + 32) < NCLS;
    int i = beg;
    for (; i + 2 <= end; i += 2) {
        int sA = csrc[i], sB = csrc[i + 1];
        float4 aA = als[sA], aB = als[sB];
        const float* hA = h + (size_t)sA * L2OUT;
        const float* hB = h + (size_t)sB * L2OUT;
        float pA0 = hA[lane], pA1 = hA[NCLS + lane], pA2 = hA[2 * NCLS + lane], pA3 = hA[3 * NCLS + lane];
        float pB0 = hB[lane], pB1 = hB[NCLS + lane], pB2 = hB[2 * NCLS + lane], pB3 = hB[3 * NCLS + lane];
        float qA0 = 0.f, qA1 = 0.f, qA2 = 0.f, qA3 = 0.f;
        float qB0 = 0.f, qB1 = 0.f, qB2 = 0.f, qB3 = 0.f;
        if (has2) {
            int c = lane + 32;
            qA0 = hA[c]; qA1 = hA[NCLS + c]; qA2 = hA[2 * NCLS + c]; qA3 = hA[3 * NCLS + c];
            qB0 = hB[c]; qB1 = hB[NCLS + c]; qB2 = hB[2 * NCLS + c]; qB3 = hB[3 * NCLS + c];
        }
        float eA0 = expf(lrelu(aA.x + ad.x)), eA1 = expf(lrelu(aA.y + ad.y));
        float eA2 = expf(lrelu(aA.z + ad.z)), eA3 = expf(lrelu(aA.w + ad.w));
        float eB0 = expf(lrelu(aB.x + ad.x)), eB1 = expf(lrelu(aB.y + ad.y));
        float eB2 = expf(lrelu(aB.z + ad.z)), eB3 = expf(lrelu(aB.w + ad.w));
        d0 += eA0 + eB0; d1 += eA1 + eB1; d2 += eA2 + eB2; d3 += eA3 + eB3;
        a0 = fmaf(eA0, pA0, fmaf(eB0, pB0, a0));
        a1 = fmaf(eA1, pA1, fmaf(eB1, pB1, a1));
        a2 = fmaf(eA2, pA2, fmaf(eB2, pB2, a2));
        a3 = fmaf(eA3, pA3, fmaf(eB3, pB3, a3));
        c0 = fmaf(eA0, qA0, fmaf(eB0, qB0, c0));
        c1 = fmaf(eA1, qA1, fmaf(eB1, qB1, c1));
        c2 = fmaf(eA2, qA2, fmaf(eB2, qB2, c2));
        c3 = fmaf(eA3, qA3, fmaf(eB3, qB3, c3));
    }
    for (; i < end; i++) {
        int s = csrc[i];
        float4 as4 = als[s];
        float e0 = expf(lrelu(as4.x + ad.x));
        float e1 = expf(lrelu(as4.y + ad.y));
        float e2 = expf(lrelu(as4.z + ad.z));
        float e3 = expf(lrelu(as4.w + ad.w));
        d0 += e0; d1 += e1; d2 += e2; d3 += e3;
        const float* hs = h + (size_t)s * L2OUT;
        a0 = fmaf(e0, hs[lane], a0);
        a1 = fmaf(e1, hs[NCLS + lane], a1);
        a2 = fmaf(e2, hs[2 * NCLS + lane], a2);
        a3 = fmaf(e3, hs[3 * NCLS + lane], a3);
        if (has2) {
            int c = lane + 32;
            c0 = fmaf(e0, hs[c], c0);
            c1 = fmaf(e1, hs[NCLS + c], c1);
            c2 = fmaf(e2, hs[2 * NCLS + c], c2);
            c3 = fmaf(e3, hs[3 * NCLS + c], c3);
        }
    }
    float i0 = 1.f / (d0 + 1e-16f), i1 = 1.f / (d1 + 1e-16f);
    float i2 = 1.f / (d2 + 1e-16f), i3 = 1.f / (d3 + 1e-16f);
    float v0 = 0.25f * (a0 * i0 + a1 * i1 + a2 * i2 + a3 * i3)
             + b2[lane] + skip47[(size_t)w * NCLS + lane];
    float v1 = -1e30f;
    if (has2) {
        int c = lane + 32;
        v1 = 0.25f * (c0 * i0 + c1 * i1 + c2 * i2 + c3 * i3)
           + b2[c] + skip47[(size_t)w * NCLS + c];
    }
    float m = fmaxf(v0, v1);
#pragma unroll
    for (int o = 16; o; o >>= 1) m = fmaxf(m, __shfl_xor_sync(0xffffffffu, m, o));
    float s = expf(v0 - m) + (has2 ? expf(v1 - m) : 0.f);
#pragma unroll
    for (int o = 16; o; o >>= 1) s += __shfl_xor_sync(0xffffffffu, s, o);
    float lse = m + logf(s);
    outp[(size_t)w * NCLS + lane] = v0 - lse;
    if (has2) outp[(size_t)w * NCLS + lane + 32] = v1 - lse;
}

// ---------------- BN apply + ELU -> hi/lo halves for next GEMM ---------------
__global__ void bn_apply_kernel(const float* __restrict__ pre, const float* __restrict__ sums,
                                const float* __restrict__ gamma, const float* __restrict__ beta,
                                __half* __restrict__ oh, __half* __restrict__ ol)
{
    int c = threadIdx.x;
    float mu = sums[c] * (1.f / NN);
    float var = sums[HC + c] * (1.f / NN) - mu * mu;
    float rstd = rsqrtf(var + 1e-5f);
    float g = gamma[c] * rstd;
    float b = beta[c] - mu * g;
    for (int r = blockIdx.x; r < NN; r += gridDim.x) {
        size_t idx = (size_t)r * HC + c;
        float v = fmaf(pre[idx], g, b);
        float o = v > 0.f ? v : expf(v) - 1.f;
        __half hi, lo; split2(o, hi, lo);
        oh[idx] = hi; ol[idx] = lo;
    }
}

// ---------------- host orchestration ----------------
extern "C" void kernel_launch(void* const* d_in, const int* in_sizes, int n_in,
                              void* d_out, int out_size)
{
    const float* x   = (const float*)d_in[0];
    const int*   ei  = (const int*)d_in[1];
    const float* w0  = (const float*)d_in[2];
    const float* as0 = (const float*)d_in[3];
    const float* ad0 = (const float*)d_in[4];
    const float* b0  = (const float*)d_in[5];
    const float* sw0 = (const float*)d_in[6];
    const float* sb0 = (const float*)d_in[7];
    const float* g0  = (const float*)d_in[8];
    const float* be0 = (const float*)d_in[9];
    const float* w1  = (const float*)d_in[10];
    const float* as1 = (const float*)d_in[11];
    const float* ad1 = (const float*)d_in[12];
    const float* b1  = (const float*)d_in[13];
    const float* sw1 = (const float*)d_in[14];
    const float* sb1 = (const float*)d_in[15];
    const float* g1  = (const float*)d_in[16];
    const float* be1 = (const float*)d_in[17];
    const float* w2  = (const float*)d_in[18];
    const float* as2 = (const float*)d_in[19];
    const float* ad2 = (const float*)d_in[20];
    const float* b2  = (const float*)d_in[21];
    const float* sw2 = (const float*)d_in[22];
    const float* sb2 = (const float*)d_in[23];

    const int* src = ei;
    const int* dst = ei + EE;

    float *h, *skip, *agg, *als, *ald, *bnsum;
    __half *xh, *xl, *ah, *al2, *b0h, *b0l, *b1h, *b1l, *b2h, *b2l;
    int *cnt, *part, *bsum, *rowptr, *cursor, *csrc;
    cudaGetSymbolAddress((void**)&h, g_h);
    cudaGetSymbolAddress((void**)&skip, g_skip);
    cudaGetSymbolAddress((void**)&agg, g_agg);
    cudaGetSymbolAddress((void**)&als, g_als);
    cudaGetSymbolAddress((void**)&ald, g_ald);
    cudaGetSymbolAddress((void**)&bnsum, g_bnsum);
    cudaGetSymbolAddress((void**)&xh, g_xh);
    cudaGetSymbolAddress((void**)&xl, g_xl);
    cudaGetSymbolAddress((void**)&ah, g_ah);
    cudaGetSymbolAddress((void**)&al2, g_al2);
    cudaGetSymbolAddress((void**)&b0h, g_b0h);
    cudaGetSymbolAddress((void**)&b0l, g_b0l);
    cudaGetSymbolAddress((void**)&b1h, g_b1h);
    cudaGetSymbolAddress((void**)&b1l, g_b1l);
    cudaGetSymbolAddress((void**)&b2h, g_b2h);
    cudaGetSymbolAddress((void**)&b2l, g_b2l);
    cudaGetSymbolAddress((void**)&cnt, g_cnt);
    cudaGetSymbolAddress((void**)&part, g_part);
    cudaGetSymbolAddress((void**)&bsum, g_bsum);
    cudaGetSymbolAddress((void**)&rowptr, g_rowptr);
    cudaGetSymbolAddress((void**)&cursor, g_cursor);
    cudaGetSymbolAddress((void**)&csrc, g_csrc);

    cudaFuncSetAttribute(hgemm_split, cudaFuncAttributeMaxDynamicSharedMemorySize, SMEM_GEMM);

    dim3 gemm512(4, (NN + BM - 1) / BM);
    dim3 gemm256(2, (NN + BM - 1) / BM);
    int alBlocks = (NN * HEADS * 32 + 255) / 256;
    int nodeWarpBlocks = (NN * 32) / 256;
    int eBlocks = (EE + 255) / 256;

    // launch order keeps hgemm layer-0 as the 5th launch (profiler target)
    convert_x<<<(NN * K0P + 255) / 256, 256>>>(x, xh, xl);                     // 1
    pack_weights<<<480, 256>>>(w0, sw0, w1, sw1, w2, sw2,
                               b0h, b0l, b1h, b1l, b2h, b2l);                  // 2
    cudaMemsetAsync(cnt, 0, NN * sizeof(int));                                 // 3
    count_kernel<<<eBlocks, 256>>>(dst, cnt);                                  // 4
    hgemm_split<<<gemm512, 256, SMEM_GEMM>>>(xh, xl, b0h, b0l, sb0, h, skip,
                                             NN, K0P, 512, HC, HC);            // 5
    scan_blocks<<<NBLK, 256>>>(cnt, part, bsum);
    scan_totals<<<1, 128>>>(bsum);
    scan_add<<<(NN + 256) / 256, 256>>>(part, bsum, rowptr, cursor);
    fill_kernel<<<eBlocks, 256>>>(src, dst, cursor, csrc);

    // ===== Layer 0 (agg + BN) =====
    al_kernel<<<alBlocks, 256>>>(h, as0, ad0, als, ald, HID);
    cudaMemsetAsync(bnsum, 0, 2 * HC * sizeof(float));
    gat_agg_kernel<<<nodeWarpBlocks, 256>>>(rowptr, csrc, h, als, ald, b0, skip, agg, bnsum);
    bn_apply_kernel<<<512, 256>>>(agg, bnsum, g0, be0, ah, al2);

    // ===== Layer 1 =====
    hgemm_split<<<gemm512, 256, SMEM_GEMM>>>(ah, al2, b1h, b1l, sb1, h, skip, NN, HC, 512, HC, HC);
    al_kernel<<<alBlocks, 256>>>(h, as1, ad1, als, ald, HID);
    cudaMemsetAsync(bnsum, 0, 2 * HC * sizeof(float));
    gat_agg_kernel<<<nodeWarpBlocks, 256>>>(rowptr, csrc, h, als, ald, b1, skip, agg, bnsum);
    bn_apply_kernel<<<512, 256>>>(agg, bnsum, g1, be1, ah, al2);

    // ===== Layer 2 =====
    hgemm_split<<<gemm256, 256, SMEM_GEMM>>>(ah, al2, b2h, b2l, sb2, h, skip, NN, HC, NP2, L2OUT, NCLS);
    al_kernel<<<alBlocks, 256>>>(h, as2, ad2, als, ald, NCLS);
    gat_agg47_fused<<<nodeWarpBlocks, 256>>>(rowptr, csrc, h, (const float4*)als,
                                             (const float4*)ald, b2, skip, (float*)d_out);
}

// round 9
// speedup vs baseline: 1.1164x; 1.1164x over previous
#include <cuda_runtime.h>
#include <cuda_bf16.h>
#include <cuda_fp16.h>
#include <cstdint>
#include <math.h>

#define NN 30000
#define EE 480000
#define F_IN 100
#define HID 64
#define HEADS 4
#define NCLS 47
#define HC 256           // HEADS*HID
#define L2OUT 188        // HEADS*NCLS
#define NP2 256          // padded pack width layer2 (188 + 47 -> 256)
#define K0P 128          // padded K for layer 0 (100 -> 128)
#define NBLK 118         // ceil(NN/256)

// ---------------- scratch ----------------
__device__ __align__(16) float g_h[(size_t)NN * HC];
__device__ __align__(16) float g_skip[(size_t)NN * HC];
__device__ __align__(16) float g_agg[(size_t)NN * HC];
__device__ __align__(16) float g_als[(size_t)NN * HEADS];
__device__ __align__(16) float g_ald[(size_t)NN * HEADS];
__device__ float g_bnsum[2 * HC];
// fp16 activations (A-side: hi only — 2-term split)
__device__ __align__(16) __half g_xh[(size_t)NN * K0P];
__device__ __align__(16) __half g_ah[(size_t)NN * HC];
// half-split transposed weights [n][k] (B-side keeps hi+lo)
__device__ __align__(16) __half g_b0h[512 * K0P];
__device__ __align__(16) __half g_b0l[512 * K0P];
__device__ __align__(16) __half g_b1h[512 * HC];
__device__ __align__(16) __half g_b1l[512 * HC];
__device__ __align__(16) __half g_b2h[NP2 * HC];
__device__ __align__(16) __half g_b2l[NP2 * HC];
// CSR
__device__ int g_cnt[NN];
__device__ int g_part[NN];
__device__ int g_bsum[NBLK];
__device__ int g_rowptr[NN + 1];
__device__ int g_cursor[NN];
__device__ int g_csrc[EE];

__device__ __forceinline__ float lrelu(float x) { return x > 0.f ? x : 0.2f * x; }

__device__ __forceinline__ void split2(float v, __half& hi, __half& lo) {
    hi = __float2half_rn(v);
    lo = __float2half_rn(v - __half2float(hi));
}

// ---------------- convert x to padded fp16 ----------------
__global__ void convert_x(const float* __restrict__ x, __half* __restrict__ xh)
{
    int idx = blockIdx.x * 256 + threadIdx.x;
    if (idx >= NN * K0P) return;
    int n = idx >> 7, c = idx & (K0P - 1);
    float v = (c < F_IN) ? x[n * F_IN + c] : 0.f;
    xh[idx] = __float2half_rn(v);
}

// ---------------- pack weights -> transposed hi/lo halves ----------------
__global__ void pack_weights(const float* __restrict__ w0, const float* __restrict__ sw0,
                             const float* __restrict__ w1, const float* __restrict__ sw1,
                             const float* __restrict__ w2, const float* __restrict__ sw2,
                             __half* __restrict__ b0h, __half* __restrict__ b0l,
                             __half* __restrict__ b1h, __half* __restrict__ b1l,
                             __half* __restrict__ b2h, __half* __restrict__ b2l)
{
    int tid = blockIdx.x * blockDim.x + threadIdx.x;
    int stride = gridDim.x * blockDim.x;
    for (int i = tid; i < 512 * K0P; i += stride) {
        int n = i >> 7, k = i & (K0P - 1);
        float v = 0.f;
        if (k < F_IN) v = (n < HC) ? w0[k * HC + n] : sw0[k * HC + (n - HC)];
        __half hi, lo; split2(v, hi, lo);
        b0h[i] = hi; b0l[i] = lo;
    }
    for (int i = tid; i < 512 * HC; i += stride) {
        int n = i >> 8, k = i & (HC - 1);
        float v = (n < HC) ? w1[k * HC + n] : sw1[k * HC + (n - HC)];
        __half hi, lo; split2(v, hi, lo);
        b1h[i] = hi; b1l[i] = lo;
    }
    for (int i = tid; i < NP2 * HC; i += stride) {
        int n = i >> 8, k = i & (HC - 1);
        float v = 0.f;
        if (n < L2OUT) v = w2[k * L2OUT + n];
        else if (n < L2OUT + NCLS) v = sw2[k * NCLS + (n - L2OUT)];
        __half hi, lo; split2(v, hi, lo);
        b2h[i] = hi; b2l[i] = lo;
    }
}

// ---------------- CSR build ----------------
__global__ void count_kernel(const int* __restrict__ dst, int* __restrict__ cnt)
{
    int e = blockIdx.x * blockDim.x + threadIdx.x;
    if (e < EE) atomicAdd(&cnt[dst[e]], 1);
}

__global__ void scan_blocks(const int* __restrict__ cnt, int* __restrict__ part,
                            int* __restrict__ bsum)
{
    int t = threadIdx.x;
    int i = blockIdx.x * 256 + t;
    int lane = t & 31, wid = t >> 5;
    int v = (i < NN) ? cnt[i] : 0;
    int x = v;
#pragma unroll
    for (int off = 1; off < 32; off <<= 1) {
        int y = __shfl_up_sync(0xffffffffu, x, off);
        if (lane >= off) x += y;
    }
    __shared__ int wsum[8];
    if (lane == 31) wsum[wid] = x;
    __syncthreads();
    if (wid == 0 && lane < 8) {
        int w = wsum[lane];
#pragma unroll
        for (int off = 1; off < 8; off <<= 1) {
            int y = __shfl_up_sync(0xffu, w, off);
            if (lane >= off) w += y;
        }
        wsum[lane] = w;
    }
    __syncthreads();
    int base = (wid > 0) ? wsum[wid - 1] : 0;
    int incl = x + base;
    if (i < NN) part[i] = incl - v;
    if (t == 255) bsum[blockIdx.x] = incl;
}

__global__ void scan_totals(int* __restrict__ bsum)
{
    int t = threadIdx.x;
    int lane = t & 31, wid = t >> 5;
    int v = (t < NBLK) ? bsum[t] : 0;
    int x = v;
#pragma unroll
    for (int off = 1; off < 32; off <<= 1) {
        int y = __shfl_up_sync(0xffffffffu, x, off);
        if (lane >= off) x += y;
    }
    __shared__ int wsum[4];
    if (lane == 31) wsum[wid] = x;
    __syncthreads();
    if (wid == 0 && lane < 4) {
        int w = wsum[lane];
#pragma unroll
        for (int off = 1; off < 4; off <<= 1) {
            int y = __shfl_up_sync(0xfu, w, off);
            if (lane >= off) w += y;
        }
        wsum[lane] = w;
    }
    __syncthreads();
    int base = (wid > 0) ? wsum[wid - 1] : 0;
    if (t < NBLK) bsum[t] = x + base - v;
}

__global__ void scan_add(const int* __restrict__ part, const int* __restrict__ bsum,
                         int* __restrict__ rowptr, int* __restrict__ cursor)
{
    int i = blockIdx.x * 256 + threadIdx.x;
    if (i < NN) {
        int r = part[i] + bsum[i >> 8];
        rowptr[i] = r;
        cursor[i] = r;
    }
    if (i == NN) rowptr[NN] = EE;
}

__global__ void fill_kernel(const int* __restrict__ src, const int* __restrict__ dst,
                            int* __restrict__ cursor, int* __restrict__ csrc)
{
    int e = blockIdx.x * blockDim.x + threadIdx.x;
    if (e >= EE) return;
    int d = dst[e];
    int pos = atomicAdd(&cursor[d], 1);
    csrc[pos] = src[e];
}

// ---------------- tensor-core GEMM: cp.async + ldmatrix + double buffer ------
// 2-term split: C ≈ A_fp16 @ (Bhi + Blo)
#define BM 128
#define BN 128
#define BKK 32
#define BKP 40          // padded K stride in halves (80B rows, conflict-free ldmatrix)
#define OAH 0
#define OBH 5120
#define OBL 10240
#define STGH 15360      // halves per stage
#define SMEM_GEMM (2 * STGH * 2)   // bytes = 61440

__device__ __forceinline__ void mma16816(float* d, const unsigned* a, const unsigned* b)
{
    asm volatile(
        "mma.sync.aligned.m16n8k16.row.col.f32.f16.f16.f32 "
        "{%0,%1,%2,%3}, {%4,%5,%6,%7}, {%8,%9}, {%0,%1,%2,%3};"
        : "+f"(d[0]), "+f"(d[1]), "+f"(d[2]), "+f"(d[3])
        : "r"(a[0]), "r"(a[1]), "r"(a[2]), "r"(a[3]), "r"(b[0]), "r"(b[1]));
}

__device__ __forceinline__ void cp16(unsigned dst, const void* src, int sz)
{
    asm volatile("cp.async.ca.shared.global [%0], [%1], 16, %2;"
                 :: "r"(dst), "l"(src), "r"(sz));
}

__device__ __forceinline__ void ldm4(unsigned addr, unsigned& r0, unsigned& r1,
                                     unsigned& r2, unsigned& r3)
{
    asm volatile("ldmatrix.sync.aligned.m8n8.x4.shared.b16 {%0,%1,%2,%3}, [%4];"
                 : "=r"(r0), "=r"(r1), "=r"(r2), "=r"(r3) : "r"(addr));
}

__device__ __forceinline__ void issue_stage(
    unsigned sb, const __half* Ah,
    const __half* Bh, const __half* Bl,
    int rowBlock, int colBlock, int M, int KA, int k0, int sr, int sk)
{
#pragma unroll
    for (int i = 0; i < 2; i++) {
        int row = sr + i * 64;
        int gr = rowBlock + row;
        int sz = (gr < M) ? 16 : 0;
        size_t off = (size_t)(sz ? gr : 0) * KA + k0 + sk;
        cp16(sb + (unsigned)(OAH + row * BKP + sk) * 2, Ah + off, sz);
        int gc = colBlock + row;                    // Npack padded: always valid
        size_t boff = (size_t)gc * KA + k0 + sk;
        cp16(sb + (unsigned)(OBH + row * BKP + sk) * 2, Bh + boff, 16);
        cp16(sb + (unsigned)(OBL + row * BKP + sk) * 2, Bl + boff, 16);
    }
    asm volatile("cp.async.commit_group;");
}

__global__ __launch_bounds__(256, 2) void hgemm_split(
    const __half* __restrict__ Ah,
    const __half* __restrict__ Bh, const __half* __restrict__ Bl,
    const float* __restrict__ sbias, float* __restrict__ hOut, float* __restrict__ skipOut,
    int M, int KA, int Npack, int splitH, int splitS)
{
    extern __shared__ __half sm[];
    unsigned smB = (unsigned)__cvta_generic_to_shared(sm);

    int tid = threadIdx.x;
    int lane = tid & 31, wid = tid >> 5;
    int rowBlock = blockIdx.y * BM;
    int colBlock = blockIdx.x * BN;
    int wm = (wid & 1) * 64;
    int wn = (wid >> 1) * 32;
    int gID = lane >> 2, tig = lane & 3;

    float acc[4][4][4];
#pragma unroll
    for (int mt = 0; mt < 4; mt++)
#pragma unroll
        for (int nt = 0; nt < 4; nt++)
#pragma unroll
            for (int r = 0; r < 4; r++) acc[mt][nt][r] = 0.f;

    int kIters = KA >> 5;
    int sr = tid >> 2;
    int sk = (tid & 3) * 8;

    int aRow = (lane & 15);
    int aCol = (lane & 16) >> 1;
    int bNrow = (lane & 7) + ((lane & 16) >> 1);
    int bCol = (lane & 8);

    issue_stage(smB, Ah, Bh, Bl, rowBlock, colBlock, M, KA, 0, sr, sk);

    for (int it = 0; it < kIters; it++) {
        int cur = it & 1;
        if (it + 1 < kIters) {
            issue_stage(smB + (unsigned)(cur ^ 1) * STGH * 2, Ah, Bh, Bl,
                        rowBlock, colBlock, M, KA, (it + 1) * BKK, sr, sk);
            asm volatile("cp.async.wait_group 1;");
        } else {
            asm volatile("cp.async.wait_group 0;");
        }
        __syncthreads();

        unsigned aHb = smB + (unsigned)cur * STGH * 2;
        unsigned bHb = aHb + OBH * 2;
        unsigned bLb = aHb + OBL * 2;

#pragma unroll
        for (int ks = 0; ks < 2; ks++) {
            int kk = ks * 16;
            // load B fragments (hi + lo)
            unsigned bHf[8], bLf[8];
#pragma unroll
            for (int pair = 0; pair < 2; pair++) {
                int n = wn + pair * 16 + bNrow;
                unsigned off = (unsigned)(n * BKP + kk + bCol) * 2;
                ldm4(bHb + off, bHf[pair * 4 + 0], bHf[pair * 4 + 1],
                                bHf[pair * 4 + 2], bHf[pair * 4 + 3]);
                ldm4(bLb + off, bLf[pair * 4 + 0], bLf[pair * 4 + 1],
                                bLf[pair * 4 + 2], bLf[pair * 4 + 3]);
            }
            // load A fragments
            unsigned aHf[4][4];
#pragma unroll
            for (int mt = 0; mt < 4; mt++) {
                int r = wm + mt * 16 + aRow;
                unsigned off = (unsigned)(r * BKP + kk + aCol) * 2;
                ldm4(aHb + off, aHf[mt][0], aHf[mt][1], aHf[mt][2], aHf[mt][3]);
            }
            // pass 1: A @ B-hi
#pragma unroll
            for (int mt = 0; mt < 4; mt++)
#pragma unroll
                for (int nt = 0; nt < 4; nt++)
                    mma16816(acc[mt][nt], aHf[mt], &bHf[(nt >> 1) * 4 + (nt & 1) * 2]);
            // pass 2: A @ B-lo
#pragma unroll
            for (int mt = 0; mt < 4; mt++)
#pragma unroll
                for (int nt = 0; nt < 4; nt++)
                    mma16816(acc[mt][nt], aHf[mt], &bLf[(nt >> 1) * 4 + (nt & 1) * 2]);
        }
        __syncthreads();
    }

    // epilogue: route to hOut / skipOut(+sbias)
#pragma unroll
    for (int mt = 0; mt < 4; mt++) {
        int gr0 = rowBlock + wm + mt * 16 + gID;
        int gr1 = gr0 + 8;
#pragma unroll
        for (int nt = 0; nt < 4; nt++) {
            int gc = colBlock + wn + nt * 8 + tig * 2;
#pragma unroll
            for (int half_ = 0; half_ < 2; half_++) {
                int gr = half_ ? gr1 : gr0;
                if (gr >= M) continue;
#pragma unroll
                for (int j = 0; j < 2; j++) {
                    int c = gc + j;
                    float v = acc[mt][nt][half_ * 2 + j];
                    if (c < splitH) {
                        hOut[(size_t)gr * splitH + c] = v;
                    } else if (c < splitH + splitS) {
                        int sc = c - splitH;
                        skipOut[(size_t)gr * splitS + sc] = v + sbias[sc];
                    }
                }
            }
        }
    }
}

// ---------------- attention logits ----------------
__global__ void al_kernel(const float* __restrict__ h, const float* __restrict__ a_s,
                          const float* __restrict__ a_d, float* __restrict__ als,
                          float* __restrict__ ald, int C)
{
    int w = (blockIdx.x * blockDim.x + threadIdx.x) >> 5;
    int lane = threadIdx.x & 31;
    if (w >= NN * HEADS) return;
    int n = w >> 2, hd = w & 3;
    const float* hp = h + (size_t)n * (HEADS * C) + hd * C;
    float ss = 0.f, sd = 0.f;
    for (int c = lane; c < C; c += 32) {
        float v = hp[c];
        ss = fmaf(v, a_s[hd * C + c], ss);
        sd = fmaf(v, a_d[hd * C + c], sd);
    }
#pragma unroll
    for (int o = 16; o; o >>= 1) {
        ss += __shfl_xor_sync(0xffffffffu, ss, o);
        sd += __shfl_xor_sync(0xffffffffu, sd, o);
    }
    if (lane == 0) { als[w] = ss; ald[w] = sd; }
}

// ---------------- fused GAT agg + bias + skip + BN-stats (layers 0/1) --------
__global__ __launch_bounds__(256) void gat_agg_kernel(
    const int* __restrict__ rowptr, const int* __restrict__ csrc,
    const float* __restrict__ h, const float* __restrict__ als,
    const float* __restrict__ ald, const float* __restrict__ bias,
    const float* __restrict__ skip, float* __restrict__ outp, float* __restrict__ sums)
{
    __shared__ float slabS[8][HC];
    __shared__ float slabQ[8][HC];
    int tid = threadIdx.x;
    int w = (blockIdx.x * 256 + tid) >> 5;
    int lane = tid & 31;
    int wid = tid >> 5;
    int head = lane >> 3;
    float ad = ald[w * 4 + head];
    int beg = rowptr[w], end = rowptr[w + 1];
    float4 acc0 = make_float4(0.f, 0.f, 0.f, 0.f);
    float4 acc1 = make_float4(0.f, 0.f, 0.f, 0.f);
    float den = 0.f;
    int i = beg;
    int lo2 = lane * 2;
    for (; i + 4 <= end; i += 4) {
        int s0 = csrc[i], s1 = csrc[i + 1], s2 = csrc[i + 2], s3 = csrc[i + 3];
        float A0 = als[s0 * 4 + head], A1 = als[s1 * 4 + head];
        float A2 = als[s2 * 4 + head], A3 = als[s3 * 4 + head];
        const float4* h0 = (const float4*)(h + (size_t)s0 * HC) + lo2;
        const float4* h1 = (const float4*)(h + (size_t)s1 * HC) + lo2;
        const float4* h2 = (const float4*)(h + (size_t)s2 * HC) + lo2;
        const float4* h3 = (const float4*)(h + (size_t)s3 * HC) + lo2;
        float4 x00 = h0[0], x01 = h0[1];
        float4 x10 = h1[0], x11 = h1[1];
        float4 x20 = h2[0], x21 = h2[1];
        float4 x30 = h3[0], x31 = h3[1];
        float e0 = expf(lrelu(A0 + ad));
        float e1 = expf(lrelu(A1 + ad));
        float e2 = expf(lrelu(A2 + ad));
        float e3 = expf(lrelu(A3 + ad));
        den += (e0 + e1) + (e2 + e3);
        acc0.x = fmaf(e0, x00.x, acc0.x); acc0.y = fmaf(e0, x00.y, acc0.y);
        acc0.z = fmaf(e0, x00.z, acc0.z); acc0.w = fmaf(e0, x00.w, acc0.w);
        acc1.x = fmaf(e0, x01.x, acc1.x); acc1.y = fmaf(e0, x01.y, acc1.y);
        acc1.z = fmaf(e0, x01.z, acc1.z); acc1.w = fmaf(e0, x01.w, acc1.w);
        acc0.x = fmaf(e1, x10.x, acc0.x); acc0.y = fmaf(e1, x10.y, acc0.y);
        acc0.z = fmaf(e1, x10.z, acc0.z); acc0.w = fmaf(e1, x10.w, acc0.w);
        acc1.x = fmaf(e1, x11.x, acc1.x); acc1.y = fmaf(e1, x11.y, acc1.y);
        acc1.z = fmaf(e1, x11.z, acc1.z); acc1.w = fmaf(e1, x11.w, acc1.w);
        acc0.x = fmaf(e2, x20.x, acc0.x); acc0.y = fmaf(e2, x20.y, acc0.y);
        acc0.z = fmaf(e2, x20.z, acc0.z); acc0.w = fmaf(e2, x20.w, acc0.w);
        acc1.x = fmaf(e2, x21.x, acc1.x); acc1.y = fmaf(e2, x21.y, acc1.y);
        acc1.z = fmaf(e2, x21.z, acc1.z); acc1.w = fmaf(e2, x21.w, acc1.w);
        acc0.x = fmaf(e3, x30.x, acc0.x); acc0.y = fmaf(e3, x30.y, acc0.y);
        acc0.z = fmaf(e3, x30.z, acc0.z); acc0.w = fmaf(e3, x30.w, acc0.w);
        acc1.x = fmaf(e3, x31.x, acc1.x); acc1.y = fmaf(e3, x31.y, acc1.y);
        acc1.z = fmaf(e3, x31.z, acc1.z); acc1.w = fmaf(e3, x31.w, acc1.w);
    }
    for (; i < end; i++) {
        int s = csrc[i];
        float e = expf(lrelu(als[s * 4 + head] + ad));
        den += e;
        const float4* hp = (const float4*)(h + (size_t)s * HC) + lo2;
        float4 v0 = hp[0], v1 = hp[1];
        acc0.x = fmaf(e, v0.x, acc0.x); acc0.y = fmaf(e, v0.y, acc0.y);
        acc0.z = fmaf(e, v0.z, acc0.z); acc0.w = fmaf(e, v0.w, acc0.w);
        acc1.x = fmaf(e, v1.x, acc1.x); acc1.y = fmaf(e, v1.y, acc1.y);
        acc1.z = fmaf(e, v1.z, acc1.z); acc1.w = fmaf(e, v1.w, acc1.w);
    }
    float inv = 1.f / (den + 1e-16f);
    int cbase = lane * 8;
    size_t obase = (size_t)w * HC + cbase;
    const float4* bp = (const float4*)(bias + cbase);
    const float4* sp = (const float4*)(skip + obase);
    float4 b0 = bp[0], b1 = bp[1];
    float4 s0 = sp[0], s1 = sp[1];
    float4 o0, o1;
    o0.x = fmaf(acc0.x, inv, b0.x + s0.x); o0.y = fmaf(acc0.y, inv, b0.y + s0.y);
    o0.z = fmaf(acc0.z, inv, b0.z + s0.z); o0.w = fmaf(acc0.w, inv, b0.w + s0.w);
    o1.x = fmaf(acc1.x, inv, b1.x + s1.x); o1.y = fmaf(acc1.y, inv, b1.y + s1.y);
    o1.z = fmaf(acc1.z, inv, b1.z + s1.z); o1.w = fmaf(acc1.w, inv, b1.w + s1.w);
    float4* op = (float4*)(outp + obase);
    op[0] = o0; op[1] = o1;

    // BN partials: per-warp exclusive slabs (no atomics), then one block reduce
    *(float4*)&slabS[wid][cbase] = o0;
    *(float4*)&slabS[wid][cbase + 4] = o1;
    float4 q0 = make_float4(o0.x * o0.x, o0.y * o0.y, o0.z * o0.z, o0.w * o0.w);
    float4 q1 = make_float4(o1.x * o1.x, o1.y * o1.y, o1.z * o1.z, o1.w * o1.w);
    *(float4*)&slabQ[wid][cbase] = q0;
    *(float4*)&slabQ[wid][cbase + 4] = q1;
    __syncthreads();
    float s = 0.f, q = 0.f;
#pragma unroll
    for (int ww = 0; ww < 8; ww++) { s += slabS[ww][tid]; q += slabQ[ww][tid]; }
    atomicAdd(&sums[tid], s);
    atomicAdd(&sums[HC + tid], q);
}

// ---------------- layer 2: agg + mean heads + bias + skip + log_softmax ------
__global__ __launch_bounds__(256) void gat_agg47_fused(
    const int* __restrict__ rowptr, const int* __restrict__ csrc,
    const float* __restrict__ h, const float4* __restrict__ als,
    const float4* __restrict__ ald, const float* __restrict__ b2,
    const float* __restrict__ skip47, float* __restrict__ outp)
{
    int w = (blockIdx.x * blockDim.x + threadIdx.x) >> 5;
    int lane = threadIdx.x & 31;
    if (w >= NN) return;
    float4 ad = ald[w];
    int beg = rowptr[w], end = rowptr[w + 1];
    float a0 = 0.f, a1 = 0.f, a2 = 0.f, a3 = 0.f;
    float c0 = 0.f, c1 = 0.f, c2 = 0.f, c3 = 0.f;
    float d0 = 0.f, d1 = 0.f, d2 = 0.f, d3 = 0.f;
    bool has2 = (lane + 32) < NCLS;
    int i = beg;
    for (; i + 2 <= end; i += 2) {
        int sA = csrc[i], sB = csrc[i + 1];
        float4 aA = als[sA], aB = als[sB];
        const float* hA = h + (size_t)sA * L2OUT;
        const float* hB = h + (size_t)sB * L2OUT;
        float pA0 = hA[lane], pA1 = hA[NCLS + lane], pA2 = hA[2 * NCLS + lane], pA3 = hA[3 * NCLS + lane];
        float pB0 = hB[lane], pB1 = hB[NCLS + lane], pB2 = hB[2 * NCLS + lane], pB3 = hB[3 * NCLS + lane];
        float qA0 = 0.f, qA1 = 0.f, qA2 = 0.f, qA3 = 0.f;
        float qB0 = 0.f, qB1 = 0.f, qB2 = 0.f, qB3 = 0.f;
        if (has2) {
            int c = lane + 32;
            qA0 = hA[c]; qA1 = hA[NCLS + c]; qA2 = hA[2 * NCLS + c]; qA3 = hA[3 * NCLS + c];
            qB0 = hB[c]; qB1 = hB[NCLS + c]; qB2 = hB[2 * NCLS + c]; qB3 = hB[3 * NCLS + c];
        }
        float eA0 = expf(lrelu(aA.x + ad.x)), eA1 = expf(lrelu(aA.y + ad.y));
        float eA2 = expf(lrelu(aA.z + ad.z)), eA3 = expf(lrelu(aA.w + ad.w));
        float eB0 = expf(lrelu(aB.x + ad.x)), eB1 = expf(lrelu(aB.y + ad.y));
        float eB2 = expf(lrelu(aB.z + ad.z)), eB3 = expf(lrelu(aB.w + ad.w));
        d0 += eA0 + eB0; d1 += eA1 + eB1; d2 += eA2 + eB2; d3 += eA3 + eB3;
        a0 = fmaf(eA0, pA0, fmaf(eB0, pB0, a0));
        a1 = fmaf(eA1, pA1, fmaf(eB1, pB1, a1));
        a2 = fmaf(eA2, pA2, fmaf(eB2, pB2, a2));
        a3 = fmaf(eA3, pA3, fmaf(eB3, pB3, a3));
        c0 = fmaf(eA0, qA0, fmaf(eB0, qB0, c0));
        c1 = fmaf(eA1, qA1, fmaf(eB1, qB1, c1));
        c2 = fmaf(eA2, qA2, fmaf(eB2, qB2, c2));
        c3 = fmaf(eA3, qA3, fmaf(eB3, qB3, c3));
    }
    for (; i < end; i++) {
        int s = csrc[i];
        float4 as4 = als[s];
        float e0 = expf(lrelu(as4.x + ad.x));
        float e1 = expf(lrelu(as4.y + ad.y));
        float e2 = expf(lrelu(as4.z + ad.z));
        float e3 = expf(lrelu(as4.w + ad.w));
        d0 += e0; d1 += e1; d2 += e2; d3 += e3;
        const float* hs = h + (size_t)s * L2OUT;
        a0 = fmaf(e0, hs[lane], a0);
        a1 = fmaf(e1, hs[NCLS + lane], a1);
        a2 = fmaf(e2, hs[2 * NCLS + lane], a2);
        a3 = fmaf(e3, hs[3 * NCLS + lane], a3);
        if (has2) {
            int c = lane + 32;
            c0 = fmaf(e0, hs[c], c0);
            c1 = fmaf(e1, hs[NCLS + c], c1);
            c2 = fmaf(e2, hs[2 * NCLS + c], c2);
            c3 = fmaf(e3, hs[3 * NCLS + c], c3);
        }
    }
    float i0 = 1.f / (d0 + 1e-16f), i1 = 1.f / (d1 + 1e-16f);
    float i2 = 1.f / (d2 + 1e-16f), i3 = 1.f / (d3 + 1e-16f);
    float v0 = 0.25f * (a0 * i0 + a1 * i1 + a2 * i2 + a3 * i3)
             + b2[lane] + skip47[(size_t)w * NCLS + lane];
    float v1 = -1e30f;
    if (has2) {
        int c = lane + 32;
        v1 = 0.25f * (c0 * i0 + c1 * i1 + c2 * i2 + c3 * i3)
           + b2[c] + skip47[(size_t)w * NCLS + c];
    }
    float m = fmaxf(v0, v1);
#pragma unroll
    for (int o = 16; o; o >>= 1) m = fmaxf(m, __shfl_xor_sync(0xffffffffu, m, o));
    float s = expf(v0 - m) + (has2 ? expf(v1 - m) : 0.f);
#pragma unroll
    for (int o = 16; o; o >>= 1) s += __shfl_xor_sync(0xffffffffu, s, o);
    float lse = m + logf(s);
    outp[(size_t)w * NCLS + lane] = v0 - lse;
    if (has2) outp[(size_t)w * NCLS + lane + 32] = v1 - lse;
}

// ---------------- BN apply + ELU -> fp16 for next GEMM ---------------
__global__ void bn_apply_kernel(const float* __restrict__ pre, const float* __restrict__ sums,
                                const float* __restrict__ gamma, const float* __restrict__ beta,
                                __half* __restrict__ oh)
{
    int c = threadIdx.x;
    float mu = sums[c] * (1.f / NN);
    float var = sums[HC + c] * (1.f / NN) - mu * mu;
    float rstd = rsqrtf(var + 1e-5f);
    float g = gamma[c] * rstd;
    float b = beta[c] - mu * g;
    for (int r = blockIdx.x; r < NN; r += gridDim.x) {
        size_t idx = (size_t)r * HC + c;
        float v = fmaf(pre[idx], g, b);
        float o = v > 0.f ? v : expf(v) - 1.f;
        oh[idx] = __float2half_rn(o);
    }
}

// ---------------- host orchestration ----------------
extern "C" void kernel_launch(void* const* d_in, const int* in_sizes, int n_in,
                              void* d_out, int out_size)
{
    const float* x   = (const float*)d_in[0];
    const int*   ei  = (const int*)d_in[1];
    const float* w0  = (const float*)d_in[2];
    const float* as0 = (const float*)d_in[3];
    const float* ad0 = (const float*)d_in[4];
    const float* b0  = (const float*)d_in[5];
    const float* sw0 = (const float*)d_in[6];
    const float* sb0 = (const float*)d_in[7];
    const float* g0  = (const float*)d_in[8];
    const float* be0 = (const float*)d_in[9];
    const float* w1  = (const float*)d_in[10];
    const float* as1 = (const float*)d_in[11];
    const float* ad1 = (const float*)d_in[12];
    const float* b1  = (const float*)d_in[13];
    const float* sw1 = (const float*)d_in[14];
    const float* sb1 = (const float*)d_in[15];
    const float* g1  = (const float*)d_in[16];
    const float* be1 = (const float*)d_in[17];
    const float* w2  = (const float*)d_in[18];
    const float* as2 = (const float*)d_in[19];
    const float* ad2 = (const float*)d_in[20];
    const float* b2  = (const float*)d_in[21];
    const float* sw2 = (const float*)d_in[22];
    const float* sb2 = (const float*)d_in[23];

    const int* src = ei;
    const int* dst = ei + EE;

    float *h, *skip, *agg, *als, *ald, *bnsum;
    __half *xh, *ah, *b0h, *b0l, *b1h, *b1l, *b2h, *b2l;
    int *cnt, *part, *bsum, *rowptr, *cursor, *csrc;
    cudaGetSymbolAddress((void**)&h, g_h);
    cudaGetSymbolAddress((void**)&skip, g_skip);
    cudaGetSymbolAddress((void**)&agg, g_agg);
    cudaGetSymbolAddress((void**)&als, g_als);
    cudaGetSymbolAddress((void**)&ald, g_ald);
    cudaGetSymbolAddress((void**)&bnsum, g_bnsum);
    cudaGetSymbolAddress((void**)&xh, g_xh);
    cudaGetSymbolAddress((void**)&ah, g_ah);
    cudaGetSymbolAddress((void**)&b0h, g_b0h);
    cudaGetSymbolAddress((void**)&b0l, g_b0l);
    cudaGetSymbolAddress((void**)&b1h, g_b1h);
    cudaGetSymbolAddress((void**)&b1l, g_b1l);
    cudaGetSymbolAddress((void**)&b2h, g_b2h);
    cudaGetSymbolAddress((void**)&b2l, g_b2l);
    cudaGetSymbolAddress((void**)&cnt, g_cnt);
    cudaGetSymbolAddress((void**)&part, g_part);
    cudaGetSymbolAddress((void**)&bsum, g_bsum);
    cudaGetSymbolAddress((void**)&rowptr, g_rowptr);
    cudaGetSymbolAddress((void**)&cursor, g_cursor);
    cudaGetSymbolAddress((void**)&csrc, g_csrc);

    cudaFuncSetAttribute(hgemm_split, cudaFuncAttributeMaxDynamicSharedMemorySize, SMEM_GEMM);

    dim3 gemm512(4, (NN + BM - 1) / BM);
    dim3 gemm256(2, (NN + BM - 1) / BM);
    int alBlocks = (NN * HEADS * 32 + 255) / 256;
    int nodeWarpBlocks = (NN * 32) / 256;
    int eBlocks = (EE + 255) / 256;

    // launch order keeps hgemm layer-0 as the 5th launch (profiler target)
    convert_x<<<(NN * K0P + 255) / 256, 256>>>(x, xh);                         // 1
    pack_weights<<<480, 256>>>(w0, sw0, w1, sw1, w2, sw2,
                               b0h, b0l, b1h, b1l, b2h, b2l);                  // 2
    cudaMemsetAsync(cnt, 0, NN * sizeof(int));                                 // 3
    count_kernel<<<eBlocks, 256>>>(dst, cnt);                                  // 4
    hgemm_split<<<gemm512, 256, SMEM_GEMM>>>(xh, b0h, b0l, sb0, h, skip,
                                             NN, K0P, 512, HC, HC);            // 5
    scan_blocks<<<NBLK, 256>>>(cnt, part, bsum);
    scan_totals<<<1, 128>>>(bsum);
    scan_add<<<(NN + 256) / 256, 256>>>(part, bsum, rowptr, cursor);
    fill_kernel<<<eBlocks, 256>>>(src, dst, cursor, csrc);

    // ===== Layer 0 (agg + BN) =====
    al_kernel<<<alBlocks, 256>>>(h, as0, ad0, als, ald, HID);
    cudaMemsetAsync(bnsum, 0, 2 * HC * sizeof(float));
    gat_agg_kernel<<<nodeWarpBlocks, 256>>>(rowptr, csrc, h, als, ald, b0, skip, agg, bnsum);
    bn_apply_kernel<<<512, 256>>>(agg, bnsum, g0, be0, ah);

    // ===== Layer 1 =====
    hgemm_split<<<gemm512, 256, SMEM_GEMM>>>(ah, b1h, b1l, sb1, h, skip, NN, HC, 512, HC, HC);
    al_kernel<<<alBlocks, 256>>>(h, as1, ad1, als, ald, HID);
    cudaMemsetAsync(bnsum, 0, 2 * HC * sizeof(float));
    gat_agg_kernel<<<nodeWarpBlocks, 256>>>(rowptr, csrc, h, als, ald, b1, skip, agg, bnsum);
    bn_apply_kernel<<<512, 256>>>(agg, bnsum, g1, be1, ah);

    // ===== Layer 2 =====
    hgemm_split<<<gemm256, 256, SMEM_GEMM>>>(ah, b2h, b2l, sb2, h, skip, NN, HC, NP2, L2OUT, NCLS);
    al_kernel<<<alBlocks, 256>>>(h, as2, ad2, als, ald, NCLS);
    gat_agg47_fused<<<nodeWarpBlocks, 256>>>(rowptr, csrc, h, (const float4*)als,
                                             (const float4*)ald, b2, skip, (float*)d_out);
}

// round 10
// speedup vs baseline: 1.3053x; 1.1692x over previous
#include <cuda_runtime.h>
#include <cuda_bf16.h>
#include <cuda_fp16.h>
#include <cstdint>
#include <math.h>

#define NN 30000
#define EE 480000
#define F_IN 100
#define HID 64
#define HEADS 4
#define NCLS 47
#define HC 256           // HEADS*HID
#define L2OUT 188        // HEADS*NCLS
#define NP2 256          // padded pack width layer2 (188 + 47 -> 256)
#define K0P 128          // padded K for layer 0 (100 -> 128)
#define NBLK 118         // ceil(NN/256)

// ---------------- scratch ----------------
__device__ __align__(16) __half g_h[(size_t)NN * HC];    // GAT-branch GEMM out (fp16)
__device__ __align__(16) float g_skip[(size_t)NN * HC];
__device__ __align__(16) float g_agg[(size_t)NN * HC];
__device__ __align__(16) float g_als[(size_t)NN * HEADS];
__device__ __align__(16) float g_ald[(size_t)NN * HEADS];
__device__ float g_bnsum[2 * HC];
// fp16 activations (A-side)
__device__ __align__(16) __half g_xh[(size_t)NN * K0P];
__device__ __align__(16) __half g_ah[(size_t)NN * HC];
// fp16 transposed weights [n][k]
__device__ __align__(16) __half g_b0h[512 * K0P];
__device__ __align__(16) __half g_b1h[512 * HC];
__device__ __align__(16) __half g_b2h[NP2 * HC];
// CSR
__device__ int g_cnt[NN];
__device__ int g_part[NN];
__device__ int g_bsum[NBLK];
__device__ int g_rowptr[NN + 1];
__device__ int g_cursor[NN];
__device__ int g_csrc[EE];

__device__ __forceinline__ float lrelu(float x) { return x > 0.f ? x : 0.2f * x; }

// ---------------- convert x to padded fp16 ----------------
__global__ void convert_x(const float* __restrict__ x, __half* __restrict__ xh)
{
    int idx = blockIdx.x * 256 + threadIdx.x;
    if (idx >= NN * K0P) return;
    int n = idx >> 7, c = idx & (K0P - 1);
    float v = (c < F_IN) ? x[n * F_IN + c] : 0.f;
    xh[idx] = __float2half_rn(v);
}

// ---------------- pack weights -> transposed fp16 ----------------
__global__ void pack_weights(const float* __restrict__ w0, const float* __restrict__ sw0,
                             const float* __restrict__ w1, const float* __restrict__ sw1,
                             const float* __restrict__ w2, const float* __restrict__ sw2,
                             __half* __restrict__ b0h, __half* __restrict__ b1h,
                             __half* __restrict__ b2h)
{
    int tid = blockIdx.x * blockDim.x + threadIdx.x;
    int stride = gridDim.x * blockDim.x;
    for (int i = tid; i < 512 * K0P; i += stride) {
        int n = i >> 7, k = i & (K0P - 1);
        float v = 0.f;
        if (k < F_IN) v = (n < HC) ? w0[k * HC + n] : sw0[k * HC + (n - HC)];
        b0h[i] = __float2half_rn(v);
    }
    for (int i = tid; i < 512 * HC; i += stride) {
        int n = i >> 8, k = i & (HC - 1);
        float v = (n < HC) ? w1[k * HC + n] : sw1[k * HC + (n - HC)];
        b1h[i] = __float2half_rn(v);
    }
    for (int i = tid; i < NP2 * HC; i += stride) {
        int n = i >> 8, k = i & (HC - 1);
        float v = 0.f;
        if (n < L2OUT) v = w2[k * L2OUT + n];
        else if (n < L2OUT + NCLS) v = sw2[k * NCLS + (n - L2OUT)];
        b2h[i] = __float2half_rn(v);
    }
}

// ---------------- CSR build ----------------
__global__ void count_kernel(const int* __restrict__ dst, int* __restrict__ cnt)
{
    int e = blockIdx.x * blockDim.x + threadIdx.x;
    if (e < EE) atomicAdd(&cnt[dst[e]], 1);
}

__global__ void scan_blocks(const int* __restrict__ cnt, int* __restrict__ part,
                            int* __restrict__ bsum)
{
    int t = threadIdx.x;
    int i = blockIdx.x * 256 + t;
    int lane = t & 31, wid = t >> 5;
    int v = (i < NN) ? cnt[i] : 0;
    int x = v;
#pragma unroll
    for (int off = 1; off < 32; off <<= 1) {
        int y = __shfl_up_sync(0xffffffffu, x, off);
        if (lane >= off) x += y;
    }
    __shared__ int wsum[8];
    if (lane == 31) wsum[wid] = x;
    __syncthreads();
    if (wid == 0 && lane < 8) {
        int w = wsum[lane];
#pragma unroll
        for (int off = 1; off < 8; off <<= 1) {
            int y = __shfl_up_sync(0xffu, w, off);
            if (lane >= off) w += y;
        }
        wsum[lane] = w;
    }
    __syncthreads();
    int base = (wid > 0) ? wsum[wid - 1] : 0;
    int incl = x + base;
    if (i < NN) part[i] = incl - v;
    if (t == 255) bsum[blockIdx.x] = incl;
}

__global__ void scan_totals(int* __restrict__ bsum)
{
    int t = threadIdx.x;
    int lane = t & 31, wid = t >> 5;
    int v = (t < NBLK) ? bsum[t] : 0;
    int x = v;
#pragma unroll
    for (int off = 1; off < 32; off <<= 1) {
        int y = __shfl_up_sync(0xffffffffu, x, off);
        if (lane >= off) x += y;
    }
    __shared__ int wsum[4];
    if (lane == 31) wsum[wid] = x;
    __syncthreads();
    if (wid == 0 && lane < 4) {
        int w = wsum[lane];
#pragma unroll
        for (int off = 1; off < 4; off <<= 1) {
            int y = __shfl_up_sync(0xfu, w, off);
            if (lane >= off) w += y;
        }
        wsum[lane] = w;
    }
    __syncthreads();
    int base = (wid > 0) ? wsum[wid - 1] : 0;
    if (t < NBLK) bsum[t] = x + base - v;
}

__global__ void scan_add(const int* __restrict__ part, const int* __restrict__ bsum,
                         int* __restrict__ rowptr, int* __restrict__ cursor)
{
    int i = blockIdx.x * 256 + threadIdx.x;
    if (i < NN) {
        int r = part[i] + bsum[i >> 8];
        rowptr[i] = r;
        cursor[i] = r;
    }
    if (i == NN) rowptr[NN] = EE;
}

__global__ void fill_kernel(const int* __restrict__ src, const int* __restrict__ dst,
                            int* __restrict__ cursor, int* __restrict__ csrc)
{
    int e = blockIdx.x * blockDim.x + threadIdx.x;
    if (e >= EE) return;
    int d = dst[e];
    int pos = atomicAdd(&cursor[d], 1);
    csrc[pos] = src[e];
}

// ---------------- pure fp16 tensor-core GEMM ------
#define BM 128
#define BN 128
#define BKK 32
#define BKP 40          // padded K stride in halves (80B rows, conflict-free ldmatrix)
#define OBH 5120
#define STGH 10240      // halves per stage
#define SMEM_GEMM (2 * STGH * 2)   // 40960 bytes

__device__ __forceinline__ void mma16816(float* d, const unsigned* a, const unsigned* b)
{
    asm volatile(
        "mma.sync.aligned.m16n8k16.row.col.f32.f16.f16.f32 "
        "{%0,%1,%2,%3}, {%4,%5,%6,%7}, {%8,%9}, {%0,%1,%2,%3};"
        : "+f"(d[0]), "+f"(d[1]), "+f"(d[2]), "+f"(d[3])
        : "r"(a[0]), "r"(a[1]), "r"(a[2]), "r"(a[3]), "r"(b[0]), "r"(b[1]));
}

__device__ __forceinline__ void cp16(unsigned dst, const void* src, int sz)
{
    asm volatile("cp.async.ca.shared.global [%0], [%1], 16, %2;"
                 :: "r"(dst), "l"(src), "r"(sz));
}

__device__ __forceinline__ void ldm4(unsigned addr, unsigned& r0, unsigned& r1,
                                     unsigned& r2, unsigned& r3)
{
    asm volatile("ldmatrix.sync.aligned.m8n8.x4.shared.b16 {%0,%1,%2,%3}, [%4];"
                 : "=r"(r0), "=r"(r1), "=r"(r2), "=r"(r3) : "r"(addr));
}

__device__ __forceinline__ void issue_stage(
    unsigned sb, const __half* Ah, const __half* Bh,
    int rowBlock, int colBlock, int M, int KA, int k0, int sr, int sk)
{
#pragma unroll
    for (int i = 0; i < 2; i++) {
        int row = sr + i * 64;
        int gr = rowBlock + row;
        int sz = (gr < M) ? 16 : 0;
        size_t off = (size_t)(sz ? gr : 0) * KA + k0 + sk;
        cp16(sb + (unsigned)(row * BKP + sk) * 2, Ah + off, sz);
        int gc = colBlock + row;                    // Npack padded: always valid
        size_t boff = (size_t)gc * KA + k0 + sk;
        cp16(sb + (unsigned)(OBH + row * BKP + sk) * 2, Bh + boff, 16);
    }
    asm volatile("cp.async.commit_group;");
}

__global__ __launch_bounds__(256, 2) void hgemm_f16(
    const __half* __restrict__ Ah, const __half* __restrict__ Bh,
    const float* __restrict__ sbias, __half* __restrict__ hOut, float* __restrict__ skipOut,
    int M, int KA, int Npack, int splitH, int splitS)
{
    extern __shared__ __half sm[];
    unsigned smB = (unsigned)__cvta_generic_to_shared(sm);

    int tid = threadIdx.x;
    int lane = tid & 31, wid = tid >> 5;
    int rowBlock = blockIdx.y * BM;
    int colBlock = blockIdx.x * BN;
    int wm = (wid & 1) * 64;
    int wn = (wid >> 1) * 32;
    int gID = lane >> 2, tig = lane & 3;

    float acc[4][4][4];
#pragma unroll
    for (int mt = 0; mt < 4; mt++)
#pragma unroll
        for (int nt = 0; nt < 4; nt++)
#pragma unroll
            for (int r = 0; r < 4; r++) acc[mt][nt][r] = 0.f;

    int kIters = KA >> 5;
    int sr = tid >> 2;
    int sk = (tid & 3) * 8;

    int aRow = (lane & 15);
    int aCol = (lane & 16) >> 1;
    int bNrow = (lane & 7) + ((lane & 16) >> 1);
    int bCol = (lane & 8);

    issue_stage(smB, Ah, Bh, rowBlock, colBlock, M, KA, 0, sr, sk);

    for (int it = 0; it < kIters; it++) {
        int cur = it & 1;
        if (it + 1 < kIters) {
            issue_stage(smB + (unsigned)(cur ^ 1) * STGH * 2, Ah, Bh,
                        rowBlock, colBlock, M, KA, (it + 1) * BKK, sr, sk);
            asm volatile("cp.async.wait_group 1;");
        } else {
            asm volatile("cp.async.wait_group 0;");
        }
        __syncthreads();

        unsigned aHb = smB + (unsigned)cur * STGH * 2;
        unsigned bHb = aHb + OBH * 2;

#pragma unroll
        for (int ks = 0; ks < 2; ks++) {
            int kk = ks * 16;
            unsigned bHf[8];
#pragma unroll
            for (int pair = 0; pair < 2; pair++) {
                int n = wn + pair * 16 + bNrow;
                unsigned off = (unsigned)(n * BKP + kk + bCol) * 2;
                ldm4(bHb + off, bHf[pair * 4 + 0], bHf[pair * 4 + 1],
                                bHf[pair * 4 + 2], bHf[pair * 4 + 3]);
            }
            unsigned aHf[4][4];
#pragma unroll
            for (int mt = 0; mt < 4; mt++) {
                int r = wm + mt * 16 + aRow;
                unsigned off = (unsigned)(r * BKP + kk + aCol) * 2;
                ldm4(aHb + off, aHf[mt][0], aHf[mt][1], aHf[mt][2], aHf[mt][3]);
            }
#pragma unroll
            for (int mt = 0; mt < 4; mt++)
#pragma unroll
                for (int nt = 0; nt < 4; nt++)
                    mma16816(acc[mt][nt], aHf[mt], &bHf[(nt >> 1) * 4 + (nt & 1) * 2]);
        }
        __syncthreads();
    }

    // epilogue: route to hOut(fp16) / skipOut(fp32, +sbias)
#pragma unroll
    for (int mt = 0; mt < 4; mt++) {
        int gr0 = rowBlock + wm + mt * 16 + gID;
        int gr1 = gr0 + 8;
#pragma unroll
        for (int nt = 0; nt < 4; nt++) {
            int gc = colBlock + wn + nt * 8 + tig * 2;
#pragma unroll
            for (int half_ = 0; half_ < 2; half_++) {
                int gr = half_ ? gr1 : gr0;
                if (gr >= M) continue;
                float v0 = acc[mt][nt][half_ * 2 + 0];
                float v1 = acc[mt][nt][half_ * 2 + 1];
                if (gc < splitH) {        // pair aligned: both cols in region
                    *(__half2*)(hOut + (size_t)gr * splitH + gc) =
                        __floats2half2_rn(v0, v1);
                } else {
#pragma unroll
                    for (int j = 0; j < 2; j++) {
                        int c2 = gc + j;
                        if (c2 < splitH + splitS) {
                            int sc = c2 - splitH;
                            skipOut[(size_t)gr * splitS + sc] = (j ? v1 : v0) + sbias[sc];
                        }
                    }
                }
            }
        }
    }
}

// ---------------- attention logits (fp16 h) ----------------
__global__ void al_kernel(const __half* __restrict__ h, const float* __restrict__ a_s,
                          const float* __restrict__ a_d, float* __restrict__ als,
                          float* __restrict__ ald, int C)
{
    int w = (blockIdx.x * blockDim.x + threadIdx.x) >> 5;
    int lane = threadIdx.x & 31;
    if (w >= NN * HEADS) return;
    int n = w >> 2, hd = w & 3;
    const __half* hp = h + (size_t)n * (HEADS * C) + hd * C;
    float ss = 0.f, sd = 0.f;
    for (int c = lane; c < C; c += 32) {
        float v = __half2float(hp[c]);
        ss = fmaf(v, a_s[hd * C + c], ss);
        sd = fmaf(v, a_d[hd * C + c], sd);
    }
#pragma unroll
    for (int o = 16; o; o >>= 1) {
        ss += __shfl_xor_sync(0xffffffffu, ss, o);
        sd += __shfl_xor_sync(0xffffffffu, sd, o);
    }
    if (lane == 0) { als[w] = ss; ald[w] = sd; }
}

__device__ __forceinline__ void haccum(float e, uint4 u, float* ac)
{
    const __half2* p = (const __half2*)&u;
#pragma unroll
    for (int j = 0; j < 4; j++) {
        float2 f = __half22float2(p[j]);
        ac[2 * j]     = fmaf(e, f.x, ac[2 * j]);
        ac[2 * j + 1] = fmaf(e, f.y, ac[2 * j + 1]);
    }
}

// ---------------- fused GAT agg + bias + skip + BN-stats (layers 0/1) --------
__global__ __launch_bounds__(256) void gat_agg_kernel(
    const int* __restrict__ rowptr, const int* __restrict__ csrc,
    const __half* __restrict__ h, const float* __restrict__ als,
    const float* __restrict__ ald, const float* __restrict__ bias,
    const float* __restrict__ skip, float* __restrict__ outp, float* __restrict__ sums)
{
    __shared__ float slabS[8][HC];
    __shared__ float slabQ[8][HC];
    int tid = threadIdx.x;
    int w = (blockIdx.x * 256 + tid) >> 5;
    int lane = tid & 31;
    int wid = tid >> 5;
    int head = lane >> 3;
    float ad = ald[w * 4 + head];
    int beg = rowptr[w], end = rowptr[w + 1];
    float ac[8];
#pragma unroll
    for (int j = 0; j < 8; j++) ac[j] = 0.f;
    float den = 0.f;
    int i = beg;
    for (; i + 4 <= end; i += 4) {
        int s0 = csrc[i], s1 = csrc[i + 1], s2 = csrc[i + 2], s3 = csrc[i + 3];
        float A0 = als[s0 * 4 + head], A1 = als[s1 * 4 + head];
        float A2 = als[s2 * 4 + head], A3 = als[s3 * 4 + head];
        uint4 u0 = ((const uint4*)(h + (size_t)s0 * HC))[lane];
        uint4 u1 = ((const uint4*)(h + (size_t)s1 * HC))[lane];
        uint4 u2 = ((const uint4*)(h + (size_t)s2 * HC))[lane];
        uint4 u3 = ((const uint4*)(h + (size_t)s3 * HC))[lane];
        float e0 = expf(lrelu(A0 + ad));
        float e1 = expf(lrelu(A1 + ad));
        float e2 = expf(lrelu(A2 + ad));
        float e3 = expf(lrelu(A3 + ad));
        den += (e0 + e1) + (e2 + e3);
        haccum(e0, u0, ac);
        haccum(e1, u1, ac);
        haccum(e2, u2, ac);
        haccum(e3, u3, ac);
    }
    for (; i < end; i++) {
        int s = csrc[i];
        float e = expf(lrelu(als[s * 4 + head] + ad));
        den += e;
        uint4 u = ((const uint4*)(h + (size_t)s * HC))[lane];
        haccum(e, u, ac);
    }
    float inv = 1.f / (den + 1e-16f);
    int cbase = lane * 8;
    size_t obase = (size_t)w * HC + cbase;
    const float4* bp = (const float4*)(bias + cbase);
    const float4* sp = (const float4*)(skip + obase);
    float4 b0 = bp[0], b1 = bp[1];
    float4 s0 = sp[0], s1 = sp[1];
    float4 o0, o1;
    o0.x = fmaf(ac[0], inv, b0.x + s0.x); o0.y = fmaf(ac[1], inv, b0.y + s0.y);
    o0.z = fmaf(ac[2], inv, b0.z + s0.z); o0.w = fmaf(ac[3], inv, b0.w + s0.w);
    o1.x = fmaf(ac[4], inv, b1.x + s1.x); o1.y = fmaf(ac[5], inv, b1.y + s1.y);
    o1.z = fmaf(ac[6], inv, b1.z + s1.z); o1.w = fmaf(ac[7], inv, b1.w + s1.w);
    float4* op = (float4*)(outp + obase);
    op[0] = o0; op[1] = o1;

    // BN partials: per-warp exclusive slabs (no atomics), then one block reduce
    *(float4*)&slabS[wid][cbase] = o0;
    *(float4*)&slabS[wid][cbase + 4] = o1;
    float4 q0 = make_float4(o0.x * o0.x, o0.y * o0.y, o0.z * o0.z, o0.w * o0.w);
    float4 q1 = make_float4(o1.x * o1.x, o1.y * o1.y, o1.z * o1.z, o1.w * o1.w);
    *(float4*)&slabQ[wid][cbase] = q0;
    *(float4*)&slabQ[wid][cbase + 4] = q1;
    __syncthreads();
    float s = 0.f, q = 0.f;
#pragma unroll
    for (int ww = 0; ww < 8; ww++) { s += slabS[ww][tid]; q += slabQ[ww][tid]; }
    atomicAdd(&sums[tid], s);
    atomicAdd(&sums[HC + tid], q);
}

// ---------------- layer 2: agg + mean heads + bias + skip + log_softmax ------
__global__ __launch_bounds__(256) void gat_agg47_fused(
    const int* __restrict__ rowptr, const int* __restrict__ csrc,
    const __half* __restrict__ h, const float4* __restrict__ als,
    const float4* __restrict__ ald, const float* __restrict__ b2,
    const float* __restrict__ skip47, float* __restrict__ outp)
{
    int w = (blockIdx.x * blockDim.x + threadIdx.x) >> 5;
    int lane = threadIdx.x & 31;
    if (w >= NN) return;
    float4 ad = ald[w];
    int beg = rowptr[w], end = rowptr[w + 1];
    float a0 = 0.f, a1 = 0.f, a2 = 0.f, a3 = 0.f;
    float c0 = 0.f, c1 = 0.f, c2 = 0.f, c3 = 0.f;
    float d0 = 0.f, d1 = 0.f, d2 = 0.f, d3 = 0.f;
    bool has2 = (lane + 32) < NCLS;
    for (int i = beg; i < end; i++) {
        int s = csrc[i];
        float4 as4 = als[s];
        float e0 = expf(lrelu(as4.x + ad.x));
        float e1 = expf(lrelu(as4.y + ad.y));
        float e2 = expf(lrelu(as4.z + ad.z));
        float e3 = expf(lrelu(as4.w + ad.w));
        d0 += e0; d1 += e1; d2 += e2; d3 += e3;
        const __half* hs = h + (size_t)s * L2OUT;
        a0 = fmaf(e0, __half2float(hs[lane]), a0);
        a1 = fmaf(e1, __half2float(hs[NCLS + lane]), a1);
        a2 = fmaf(e2, __half2float(hs[2 * NCLS + lane]), a2);
        a3 = fmaf(e3, __half2float(hs[3 * NCLS + lane]), a3);
        if (has2) {
            int c = lane + 32;
            c0 = fmaf(e0, __half2float(hs[c]), c0);
            c1 = fmaf(e1, __half2float(hs[NCLS + c]), c1);
            c2 = fmaf(e2, __half2float(hs[2 * NCLS + c]), c2);
            c3 = fmaf(e3, __half2float(hs[3 * NCLS + c]), c3);
        }
    }
    float i0 = 1.f / (d0 + 1e-16f), i1 = 1.f / (d1 + 1e-16f);
    float i2 = 1.f / (d2 + 1e-16f), i3 = 1.f / (d3 + 1e-16f);
    float v0 = 0.25f * (a0 * i0 + a1 * i1 + a2 * i2 + a3 * i3)
             + b2[lane] + skip47[(size_t)w * NCLS + lane];
    float v1 = -1e30f;
    if (has2) {
        int c = lane + 32;
        v1 = 0.25f * (c0 * i0 + c1 * i1 + c2 * i2 + c3 * i3)
           + b2[c] + skip47[(size_t)w * NCLS + c];
    }
    float m = fmaxf(v0, v1);
#pragma unroll
    for (int o = 16; o; o >>= 1) m = fmaxf(m, __shfl_xor_sync(0xffffffffu, m, o));
    float s = expf(v0 - m) + (has2 ? expf(v1 - m) : 0.f);
#pragma unroll
    for (int o = 16; o; o >>= 1) s += __shfl_xor_sync(0xffffffffu, s, o);
    float lse = m + logf(s);
    outp[(size_t)w * NCLS + lane] = v0 - lse;
    if (has2) outp[(size_t)w * NCLS + lane + 32] = v1 - lse;
}

// ---------------- BN apply + ELU -> fp16 for next GEMM ---------------
__global__ void bn_apply_kernel(const float* __restrict__ pre, const float* __restrict__ sums,
                                const float* __restrict__ gamma, const float* __restrict__ beta,
                                __half* __restrict__ oh)
{
    int c = threadIdx.x;
    float mu = sums[c] * (1.f / NN);
    float var = sums[HC + c] * (1.f / NN) - mu * mu;
    float rstd = rsqrtf(var + 1e-5f);
    float g = gamma[c] * rstd;
    float b = beta[c] - mu * g;
    for (int r = blockIdx.x; r < NN; r += gridDim.x) {
        size_t idx = (size_t)r * HC + c;
        float v = fmaf(pre[idx], g, b);
        float o = v > 0.f ? v : expf(v) - 1.f;
        oh[idx] = __float2half_rn(o);
    }
}

// ---------------- host orchestration ----------------
extern "C" void kernel_launch(void* const* d_in, const int* in_sizes, int n_in,
                              void* d_out, int out_size)
{
    const float* x   = (const float*)d_in[0];
    const int*   ei  = (const int*)d_in[1];
    const float* w0  = (const float*)d_in[2];
    const float* as0 = (const float*)d_in[3];
    const float* ad0 = (const float*)d_in[4];
    const float* b0  = (const float*)d_in[5];
    const float* sw0 = (const float*)d_in[6];
    const float* sb0 = (const float*)d_in[7];
    const float* g0  = (const float*)d_in[8];
    const float* be0 = (const float*)d_in[9];
    const float* w1  = (const float*)d_in[10];
    const float* as1 = (const float*)d_in[11];
    const float* ad1 = (const float*)d_in[12];
    const float* b1  = (const float*)d_in[13];
    const float* sw1 = (const float*)d_in[14];
    const float* sb1 = (const float*)d_in[15];
    const float* g1  = (const float*)d_in[16];
    const float* be1 = (const float*)d_in[17];
    const float* w2  = (const float*)d_in[18];
    const float* as2 = (const float*)d_in[19];
    const float* ad2 = (const float*)d_in[20];
    const float* b2  = (const float*)d_in[21];
    const float* sw2 = (const float*)d_in[22];
    const float* sb2 = (const float*)d_in[23];

    const int* src = ei;
    const int* dst = ei + EE;

    float *skip, *agg, *als, *ald, *bnsum;
    __half *h, *xh, *ah, *b0h, *b1h, *b2h;
    int *cnt, *part, *bsum, *rowptr, *cursor, *csrc;
    cudaGetSymbolAddress((void**)&h, g_h);
    cudaGetSymbolAddress((void**)&skip, g_skip);
    cudaGetSymbolAddress((void**)&agg, g_agg);
    cudaGetSymbolAddress((void**)&als, g_als);
    cudaGetSymbolAddress((void**)&ald, g_ald);
    cudaGetSymbolAddress((void**)&bnsum, g_bnsum);
    cudaGetSymbolAddress((void**)&xh, g_xh);
    cudaGetSymbolAddress((void**)&ah, g_ah);
    cudaGetSymbolAddress((void**)&b0h, g_b0h);
    cudaGetSymbolAddress((void**)&b1h, g_b1h);
    cudaGetSymbolAddress((void**)&b2h, g_b2h);
    cudaGetSymbolAddress((void**)&cnt, g_cnt);
    cudaGetSymbolAddress((void**)&part, g_part);
    cudaGetSymbolAddress((void**)&bsum, g_bsum);
    cudaGetSymbolAddress((void**)&rowptr, g_rowptr);
    cudaGetSymbolAddress((void**)&cursor, g_cursor);
    cudaGetSymbolAddress((void**)&csrc, g_csrc);

    cudaFuncSetAttribute(hgemm_f16, cudaFuncAttributeMaxDynamicSharedMemorySize, SMEM_GEMM);

    dim3 gemm512(4, (NN + BM - 1) / BM);
    dim3 gemm256(2, (NN + BM - 1) / BM);
    int alBlocks = (NN * HEADS * 32 + 255) / 256;
    int nodeWarpBlocks = (NN * 32) / 256;
    int eBlocks = (EE + 255) / 256;

    // launch order keeps hgemm layer-0 as the 5th launch (profiler target)
    convert_x<<<(NN * K0P + 255) / 256, 256>>>(x, xh);                         // 1
    pack_weights<<<480, 256>>>(w0, sw0, w1, sw1, w2, sw2, b0h, b1h, b2h);      // 2
    cudaMemsetAsync(cnt, 0, NN * sizeof(int));                                 // 3
    count_kernel<<<eBlocks, 256>>>(dst, cnt);                                  // 4
    hgemm_f16<<<gemm512, 256, SMEM_GEMM>>>(xh, b0h, sb0, h, skip,
                                           NN, K0P, 512, HC, HC);              // 5
    scan_blocks<<<NBLK, 256>>>(cnt, part, bsum);
    scan_totals<<<1, 128>>>(bsum);
    scan_add<<<(NN + 256) / 256, 256>>>(part, bsum, rowptr, cursor);
    fill_kernel<<<eBlocks, 256>>>(src, dst, cursor, csrc);

    // ===== Layer 0 (agg + BN) =====
    al_kernel<<<alBlocks, 256>>>(h, as0, ad0, als, ald, HID);
    cudaMemsetAsync(bnsum, 0, 2 * HC * sizeof(float));
    gat_agg_kernel<<<nodeWarpBlocks, 256>>>(rowptr, csrc, h, als, ald, b0, skip, agg, bnsum);
    bn_apply_kernel<<<512, 256>>>(agg, bnsum, g0, be0, ah);

    // ===== Layer 1 =====
    hgemm_f16<<<gemm512, 256, SMEM_GEMM>>>(ah, b1h, sb1, h, skip, NN, HC, 512, HC, HC);
    al_kernel<<<alBlocks, 256>>>(h, as1, ad1, als, ald, HID);
    cudaMemsetAsync(bnsum, 0, 2 * HC * sizeof(float));
    gat_agg_kernel<<<nodeWarpBlocks, 256>>>(rowptr, csrc, h, als, ald, b1, skip, agg, bnsum);
    bn_apply_kernel<<<512, 256>>>(agg, bnsum, g1, be1, ah);

    // ===== Layer 2 =====
    hgemm_f16<<<gemm256, 256, SMEM_GEMM>>>(ah, b2h, sb2, h, skip, NN, HC, NP2, L2OUT, NCLS);
    al_kernel<<<alBlocks, 256>>>(h, as2, ad2, als, ald, NCLS);
    gat_agg47_fused<<<nodeWarpBlocks, 256>>>(rowptr, csrc, h, (const float4*)als,
                                             (const float4*)ald, b2, skip, (float*)d_out);
}

// round 11
// speedup vs baseline: 1.4082x; 1.0788x over previous
#include <cuda_runtime.h>
#include <cuda_bf16.h>
#include <cuda_fp16.h>
#include <cstdint>
#include <math.h>

#define NN 30000
#define EE 480000
#define F_IN 100
#define HID 64
#define HEADS 4
#define NCLS 47
#define HC 256           // HEADS*HID
#define L2OUT 188        // HEADS*NCLS
#define NP2 256          // padded pack width layer2 (188 + 47 -> 256)
#define K0P 128          // padded K for layer 0 (100 -> 128)
#define NBLK 118         // ceil(NN/256)

// ---------------- scratch ----------------
__device__ __align__(16) __half g_h[(size_t)NN * HC];    // GAT-branch GEMM out (fp16)
__device__ __align__(16) float g_skip[(size_t)NN * HC];
__device__ __align__(16) float g_agg[(size_t)NN * HC];
__device__ __align__(16) float g_als[(size_t)NN * HEADS];
__device__ __align__(16) float g_ald[(size_t)NN * HEADS];
__device__ float g_bnsum[2 * HC];
// fp16 activations (A-side)
__device__ __align__(16) __half g_xh[(size_t)NN * K0P];
__device__ __align__(16) __half g_ah[(size_t)NN * HC];
// fp16 transposed weights [n][k]
__device__ __align__(16) __half g_b0h[512 * K0P];
__device__ __align__(16) __half g_b1h[512 * HC];
__device__ __align__(16) __half g_b2h[NP2 * HC];
// CSR
__device__ int g_cnt[NN];
__device__ int g_part[NN];
__device__ int g_bsum[NBLK];
__device__ int g_rowptr[NN + 1];
__device__ int g_cursor[NN];
__device__ int g_csrc[EE];

__device__ __forceinline__ float lrelu(float x) { return x > 0.f ? x : 0.2f * x; }

// ---------------- convert x to padded fp16 ----------------
__global__ void convert_x(const float* __restrict__ x, __half* __restrict__ xh)
{
    int idx = blockIdx.x * 256 + threadIdx.x;
    if (idx >= NN * K0P) return;
    int n = idx >> 7, c = idx & (K0P - 1);
    float v = (c < F_IN) ? x[n * F_IN + c] : 0.f;
    xh[idx] = __float2half_rn(v);
}

// ---------------- pack weights -> transposed fp16 ----------------
__global__ void pack_weights(const float* __restrict__ w0, const float* __restrict__ sw0,
                             const float* __restrict__ w1, const float* __restrict__ sw1,
                             const float* __restrict__ w2, const float* __restrict__ sw2,
                             __half* __restrict__ b0h, __half* __restrict__ b1h,
                             __half* __restrict__ b2h)
{
    int tid = blockIdx.x * blockDim.x + threadIdx.x;
    int stride = gridDim.x * blockDim.x;
    for (int i = tid; i < 512 * K0P; i += stride) {
        int n = i >> 7, k = i & (K0P - 1);
        float v = 0.f;
        if (k < F_IN) v = (n < HC) ? w0[k * HC + n] : sw0[k * HC + (n - HC)];
        b0h[i] = __float2half_rn(v);
    }
    for (int i = tid; i < 512 * HC; i += stride) {
        int n = i >> 8, k = i & (HC - 1);
        float v = (n < HC) ? w1[k * HC + n] : sw1[k * HC + (n - HC)];
        b1h[i] = __float2half_rn(v);
    }
    for (int i = tid; i < NP2 * HC; i += stride) {
        int n = i >> 8, k = i & (HC - 1);
        float v = 0.f;
        if (n < L2OUT) v = w2[k * L2OUT + n];
        else if (n < L2OUT + NCLS) v = sw2[k * NCLS + (n - L2OUT)];
        b2h[i] = __float2half_rn(v);
    }
}

// ---------------- CSR build (also clears als/ald for layer-0 fused logits) ---
__global__ void count_kernel(const int* __restrict__ dst, int* __restrict__ cnt,
                             float* __restrict__ als, float* __restrict__ ald)
{
    int e = blockIdx.x * blockDim.x + threadIdx.x;
    if (e < NN * HEADS) { als[e] = 0.f; ald[e] = 0.f; }
    if (e < EE) atomicAdd(&cnt[dst[e]], 1);
}

__global__ void scan_blocks(const int* __restrict__ cnt, int* __restrict__ part,
                            int* __restrict__ bsum)
{
    int t = threadIdx.x;
    int i = blockIdx.x * 256 + t;
    int lane = t & 31, wid = t >> 5;
    int v = (i < NN) ? cnt[i] : 0;
    int x = v;
#pragma unroll
    for (int off = 1; off < 32; off <<= 1) {
        int y = __shfl_up_sync(0xffffffffu, x, off);
        if (lane >= off) x += y;
    }
    __shared__ int wsum[8];
    if (lane == 31) wsum[wid] = x;
    __syncthreads();
    if (wid == 0 && lane < 8) {
        int w = wsum[lane];
#pragma unroll
        for (int off = 1; off < 8; off <<= 1) {
            int y = __shfl_up_sync(0xffu, w, off);
            if (lane >= off) w += y;
        }
        wsum[lane] = w;
    }
    __syncthreads();
    int base = (wid > 0) ? wsum[wid - 1] : 0;
    int incl = x + base;
    if (i < NN) part[i] = incl - v;
    if (t == 255) bsum[blockIdx.x] = incl;
}

__global__ void scan_totals(int* __restrict__ bsum)
{
    int t = threadIdx.x;
    int lane = t & 31, wid = t >> 5;
    int v = (t < NBLK) ? bsum[t] : 0;
    int x = v;
#pragma unroll
    for (int off = 1; off < 32; off <<= 1) {
        int y = __shfl_up_sync(0xffffffffu, x, off);
        if (lane >= off) x += y;
    }
    __shared__ int wsum[4];
    if (lane == 31) wsum[wid] = x;
    __syncthreads();
    if (wid == 0 && lane < 4) {
        int w = wsum[lane];
#pragma unroll
        for (int off = 1; off < 4; off <<= 1) {
            int y = __shfl_up_sync(0xfu, w, off);
            if (lane >= off) w += y;
        }
        wsum[lane] = w;
    }
    __syncthreads();
    int base = (wid > 0) ? wsum[wid - 1] : 0;
    if (t < NBLK) bsum[t] = x + base - v;
}

__global__ void scan_add(const int* __restrict__ part, const int* __restrict__ bsum,
                         int* __restrict__ rowptr, int* __restrict__ cursor)
{
    int i = blockIdx.x * 256 + threadIdx.x;
    if (i < NN) {
        int r = part[i] + bsum[i >> 8];
        rowptr[i] = r;
        cursor[i] = r;
    }
    if (i == NN) rowptr[NN] = EE;
}

__global__ void fill_kernel(const int* __restrict__ src, const int* __restrict__ dst,
                            int* __restrict__ cursor, int* __restrict__ csrc)
{
    int e = blockIdx.x * blockDim.x + threadIdx.x;
    if (e >= EE) return;
    int d = dst[e];
    int pos = atomicAdd(&cursor[d], 1);
    csrc[pos] = src[e];
}

// ---------------- pure fp16 tensor-core GEMM, 3-stage pipeline ------
#define BM 128
#define BN 128
#define BKK 32
#define BKP 40          // padded K stride in halves (80B rows, conflict-free ldmatrix)
#define OBH 5120
#define STGH 10240      // halves per stage
#define NSTG 3
#define SMEM_GEMM (NSTG * STGH * 2)   // 61440 bytes

__device__ __forceinline__ void mma16816(float* d, const unsigned* a, const unsigned* b)
{
    asm volatile(
        "mma.sync.aligned.m16n8k16.row.col.f32.f16.f16.f32 "
        "{%0,%1,%2,%3}, {%4,%5,%6,%7}, {%8,%9}, {%0,%1,%2,%3};"
        : "+f"(d[0]), "+f"(d[1]), "+f"(d[2]), "+f"(d[3])
        : "r"(a[0]), "r"(a[1]), "r"(a[2]), "r"(a[3]), "r"(b[0]), "r"(b[1]));
}

__device__ __forceinline__ void cp16(unsigned dst, const void* src, int sz)
{
    asm volatile("cp.async.ca.shared.global [%0], [%1], 16, %2;"
                 :: "r"(dst), "l"(src), "r"(sz));
}

__device__ __forceinline__ void ldm4(unsigned addr, unsigned& r0, unsigned& r1,
                                     unsigned& r2, unsigned& r3)
{
    asm volatile("ldmatrix.sync.aligned.m8n8.x4.shared.b16 {%0,%1,%2,%3}, [%4];"
                 : "=r"(r0), "=r"(r1), "=r"(r2), "=r"(r3) : "r"(addr));
}

__device__ __forceinline__ void issue_stage(
    unsigned sb, const __half* Ah, const __half* Bh,
    int rowBlock, int colBlock, int M, int KA, int k0, int sr, int sk)
{
#pragma unroll
    for (int i = 0; i < 2; i++) {
        int row = sr + i * 64;
        int gr = rowBlock + row;
        int sz = (gr < M) ? 16 : 0;
        size_t off = (size_t)(sz ? gr : 0) * KA + k0 + sk;
        cp16(sb + (unsigned)(row * BKP + sk) * 2, Ah + off, sz);
        int gc = colBlock + row;                    // Npack padded: always valid
        size_t boff = (size_t)gc * KA + k0 + sk;
        cp16(sb + (unsigned)(OBH + row * BKP + sk) * 2, Bh + boff, 16);
    }
    asm volatile("cp.async.commit_group;");
}

__global__ __launch_bounds__(256, 2) void hgemm_f16(
    const __half* __restrict__ Ah, const __half* __restrict__ Bh,
    const float* __restrict__ sbias, __half* __restrict__ hOut, float* __restrict__ skipOut,
    const float* __restrict__ aS, const float* __restrict__ aD,
    float* __restrict__ als, float* __restrict__ ald,
    int M, int KA, int Npack, int splitH, int splitS)
{
    extern __shared__ __half sm[];
    unsigned smB = (unsigned)__cvta_generic_to_shared(sm);

    int tid = threadIdx.x;
    int lane = tid & 31, wid = tid >> 5;
    int rowBlock = blockIdx.y * BM;
    int colBlock = blockIdx.x * BN;
    int wm = (wid & 1) * 64;
    int wn = (wid >> 1) * 32;
    int gID = lane >> 2, tig = lane & 3;

    float acc[4][4][4];
#pragma unroll
    for (int mt = 0; mt < 4; mt++)
#pragma unroll
        for (int nt = 0; nt < 4; nt++)
#pragma unroll
            for (int r = 0; r < 4; r++) acc[mt][nt][r] = 0.f;

    int kIters = KA >> 5;   // always >= 4 here
    int sr = tid >> 2;
    int sk = (tid & 3) * 8;

    int aRow = (lane & 15);
    int aCol = (lane & 16) >> 1;
    int bNrow = (lane & 7) + ((lane & 16) >> 1);
    int bCol = (lane & 8);

    issue_stage(smB, Ah, Bh, rowBlock, colBlock, M, KA, 0, sr, sk);
    issue_stage(smB + STGH * 2, Ah, Bh, rowBlock, colBlock, M, KA, BKK, sr, sk);

    int cur = 0;
    for (int it = 0; it < kIters; it++) {
        if (it + 1 < kIters) asm volatile("cp.async.wait_group 1;");
        else                 asm volatile("cp.async.wait_group 0;");
        __syncthreads();

        if (it + 2 < kIters) {
            int s2 = cur + 2; if (s2 >= NSTG) s2 -= NSTG;
            issue_stage(smB + (unsigned)s2 * STGH * 2, Ah, Bh,
                        rowBlock, colBlock, M, KA, (it + 2) * BKK, sr, sk);
        }

        unsigned aHb = smB + (unsigned)cur * STGH * 2;
        unsigned bHb = aHb + OBH * 2;

#pragma unroll
        for (int ks = 0; ks < 2; ks++) {
            int kk = ks * 16;
            unsigned bHf[8];
#pragma unroll
            for (int pair = 0; pair < 2; pair++) {
                int n = wn + pair * 16 + bNrow;
                unsigned off = (unsigned)(n * BKP + kk + bCol) * 2;
                ldm4(bHb + off, bHf[pair * 4 + 0], bHf[pair * 4 + 1],
                                bHf[pair * 4 + 2], bHf[pair * 4 + 3]);
            }
            unsigned aHf[4][4];
#pragma unroll
            for (int mt = 0; mt < 4; mt++) {
                int r = wm + mt * 16 + aRow;
                unsigned off = (unsigned)(r * BKP + kk + aCol) * 2;
                ldm4(aHb + off, aHf[mt][0], aHf[mt][1], aHf[mt][2], aHf[mt][3]);
            }
#pragma unroll
            for (int mt = 0; mt < 4; mt++)
#pragma unroll
                for (int nt = 0; nt < 4; nt++)
                    mma16816(acc[mt][nt], aHf[mt], &bHf[(nt >> 1) * 4 + (nt & 1) * 2]);
        }
        cur = (cur + 1 == NSTG) ? 0 : cur + 1;
    }

    // epilogue: route to hOut(fp16) / skipOut(fp32, +sbias)
#pragma unroll
    for (int mt = 0; mt < 4; mt++) {
        int gr0 = rowBlock + wm + mt * 16 + gID;
        int gr1 = gr0 + 8;
#pragma unroll
        for (int nt = 0; nt < 4; nt++) {
            int gc = colBlock + wn + nt * 8 + tig * 2;
#pragma unroll
            for (int half_ = 0; half_ < 2; half_++) {
                int gr = half_ ? gr1 : gr0;
                if (gr >= M) continue;
                float v0 = acc[mt][nt][half_ * 2 + 0];
                float v1 = acc[mt][nt][half_ * 2 + 1];
                if (gc < splitH) {        // pair aligned: both cols in region
                    *(__half2*)(hOut + (size_t)gr * splitH + gc) =
                        __floats2half2_rn(v0, v1);
                } else {
#pragma unroll
                    for (int j = 0; j < 2; j++) {
                        int c2 = gc + j;
                        if (c2 < splitH + splitS) {
                            int sc = c2 - splitH;
                            skipOut[(size_t)gr * splitS + sc] = (j ? v1 : v0) + sbias[sc];
                        }
                    }
                }
            }
        }
    }

    // fused attention-logit partials (layers 0/1: heads are 64-wide, warp span
    // of 32 cols sits in exactly one head)
    if (aS != nullptr && colBlock < splitH) {
        int head = (colBlock + wn) >> 6;
        int base = (colBlock + wn) & 63;
        float cs[8], cd[8];
#pragma unroll
        for (int nt = 0; nt < 4; nt++)
#pragma unroll
            for (int j = 0; j < 2; j++) {
                int lc = base + nt * 8 + tig * 2 + j;
                cs[nt * 2 + j] = aS[head * HID + lc];
                cd[nt * 2 + j] = aD[head * HID + lc];
            }
#pragma unroll
        for (int mt = 0; mt < 4; mt++)
#pragma unroll
            for (int half_ = 0; half_ < 2; half_++) {
                int gr = rowBlock + wm + mt * 16 + gID + half_ * 8;
                float ps = 0.f, pd = 0.f;
#pragma unroll
                for (int k = 0; k < 8; k++) {
                    float v = acc[mt][k >> 1][half_ * 2 + (k & 1)];
                    ps = fmaf(v, cs[k], ps);
                    pd = fmaf(v, cd[k], pd);
                }
                ps += __shfl_xor_sync(0xffffffffu, ps, 1);
                ps += __shfl_xor_sync(0xffffffffu, ps, 2);
                pd += __shfl_xor_sync(0xffffffffu, pd, 1);
                pd += __shfl_xor_sync(0xffffffffu, pd, 2);
                if (tig == 0 && gr < M) {
                    atomicAdd(&als[gr * HEADS + head], ps);
                    atomicAdd(&ald[gr * HEADS + head], pd);
                }
            }
    }
}

// ---------------- attention logits (fp16 h) — layer 2 only ----------------
__global__ void al_kernel(const __half* __restrict__ h, const float* __restrict__ a_s,
                          const float* __restrict__ a_d, float* __restrict__ als,
                          float* __restrict__ ald, int C)
{
    int w = (blockIdx.x * blockDim.x + threadIdx.x) >> 5;
    int lane = threadIdx.x & 31;
    if (w >= NN * HEADS) return;
    int n = w >> 2, hd = w & 3;
    const __half* hp = h + (size_t)n * (HEADS * C) + hd * C;
    float ss = 0.f, sd = 0.f;
    for (int c = lane; c < C; c += 32) {
        float v = __half2float(hp[c]);
        ss = fmaf(v, a_s[hd * C + c], ss);
        sd = fmaf(v, a_d[hd * C + c], sd);
    }
#pragma unroll
    for (int o = 16; o; o >>= 1) {
        ss += __shfl_xor_sync(0xffffffffu, ss, o);
        sd += __shfl_xor_sync(0xffffffffu, sd, o);
    }
    if (lane == 0) { als[w] = ss; ald[w] = sd; }
}

__device__ __forceinline__ void haccum(float e, uint4 u, float* ac)
{
    const __half2* p = (const __half2*)&u;
#pragma unroll
    for (int j = 0; j < 4; j++) {
        float2 f = __half22float2(p[j]);
        ac[2 * j]     = fmaf(e, f.x, ac[2 * j]);
        ac[2 * j + 1] = fmaf(e, f.y, ac[2 * j + 1]);
    }
}

// ---------------- fused GAT agg + bias + skip + BN-stats (layers 0/1) --------
__global__ __launch_bounds__(256) void gat_agg_kernel(
    const int* __restrict__ rowptr, const int* __restrict__ csrc,
    const __half* __restrict__ h, const float* __restrict__ als,
    const float* __restrict__ ald, const float* __restrict__ bias,
    const float* __restrict__ skip, float* __restrict__ outp, float* __restrict__ sums)
{
    __shared__ float slabS[8][HC];
    __shared__ float slabQ[8][HC];
    int tid = threadIdx.x;
    int w = (blockIdx.x * 256 + tid) >> 5;
    int lane = tid & 31;
    int wid = tid >> 5;
    int head = lane >> 3;
    float ad = ald[w * 4 + head];
    int beg = rowptr[w], end = rowptr[w + 1];
    float ac[8];
#pragma unroll
    for (int j = 0; j < 8; j++) ac[j] = 0.f;
    float den = 0.f;
    int i = beg;
    for (; i + 4 <= end; i += 4) {
        int s0 = csrc[i], s1 = csrc[i + 1], s2 = csrc[i + 2], s3 = csrc[i + 3];
        float A0 = als[s0 * 4 + head], A1 = als[s1 * 4 + head];
        float A2 = als[s2 * 4 + head], A3 = als[s3 * 4 + head];
        uint4 u0 = ((const uint4*)(h + (size_t)s0 * HC))[lane];
        uint4 u1 = ((const uint4*)(h + (size_t)s1 * HC))[lane];
        uint4 u2 = ((const uint4*)(h + (size_t)s2 * HC))[lane];
        uint4 u3 = ((const uint4*)(h + (size_t)s3 * HC))[lane];
        float e0 = expf(lrelu(A0 + ad));
        float e1 = expf(lrelu(A1 + ad));
        float e2 = expf(lrelu(A2 + ad));
        float e3 = expf(lrelu(A3 + ad));
        den += (e0 + e1) + (e2 + e3);
        haccum(e0, u0, ac);
        haccum(e1, u1, ac);
        haccum(e2, u2, ac);
        haccum(e3, u3, ac);
    }
    for (; i < end; i++) {
        int s = csrc[i];
        float e = expf(lrelu(als[s * 4 + head] + ad));
        den += e;
        uint4 u = ((const uint4*)(h + (size_t)s * HC))[lane];
        haccum(e, u, ac);
    }
    float inv = 1.f / (den + 1e-16f);
    int cbase = lane * 8;
    size_t obase = (size_t)w * HC + cbase;
    const float4* bp = (const float4*)(bias + cbase);
    const float4* sp = (const float4*)(skip + obase);
    float4 b0 = bp[0], b1 = bp[1];
    float4 s0 = sp[0], s1 = sp[1];
    float4 o0, o1;
    o0.x = fmaf(ac[0], inv, b0.x + s0.x); o0.y = fmaf(ac[1], inv, b0.y + s0.y);
    o0.z = fmaf(ac[2], inv, b0.z + s0.z); o0.w = fmaf(ac[3], inv, b0.w + s0.w);
    o1.x = fmaf(ac[4], inv, b1.x + s1.x); o1.y = fmaf(ac[5], inv, b1.y + s1.y);
    o1.z = fmaf(ac[6], inv, b1.z + s1.z); o1.w = fmaf(ac[7], inv, b1.w + s1.w);
    float4* op = (float4*)(outp + obase);
    op[0] = o0; op[1] = o1;

    // BN partials: per-warp exclusive slabs (no atomics), then one block reduce
    *(float4*)&slabS[wid][cbase] = o0;
    *(float4*)&slabS[wid][cbase + 4] = o1;
    float4 q0 = make_float4(o0.x * o0.x, o0.y * o0.y, o0.z * o0.z, o0.w * o0.w);
    float4 q1 = make_float4(o1.x * o1.x, o1.y * o1.y, o1.z * o1.z, o1.w * o1.w);
    *(float4*)&slabQ[wid][cbase] = q0;
    *(float4*)&slabQ[wid][cbase + 4] = q1;
    __syncthreads();
    float s = 0.f, q = 0.f;
#pragma unroll
    for (int ww = 0; ww < 8; ww++) { s += slabS[ww][tid]; q += slabQ[ww][tid]; }
    atomicAdd(&sums[tid], s);
    atomicAdd(&sums[HC + tid], q);
}

// ---------------- layer 2: agg + mean heads + bias + skip + log_softmax ------
__global__ __launch_bounds__(256) void gat_agg47_fused(
    const int* __restrict__ rowptr, const int* __restrict__ csrc,
    const __half* __restrict__ h, const float4* __restrict__ als,
    const float4* __restrict__ ald, const float* __restrict__ b2,
    const float* __restrict__ skip47, float* __restrict__ outp)
{
    int w = (blockIdx.x * blockDim.x + threadIdx.x) >> 5;
    int lane = threadIdx.x & 31;
    if (w >= NN) return;
    float4 ad = ald[w];
    int beg = rowptr[w], end = rowptr[w + 1];
    float a0 = 0.f, a1 = 0.f, a2 = 0.f, a3 = 0.f;
    float c0 = 0.f, c1 = 0.f, c2 = 0.f, c3 = 0.f;
    float d0 = 0.f, d1 = 0.f, d2 = 0.f, d3 = 0.f;
    bool has2 = (lane + 32) < NCLS;
    for (int i = beg; i < end; i++) {
        int s = csrc[i];
        float4 as4 = als[s];
        float e0 = expf(lrelu(as4.x + ad.x));
        float e1 = expf(lrelu(as4.y + ad.y));
        float e2 = expf(lrelu(as4.z + ad.z));
        float e3 = expf(lrelu(as4.w + ad.w));
        d0 += e0; d1 += e1; d2 += e2; d3 += e3;
        const __half* hs = h + (size_t)s * L2OUT;
        a0 = fmaf(e0, __half2float(hs[lane]), a0);
        a1 = fmaf(e1, __half2float(hs[NCLS + lane]), a1);
        a2 = fmaf(e2, __half2float(hs[2 * NCLS + lane]), a2);
        a3 = fmaf(e3, __half2float(hs[3 * NCLS + lane]), a3);
        if (has2) {
            int c = lane + 32;
            c0 = fmaf(e0, __half2float(hs[c]), c0);
            c1 = fmaf(e1, __half2float(hs[NCLS + c]), c1);
            c2 = fmaf(e2, __half2float(hs[2 * NCLS + c]), c2);
            c3 = fmaf(e3, __half2float(hs[3 * NCLS + c]), c3);
        }
    }
    float i0 = 1.f / (d0 + 1e-16f), i1 = 1.f / (d1 + 1e-16f);
    float i2 = 1.f / (d2 + 1e-16f), i3 = 1.f / (d3 + 1e-16f);
    float v0 = 0.25f * (a0 * i0 + a1 * i1 + a2 * i2 + a3 * i3)
             + b2[lane] + skip47[(size_t)w * NCLS + lane];
    float v1 = -1e30f;
    if (has2) {
        int c = lane + 32;
        v1 = 0.25f * (c0 * i0 + c1 * i1 + c2 * i2 + c3 * i3)
           + b2[c] + skip47[(size_t)w * NCLS + c];
    }
    float m = fmaxf(v0, v1);
#pragma unroll
    for (int o = 16; o; o >>= 1) m = fmaxf(m, __shfl_xor_sync(0xffffffffu, m, o));
    float s = expf(v0 - m) + (has2 ? expf(v1 - m) : 0.f);
#pragma unroll
    for (int o = 16; o; o >>= 1) s += __shfl_xor_sync(0xffffffffu, s, o);
    float lse = m + logf(s);
    outp[(size_t)w * NCLS + lane] = v0 - lse;
    if (has2) outp[(size_t)w * NCLS + lane + 32] = v1 - lse;
}

// ---------------- BN apply + ELU -> fp16 (also clears als/ald for next layer) -
__global__ void bn_apply_kernel(const float* __restrict__ pre, const float* __restrict__ sums,
                                const float* __restrict__ gamma, const float* __restrict__ beta,
                                __half* __restrict__ oh,
                                float* __restrict__ als, float* __restrict__ ald)
{
    int c = threadIdx.x;
    int t = blockIdx.x * 256 + c;             // grid 512 -> 131072 >= NN*HEADS
    if (t < NN * HEADS) { als[t] = 0.f; ald[t] = 0.f; }
    float mu = sums[c] * (1.f / NN);
    float var = sums[HC + c] * (1.f / NN) - mu * mu;
    float rstd = rsqrtf(var + 1e-5f);
    float g = gamma[c] * rstd;
    float b = beta[c] - mu * g;
    for (int r = blockIdx.x; r < NN; r += gridDim.x) {
        size_t idx = (size_t)r * HC + c;
        float v = fmaf(pre[idx], g, b);
        float o = v > 0.f ? v : expf(v) - 1.f;
        oh[idx] = __float2half_rn(o);
    }
}

// ---------------- host orchestration ----------------
extern "C" void kernel_launch(void* const* d_in, const int* in_sizes, int n_in,
                              void* d_out, int out_size)
{
    const float* x   = (const float*)d_in[0];
    const int*   ei  = (const int*)d_in[1];
    const float* w0  = (const float*)d_in[2];
    const float* as0 = (const float*)d_in[3];
    const float* ad0 = (const float*)d_in[4];
    const float* b0  = (const float*)d_in[5];
    const float* sw0 = (const float*)d_in[6];
    const float* sb0 = (const float*)d_in[7];
    const float* g0  = (const float*)d_in[8];
    const float* be0 = (const float*)d_in[9];
    const float* w1  = (const float*)d_in[10];
    const float* as1 = (const float*)d_in[11];
    const float* ad1 = (const float*)d_in[12];
    const float* b1  = (const float*)d_in[13];
    const float* sw1 = (const float*)d_in[14];
    const float* sb1 = (const float*)d_in[15];
    const float* g1  = (const float*)d_in[16];
    const float* be1 = (const float*)d_in[17];
    const float* w2  = (const float*)d_in[18];
    const float* as2 = (const float*)d_in[19];
    const float* ad2 = (const float*)d_in[20];
    const float* b2  = (const float*)d_in[21];
    const float* sw2 = (const float*)d_in[22];
    const float* sb2 = (const float*)d_in[23];

    const int* src = ei;
    const int* dst = ei + EE;

    float *skip, *agg, *als, *ald, *bnsum;
    __half *h, *xh, *ah, *b0h, *b1h, *b2h;
    int *cnt, *part, *bsum, *rowptr, *cursor, *csrc;
    cudaGetSymbolAddress((void**)&h, g_h);
    cudaGetSymbolAddress((void**)&skip, g_skip);
    cudaGetSymbolAddress((void**)&agg, g_agg);
    cudaGetSymbolAddress((void**)&als, g_als);
    cudaGetSymbolAddress((void**)&ald, g_ald);
    cudaGetSymbolAddress((void**)&bnsum, g_bnsum);
    cudaGetSymbolAddress((void**)&xh, g_xh);
    cudaGetSymbolAddress((void**)&ah, g_ah);
    cudaGetSymbolAddress((void**)&b0h, g_b0h);
    cudaGetSymbolAddress((void**)&b1h, g_b1h);
    cudaGetSymbolAddress((void**)&b2h, g_b2h);
    cudaGetSymbolAddress((void**)&cnt, g_cnt);
    cudaGetSymbolAddress((void**)&part, g_part);
    cudaGetSymbolAddress((void**)&bsum, g_bsum);
    cudaGetSymbolAddress((void**)&rowptr, g_rowptr);
    cudaGetSymbolAddress((void**)&cursor, g_cursor);
    cudaGetSymbolAddress((void**)&csrc, g_csrc);

    cudaFuncSetAttribute(hgemm_f16, cudaFuncAttributeMaxDynamicSharedMemorySize, SMEM_GEMM);

    dim3 gemm512(4, (NN + BM - 1) / BM);
    dim3 gemm256(2, (NN + BM - 1) / BM);
    int alBlocks = (NN * HEADS * 32 + 255) / 256;
    int nodeWarpBlocks = (NN * 32) / 256;
    int eBlocks = (EE + 255) / 256;

    // launch order keeps hgemm layer-0 as the 5th launch (profiler target)
    convert_x<<<(NN * K0P + 255) / 256, 256>>>(x, xh);                         // 1
    pack_weights<<<480, 256>>>(w0, sw0, w1, sw1, w2, sw2, b0h, b1h, b2h);      // 2
    cudaMemsetAsync(cnt, 0, NN * sizeof(int));                                 // 3
    count_kernel<<<eBlocks, 256>>>(dst, cnt, als, ald);                        // 4
    hgemm_f16<<<gemm512, 256, SMEM_GEMM>>>(xh, b0h, sb0, h, skip,
                                           as0, ad0, als, ald,
                                           NN, K0P, 512, HC, HC);              // 5
    scan_blocks<<<NBLK, 256>>>(cnt, part, bsum);
    scan_totals<<<1, 128>>>(bsum);
    scan_add<<<(NN + 256) / 256, 256>>>(part, bsum, rowptr, cursor);
    fill_kernel<<<eBlocks, 256>>>(src, dst, cursor, csrc);

    // ===== Layer 0 (agg + BN) =====
    cudaMemsetAsync(bnsum, 0, 2 * HC * sizeof(float));
    gat_agg_kernel<<<nodeWarpBlocks, 256>>>(rowptr, csrc, h, als, ald, b0, skip, agg, bnsum);
    bn_apply_kernel<<<512, 256>>>(agg, bnsum, g0, be0, ah, als, ald);  // clears als/ald

    // ===== Layer 1 =====
    hgemm_f16<<<gemm512, 256, SMEM_GEMM>>>(ah, b1h, sb1, h, skip,
                                           as1, ad1, als, ald, NN, HC, 512, HC, HC);
    cudaMemsetAsync(bnsum, 0, 2 * HC * sizeof(float));
    gat_agg_kernel<<<nodeWarpBlocks, 256>>>(rowptr, csrc, h, als, ald, b1, skip, agg, bnsum);
    bn_apply_kernel<<<512, 256>>>(agg, bnsum, g1, be1, ah, als, ald);

    // ===== Layer 2 =====
    hgemm_f16<<<gemm256, 256, SMEM_GEMM>>>(ah, b2h, sb2, h, skip,
                                           nullptr, nullptr, als, ald,
                                           NN, HC, NP2, L2OUT, NCLS);
    al_kernel<<<alBlocks, 256>>>(h, as2, ad2, als, ald, NCLS);
    gat_agg47_fused<<<nodeWarpBlocks, 256>>>(rowptr, csrc, h, (const float4*)als,
                                             (const float4*)ald, b2, skip, (float*)d_out);
}

// round 12
// speedup vs baseline: 1.4673x; 1.0420x over previous
#include <cuda_runtime.h>
#include <cuda_bf16.h>
#include <cuda_fp16.h>
#include <cstdint>
#include <math.h>

#define NN 30000
#define EE 480000
#define F_IN 100
#define HID 64
#define HEADS 4
#define NCLS 47
#define HC 256           // HEADS*HID
#define L2OUT 188        // HEADS*NCLS
#define NP2 256          // padded pack width layer2 (188 + 47 -> 256)
#define K0P 128          // padded K for layer 0 (100 -> 128)
#define NBLK 118         // ceil(NN/256)

// ---------------- scratch ----------------
__device__ __align__(16) __half g_h[(size_t)NN * HC];    // GAT-branch GEMM out (fp16)
__device__ __align__(16) float g_skip[(size_t)NN * HC];
__device__ __align__(16) float g_agg[(size_t)NN * HC];
__device__ __align__(16) float g_als[(size_t)NN * HEADS];
__device__ __align__(16) float g_ald[(size_t)NN * HEADS];
__device__ float g_bnsum0[2 * HC];
__device__ float g_bnsum1[2 * HC];
// fp16 activations (A-side)
__device__ __align__(16) __half g_xh[(size_t)NN * K0P];
__device__ __align__(16) __half g_ah[(size_t)NN * HC];
// fp16 transposed weights [n][k]
__device__ __align__(16) __half g_b0h[512 * K0P];
__device__ __align__(16) __half g_b1h[512 * HC];
__device__ __align__(16) __half g_b2h[NP2 * HC];
// CSR
__device__ int g_cnt[NN];
__device__ int g_part[NN];
__device__ int g_bsum[NBLK];
__device__ int g_rowptr[NN + 1];
__device__ int g_cursor[NN];
__device__ int g_csrc[EE];

__device__ __forceinline__ float lrelu(float x) { return x > 0.f ? x : 0.2f * x; }

// ---------------- prep: convert x, pack weights, zero cnt/als/ald/bnsum ------
__global__ void prep_kernel(const float* __restrict__ x, __half* __restrict__ xh,
                            const float* __restrict__ w0, const float* __restrict__ sw0,
                            const float* __restrict__ w1, const float* __restrict__ sw1,
                            const float* __restrict__ w2, const float* __restrict__ sw2,
                            __half* __restrict__ b0h, __half* __restrict__ b1h,
                            __half* __restrict__ b2h,
                            int* __restrict__ cnt, float* __restrict__ als,
                            float* __restrict__ ald, float* __restrict__ bns0,
                            float* __restrict__ bns1)
{
    int idx = blockIdx.x * 256 + threadIdx.x;   // grid covers NN*K0P = 3.84M
    if (idx < NN * K0P) {
        int n = idx >> 7, c = idx & (K0P - 1);
        float v = (c < F_IN) ? x[n * F_IN + c] : 0.f;
        xh[idx] = __float2half_rn(v);
    }
    if (idx < 512 * K0P) {
        int n = idx >> 7, k = idx & (K0P - 1);
        float v = 0.f;
        if (k < F_IN) v = (n < HC) ? w0[k * HC + n] : sw0[k * HC + (n - HC)];
        b0h[idx] = __float2half_rn(v);
    }
    if (idx < 512 * HC) {
        int n = idx >> 8, k = idx & (HC - 1);
        float v = (n < HC) ? w1[k * HC + n] : sw1[k * HC + (n - HC)];
        b1h[idx] = __float2half_rn(v);
    }
    if (idx < NP2 * HC) {
        int n = idx >> 8, k = idx & (HC - 1);
        float v = 0.f;
        if (n < L2OUT) v = w2[k * L2OUT + n];
        else if (n < L2OUT + NCLS) v = sw2[k * NCLS + (n - L2OUT)];
        b2h[idx] = __float2half_rn(v);
    }
    if (idx < NN) cnt[idx] = 0;
    if (idx < NN * HEADS) { als[idx] = 0.f; ald[idx] = 0.f; }
    if (idx < 2 * HC) { bns0[idx] = 0.f; bns1[idx] = 0.f; }
}

// ---------------- CSR build ----------------
__global__ void count_kernel(const int* __restrict__ dst, int* __restrict__ cnt)
{
    int e = blockIdx.x * blockDim.x + threadIdx.x;
    if (e < EE) atomicAdd(&cnt[dst[e]], 1);
}

__global__ void scan_blocks(const int* __restrict__ cnt, int* __restrict__ part,
                            int* __restrict__ bsum)
{
    int t = threadIdx.x;
    int i = blockIdx.x * 256 + t;
    int lane = t & 31, wid = t >> 5;
    int v = (i < NN) ? cnt[i] : 0;
    int x = v;
#pragma unroll
    for (int off = 1; off < 32; off <<= 1) {
        int y = __shfl_up_sync(0xffffffffu, x, off);
        if (lane >= off) x += y;
    }
    __shared__ int wsum[8];
    if (lane == 31) wsum[wid] = x;
    __syncthreads();
    if (wid == 0 && lane < 8) {
        int w = wsum[lane];
#pragma unroll
        for (int off = 1; off < 8; off <<= 1) {
            int y = __shfl_up_sync(0xffu, w, off);
            if (lane >= off) w += y;
        }
        wsum[lane] = w;
    }
    __syncthreads();
    int base = (wid > 0) ? wsum[wid - 1] : 0;
    int incl = x + base;
    if (i < NN) part[i] = incl - v;
    if (t == 255) bsum[blockIdx.x] = incl;
}

__global__ void scan_totals(int* __restrict__ bsum)
{
    int t = threadIdx.x;
    int lane = t & 31, wid = t >> 5;
    int v = (t < NBLK) ? bsum[t] : 0;
    int x = v;
#pragma unroll
    for (int off = 1; off < 32; off <<= 1) {
        int y = __shfl_up_sync(0xffffffffu, x, off);
        if (lane >= off) x += y;
    }
    __shared__ int wsum[4];
    if (lane == 31) wsum[wid] = x;
    __syncthreads();
    if (wid == 0 && lane < 4) {
        int w = wsum[lane];
#pragma unroll
        for (int off = 1; off < 4; off <<= 1) {
            int y = __shfl_up_sync(0xfu, w, off);
            if (lane >= off) w += y;
        }
        wsum[lane] = w;
    }
    __syncthreads();
    int base = (wid > 0) ? wsum[wid - 1] : 0;
    if (t < NBLK) bsum[t] = x + base - v;
}

__global__ void scan_add(const int* __restrict__ part, const int* __restrict__ bsum,
                         int* __restrict__ rowptr, int* __restrict__ cursor)
{
    int i = blockIdx.x * 256 + threadIdx.x;
    if (i < NN) {
        int r = part[i] + bsum[i >> 8];
        rowptr[i] = r;
        cursor[i] = r;
    }
    if (i == NN) rowptr[NN] = EE;
}

__global__ void fill_kernel(const int* __restrict__ src, const int* __restrict__ dst,
                            int* __restrict__ cursor, int* __restrict__ csrc)
{
    int e = blockIdx.x * blockDim.x + threadIdx.x;
    if (e >= EE) return;
    int d = dst[e];
    int pos = atomicAdd(&cursor[d], 1);
    csrc[pos] = src[e];
}

// ---------------- pure fp16 tensor-core GEMM, 3-stage pipeline ------
#define BM 128
#define BN 128
#define BKK 32
#define BKP 40          // padded K stride in halves (80B rows, conflict-free ldmatrix)
#define OBH 5120
#define STGH 10240      // halves per stage
#define NSTG 3
#define SMEM_GEMM (NSTG * STGH * 2)   // 61440 bytes

__device__ __forceinline__ void mma16816(float* d, const unsigned* a, const unsigned* b)
{
    asm volatile(
        "mma.sync.aligned.m16n8k16.row.col.f32.f16.f16.f32 "
        "{%0,%1,%2,%3}, {%4,%5,%6,%7}, {%8,%9}, {%0,%1,%2,%3};"
        : "+f"(d[0]), "+f"(d[1]), "+f"(d[2]), "+f"(d[3])
        : "r"(a[0]), "r"(a[1]), "r"(a[2]), "r"(a[3]), "r"(b[0]), "r"(b[1]));
}

__device__ __forceinline__ void cp16(unsigned dst, const void* src, int sz)
{
    asm volatile("cp.async.cg.shared.global [%0], [%1], 16, %2;"
                 :: "r"(dst), "l"(src), "r"(sz));
}

__device__ __forceinline__ void ldm4(unsigned addr, unsigned& r0, unsigned& r1,
                                     unsigned& r2, unsigned& r3)
{
    asm volatile("ldmatrix.sync.aligned.m8n8.x4.shared.b16 {%0,%1,%2,%3}, [%4];"
                 : "=r"(r0), "=r"(r1), "=r"(r2), "=r"(r3) : "r"(addr));
}

__device__ __forceinline__ void issue_stage(
    unsigned sb, const __half* Ah, const __half* Bh,
    int rowBlock, int colBlock, int M, int KA, int k0, int sr, int sk)
{
#pragma unroll
    for (int i = 0; i < 2; i++) {
        int row = sr + i * 64;
        int gr = rowBlock + row;
        int sz = (gr < M) ? 16 : 0;
        size_t off = (size_t)(sz ? gr : 0) * KA + k0 + sk;
        cp16(sb + (unsigned)(row * BKP + sk) * 2, Ah + off, sz);
        int gc = colBlock + row;                    // Npack padded: always valid
        size_t boff = (size_t)gc * KA + k0 + sk;
        cp16(sb + (unsigned)(OBH + row * BKP + sk) * 2, Bh + boff, 16);
    }
    asm volatile("cp.async.commit_group;");
}

__global__ __launch_bounds__(256, 2) void hgemm_f16(
    const __half* __restrict__ Ah, const __half* __restrict__ Bh,
    const float* __restrict__ sbias, __half* __restrict__ hOut, float* __restrict__ skipOut,
    const float* __restrict__ aS, const float* __restrict__ aD,
    float* __restrict__ als, float* __restrict__ ald,
    int M, int KA, int Npack, int splitH, int splitS)
{
    extern __shared__ __half sm[];
    unsigned smB = (unsigned)__cvta_generic_to_shared(sm);

    int tid = threadIdx.x;
    int lane = tid & 31, wid = tid >> 5;
    int rowBlock = blockIdx.y * BM;
    int colBlock = blockIdx.x * BN;
    int wm = (wid & 1) * 64;
    int wn = (wid >> 1) * 32;
    int gID = lane >> 2, tig = lane & 3;

    float acc[4][4][4];
#pragma unroll
    for (int mt = 0; mt < 4; mt++)
#pragma unroll
        for (int nt = 0; nt < 4; nt++)
#pragma unroll
            for (int r = 0; r < 4; r++) acc[mt][nt][r] = 0.f;

    int kIters = KA >> 5;   // always >= 4 here
    int sr = tid >> 2;
    int sk = (tid & 3) * 8;

    int aRow = (lane & 15);
    int aCol = (lane & 16) >> 1;
    int bNrow = (lane & 7) + ((lane & 16) >> 1);
    int bCol = (lane & 8);

    issue_stage(smB, Ah, Bh, rowBlock, colBlock, M, KA, 0, sr, sk);
    issue_stage(smB + STGH * 2, Ah, Bh, rowBlock, colBlock, M, KA, BKK, sr, sk);

    int cur = 0;
    for (int it = 0; it < kIters; it++) {
        if (it + 1 < kIters) asm volatile("cp.async.wait_group 1;");
        else                 asm volatile("cp.async.wait_group 0;");
        __syncthreads();

        if (it + 2 < kIters) {
            int s2 = cur + 2; if (s2 >= NSTG) s2 -= NSTG;
            issue_stage(smB + (unsigned)s2 * STGH * 2, Ah, Bh,
                        rowBlock, colBlock, M, KA, (it + 2) * BKK, sr, sk);
        }

        unsigned aHb = smB + (unsigned)cur * STGH * 2;
        unsigned bHb = aHb + OBH * 2;

#pragma unroll
        for (int ks = 0; ks < 2; ks++) {
            int kk = ks * 16;
            unsigned bHf[8];
#pragma unroll
            for (int pair = 0; pair < 2; pair++) {
                int n = wn + pair * 16 + bNrow;
                unsigned off = (unsigned)(n * BKP + kk + bCol) * 2;
                ldm4(bHb + off, bHf[pair * 4 + 0], bHf[pair * 4 + 1],
                                bHf[pair * 4 + 2], bHf[pair * 4 + 3]);
            }
            unsigned aHf[4][4];
#pragma unroll
            for (int mt = 0; mt < 4; mt++) {
                int r = wm + mt * 16 + aRow;
                unsigned off = (unsigned)(r * BKP + kk + aCol) * 2;
                ldm4(aHb + off, aHf[mt][0], aHf[mt][1], aHf[mt][2], aHf[mt][3]);
            }
#pragma unroll
            for (int mt = 0; mt < 4; mt++)
#pragma unroll
                for (int nt = 0; nt < 4; nt++)
                    mma16816(acc[mt][nt], aHf[mt], &bHf[(nt >> 1) * 4 + (nt & 1) * 2]);
        }
        cur = (cur + 1 == NSTG) ? 0 : cur + 1;
    }

    // epilogue: route to hOut(fp16) / skipOut(fp32, +sbias)
#pragma unroll
    for (int mt = 0; mt < 4; mt++) {
        int gr0 = rowBlock + wm + mt * 16 + gID;
        int gr1 = gr0 + 8;
#pragma unroll
        for (int nt = 0; nt < 4; nt++) {
            int gc = colBlock + wn + nt * 8 + tig * 2;
#pragma unroll
            for (int half_ = 0; half_ < 2; half_++) {
                int gr = half_ ? gr1 : gr0;
                if (gr >= M) continue;
                float v0 = acc[mt][nt][half_ * 2 + 0];
                float v1 = acc[mt][nt][half_ * 2 + 1];
                if (gc < splitH) {        // pair aligned: both cols in region
                    *(__half2*)(hOut + (size_t)gr * splitH + gc) =
                        __floats2half2_rn(v0, v1);
                } else {
#pragma unroll
                    for (int j = 0; j < 2; j++) {
                        int c2 = gc + j;
                        if (c2 < splitH + splitS) {
                            int sc = c2 - splitH;
                            skipOut[(size_t)gr * splitS + sc] = (j ? v1 : v0) + sbias[sc];
                        }
                    }
                }
            }
        }
    }

    // fused attention-logit partials (layers 0/1: heads are 64-wide, warp span
    // of 32 cols sits in exactly one head)
    if (aS != nullptr && colBlock < splitH) {
        int head = (colBlock + wn) >> 6;
        int base = (colBlock + wn) & 63;
        float cs[8], cd[8];
#pragma unroll
        for (int nt = 0; nt < 4; nt++)
#pragma unroll
            for (int j = 0; j < 2; j++) {
                int lc = base + nt * 8 + tig * 2 + j;
                cs[nt * 2 + j] = aS[head * HID + lc];
                cd[nt * 2 + j] = aD[head * HID + lc];
            }
#pragma unroll
        for (int mt = 0; mt < 4; mt++)
#pragma unroll
            for (int half_ = 0; half_ < 2; half_++) {
                int gr = rowBlock + wm + mt * 16 + gID + half_ * 8;
                float ps = 0.f, pd = 0.f;
#pragma unroll
                for (int k = 0; k < 8; k++) {
                    float v = acc[mt][k >> 1][half_ * 2 + (k & 1)];
                    ps = fmaf(v, cs[k], ps);
                    pd = fmaf(v, cd[k], pd);
                }
                ps += __shfl_xor_sync(0xffffffffu, ps, 1);
                ps += __shfl_xor_sync(0xffffffffu, ps, 2);
                pd += __shfl_xor_sync(0xffffffffu, pd, 1);
                pd += __shfl_xor_sync(0xffffffffu, pd, 2);
                if (tig == 0 && gr < M) {
                    atomicAdd(&als[gr * HEADS + head], ps);
                    atomicAdd(&ald[gr * HEADS + head], pd);
                }
            }
    }
}

// ---------------- attention logits (fp16 h) — layer 2 only ----------------
__global__ void al_kernel(const __half* __restrict__ h, const float* __restrict__ a_s,
                          const float* __restrict__ a_d, float* __restrict__ als,
                          float* __restrict__ ald, int C)
{
    int w = (blockIdx.x * blockDim.x + threadIdx.x) >> 5;
    int lane = threadIdx.x & 31;
    if (w >= NN * HEADS) return;
    int n = w >> 2, hd = w & 3;
    const __half* hp = h + (size_t)n * (HEADS * C) + hd * C;
    float ss = 0.f, sd = 0.f;
    for (int c = lane; c < C; c += 32) {
        float v = __half2float(hp[c]);
        ss = fmaf(v, a_s[hd * C + c], ss);
        sd = fmaf(v, a_d[hd * C + c], sd);
    }
#pragma unroll
    for (int o = 16; o; o >>= 1) {
        ss += __shfl_xor_sync(0xffffffffu, ss, o);
        sd += __shfl_xor_sync(0xffffffffu, sd, o);
    }
    if (lane == 0) { als[w] = ss; ald[w] = sd; }
}

__device__ __forceinline__ void haccum(float e, uint4 u, float* ac)
{
    const __half2* p = (const __half2*)&u;
#pragma unroll
    for (int j = 0; j < 4; j++) {
        float2 f = __half22float2(p[j]);
        ac[2 * j]     = fmaf(e, f.x, ac[2 * j]);
        ac[2 * j + 1] = fmaf(e, f.y, ac[2 * j + 1]);
    }
}

// ---------------- fused GAT agg + bias + skip + BN-stats (layers 0/1) --------
__global__ __launch_bounds__(256) void gat_agg_kernel(
    const int* __restrict__ rowptr, const int* __restrict__ csrc,
    const __half* __restrict__ h, const float* __restrict__ als,
    const float* __restrict__ ald, const float* __restrict__ bias,
    const float* __restrict__ skip, float* __restrict__ outp, float* __restrict__ sums)
{
    __shared__ float slabS[8][HC];
    __shared__ float slabQ[8][HC];
    int tid = threadIdx.x;
    int w = (blockIdx.x * 256 + tid) >> 5;
    int lane = tid & 31;
    int wid = tid >> 5;
    int head = lane >> 3;
    float ad = ald[w * 4 + head];
    int beg = rowptr[w], end = rowptr[w + 1];
    float ac[8];
#pragma unroll
    for (int j = 0; j < 8; j++) ac[j] = 0.f;
    float den = 0.f;
    int i = beg;
    for (; i + 4 <= end; i += 4) {
        int s0 = csrc[i], s1 = csrc[i + 1], s2 = csrc[i + 2], s3 = csrc[i + 3];
        float A0 = als[s0 * 4 + head], A1 = als[s1 * 4 + head];
        float A2 = als[s2 * 4 + head], A3 = als[s3 * 4 + head];
        uint4 u0 = ((const uint4*)(h + (size_t)s0 * HC))[lane];
        uint4 u1 = ((const uint4*)(h + (size_t)s1 * HC))[lane];
        uint4 u2 = ((const uint4*)(h + (size_t)s2 * HC))[lane];
        uint4 u3 = ((const uint4*)(h + (size_t)s3 * HC))[lane];
        float e0 = expf(lrelu(A0 + ad));
        float e1 = expf(lrelu(A1 + ad));
        float e2 = expf(lrelu(A2 + ad));
        float e3 = expf(lrelu(A3 + ad));
        den += (e0 + e1) + (e2 + e3);
        haccum(e0, u0, ac);
        haccum(e1, u1, ac);
        haccum(e2, u2, ac);
        haccum(e3, u3, ac);
    }
    for (; i < end; i++) {
        int s = csrc[i];
        float e = expf(lrelu(als[s * 4 + head] + ad));
        den += e;
        uint4 u = ((const uint4*)(h + (size_t)s * HC))[lane];
        haccum(e, u, ac);
    }
    float inv = 1.f / (den + 1e-16f);
    int cbase = lane * 8;
    size_t obase = (size_t)w * HC + cbase;
    const float4* bp = (const float4*)(bias + cbase);
    const float4* sp = (const float4*)(skip + obase);
    float4 b0 = bp[0], b1 = bp[1];
    float4 s0 = sp[0], s1 = sp[1];
    float4 o0, o1;
    o0.x = fmaf(ac[0], inv, b0.x + s0.x); o0.y = fmaf(ac[1], inv, b0.y + s0.y);
    o0.z = fmaf(ac[2], inv, b0.z + s0.z); o0.w = fmaf(ac[3], inv, b0.w + s0.w);
    o1.x = fmaf(ac[4], inv, b1.x + s1.x); o1.y = fmaf(ac[5], inv, b1.y + s1.y);
    o1.z = fmaf(ac[6], inv, b1.z + s1.z); o1.w = fmaf(ac[7], inv, b1.w + s1.w);
    float4* op = (float4*)(outp + obase);
    op[0] = o0; op[1] = o1;

    // BN partials: per-warp exclusive slabs (no atomics), then one block reduce
    *(float4*)&slabS[wid][cbase] = o0;
    *(float4*)&slabS[wid][cbase + 4] = o1;
    float4 q0 = make_float4(o0.x * o0.x, o0.y * o0.y, o0.z * o0.z, o0.w * o0.w);
    float4 q1 = make_float4(o1.x * o1.x, o1.y * o1.y, o1.z * o1.z, o1.w * o1.w);
    *(float4*)&slabQ[wid][cbase] = q0;
    *(float4*)&slabQ[wid][cbase + 4] = q1;
    __syncthreads();
    float s = 0.f, q = 0.f;
#pragma unroll
    for (int ww = 0; ww < 8; ww++) { s += slabS[ww][tid]; q += slabQ[ww][tid]; }
    atomicAdd(&sums[tid], s);
    atomicAdd(&sums[HC + tid], q);
}

// ---------------- layer 2: agg + mean heads + bias + skip + log_softmax ------
__global__ __launch_bounds__(256) void gat_agg47_fused(
    const int* __restrict__ rowptr, const int* __restrict__ csrc,
    const __half* __restrict__ h, const float4* __restrict__ als,
    const float4* __restrict__ ald, const float* __restrict__ b2,
    const float* __restrict__ skip47, float* __restrict__ outp)
{
    int w = (blockIdx.x * blockDim.x + threadIdx.x) >> 5;
    int lane = threadIdx.x & 31;
    if (w >= NN) return;
    float4 ad = ald[w];
    int beg = rowptr[w], end = rowptr[w + 1];
    float a0 = 0.f, a1 = 0.f, a2 = 0.f, a3 = 0.f;
    float c0 = 0.f, c1 = 0.f, c2 = 0.f, c3 = 0.f;
    float d0 = 0.f, d1 = 0.f, d2 = 0.f, d3 = 0.f;
    bool has2 = (lane + 32) < NCLS;
    for (int i = beg; i < end; i++) {
        int s = csrc[i];
        float4 as4 = als[s];
        float e0 = expf(lrelu(as4.x + ad.x));
        float e1 = expf(lrelu(as4.y + ad.y));
        float e2 = expf(lrelu(as4.z + ad.z));
        float e3 = expf(lrelu(as4.w + ad.w));
        d0 += e0; d1 += e1; d2 += e2; d3 += e3;
        const __half* hs = h + (size_t)s * L2OUT;
        a0 = fmaf(e0, __half2float(hs[lane]), a0);
        a1 = fmaf(e1, __half2float(hs[NCLS + lane]), a1);
        a2 = fmaf(e2, __half2float(hs[2 * NCLS + lane]), a2);
        a3 = fmaf(e3, __half2float(hs[3 * NCLS + lane]), a3);
        if (has2) {
            int c = lane + 32;
            c0 = fmaf(e0, __half2float(hs[c]), c0);
            c1 = fmaf(e1, __half2float(hs[NCLS + c]), c1);
            c2 = fmaf(e2, __half2float(hs[2 * NCLS + c]), c2);
            c3 = fmaf(e3, __half2float(hs[3 * NCLS + c]), c3);
        }
    }
    float i0 = 1.f / (d0 + 1e-16f), i1 = 1.f / (d1 + 1e-16f);
    float i2 = 1.f / (d2 + 1e-16f), i3 = 1.f / (d3 + 1e-16f);
    float v0 = 0.25f * (a0 * i0 + a1 * i1 + a2 * i2 + a3 * i3)
             + b2[lane] + skip47[(size_t)w * NCLS + lane];
    float v1 = -1e30f;
    if (has2) {
        int c = lane + 32;
        v1 = 0.25f * (c0 * i0 + c1 * i1 + c2 * i2 + c3 * i3)
           + b2[c] + skip47[(size_t)w * NCLS + c];
    }
    float m = fmaxf(v0, v1);
#pragma unroll
    for (int o = 16; o; o >>= 1) m = fmaxf(m, __shfl_xor_sync(0xffffffffu, m, o));
    float s = expf(v0 - m) + (has2 ? expf(v1 - m) : 0.f);
#pragma unroll
    for (int o = 16; o; o >>= 1) s += __shfl_xor_sync(0xffffffffu, s, o);
    float lse = m + logf(s);
    outp[(size_t)w * NCLS + lane] = v0 - lse;
    if (has2) outp[(size_t)w * NCLS + lane + 32] = v1 - lse;
}

// ---------------- BN apply + ELU -> fp16 (also clears als/ald for next layer) -
__global__ void bn_apply_kernel(const float* __restrict__ pre, const float* __restrict__ sums,
                                const float* __restrict__ gamma, const float* __restrict__ beta,
                                __half* __restrict__ oh,
                                float* __restrict__ als, float* __restrict__ ald)
{
    int c = threadIdx.x;
    int t = blockIdx.x * 256 + c;             // grid 512 -> 131072 >= NN*HEADS
    if (t < NN * HEADS) { als[t] = 0.f; ald[t] = 0.f; }
    float mu = sums[c] * (1.f / NN);
    float var = sums[HC + c] * (1.f / NN) - mu * mu;
    float rstd = rsqrtf(var + 1e-5f);
    float g = gamma[c] * rstd;
    float b = beta[c] - mu * g;
    for (int r = blockIdx.x; r < NN; r += gridDim.x) {
        size_t idx = (size_t)r * HC + c;
        float v = fmaf(pre[idx], g, b);
        float o = v > 0.f ? v : expf(v) - 1.f;
        oh[idx] = __float2half_rn(o);
    }
}

// ---------------- host orchestration ----------------
extern "C" void kernel_launch(void* const* d_in, const int* in_sizes, int n_in,
                              void* d_out, int out_size)
{
    const float* x   = (const float*)d_in[0];
    const int*   ei  = (const int*)d_in[1];
    const float* w0  = (const float*)d_in[2];
    const float* as0 = (const float*)d_in[3];
    const float* ad0 = (const float*)d_in[4];
    const float* b0  = (const float*)d_in[5];
    const float* sw0 = (const float*)d_in[6];
    const float* sb0 = (const float*)d_in[7];
    const float* g0  = (const float*)d_in[8];
    const float* be0 = (const float*)d_in[9];
    const float* w1  = (const float*)d_in[10];
    const float* as1 = (const float*)d_in[11];
    const float* ad1 = (const float*)d_in[12];
    const float* b1  = (const float*)d_in[13];
    const float* sw1 = (const float*)d_in[14];
    const float* sb1 = (const float*)d_in[15];
    const float* g1  = (const float*)d_in[16];
    const float* be1 = (const float*)d_in[17];
    const float* w2  = (const float*)d_in[18];
    const float* as2 = (const float*)d_in[19];
    const float* ad2 = (const float*)d_in[20];
    const float* b2  = (const float*)d_in[21];
    const float* sw2 = (const float*)d_in[22];
    const float* sb2 = (const float*)d_in[23];

    const int* src = ei;
    const int* dst = ei + EE;

    float *skip, *agg, *als, *ald, *bns0, *bns1;
    __half *h, *xh, *ah, *b0h, *b1h, *b2h;
    int *cnt, *part, *bsum, *rowptr, *cursor, *csrc;
    cudaGetSymbolAddress((void**)&h, g_h);
    cudaGetSymbolAddress((void**)&skip, g_skip);
    cudaGetSymbolAddress((void**)&agg, g_agg);
    cudaGetSymbolAddress((void**)&als, g_als);
    cudaGetSymbolAddress((void**)&ald, g_ald);
    cudaGetSymbolAddress((void**)&bns0, g_bnsum0);
    cudaGetSymbolAddress((void**)&bns1, g_bnsum1);
    cudaGetSymbolAddress((void**)&xh, g_xh);
    cudaGetSymbolAddress((void**)&ah, g_ah);
    cudaGetSymbolAddress((void**)&b0h, g_b0h);
    cudaGetSymbolAddress((void**)&b1h, g_b1h);
    cudaGetSymbolAddress((void**)&b2h, g_b2h);
    cudaGetSymbolAddress((void**)&cnt, g_cnt);
    cudaGetSymbolAddress((void**)&part, g_part);
    cudaGetSymbolAddress((void**)&bsum, g_bsum);
    cudaGetSymbolAddress((void**)&rowptr, g_rowptr);
    cudaGetSymbolAddress((void**)&cursor, g_cursor);
    cudaGetSymbolAddress((void**)&csrc, g_csrc);

    cudaFuncSetAttribute(hgemm_f16, cudaFuncAttributeMaxDynamicSharedMemorySize, SMEM_GEMM);

    dim3 gemm512(4, (NN + BM - 1) / BM);
    dim3 gemm256(2, (NN + BM - 1) / BM);
    int alBlocks = (NN * HEADS * 32 + 255) / 256;
    int nodeWarpBlocks = (NN * 32) / 256;
    int eBlocks = (EE + 255) / 256;

    // launch order keeps hgemm layer-0 as the 5th launch (profiler target)
    prep_kernel<<<(NN * K0P + 255) / 256, 256>>>(x, xh, w0, sw0, w1, sw1, w2, sw2,
                                                 b0h, b1h, b2h, cnt, als, ald,
                                                 bns0, bns1);                  // 1
    count_kernel<<<eBlocks, 256>>>(dst, cnt);                                  // 2
    scan_blocks<<<NBLK, 256>>>(cnt, part, bsum);                               // 3
    scan_totals<<<1, 128>>>(bsum);                                             // 4
    hgemm_f16<<<gemm512, 256, SMEM_GEMM>>>(xh, b0h, sb0, h, skip,
                                           as0, ad0, als, ald,
                                           NN, K0P, 512, HC, HC);              // 5
    scan_add<<<(NN + 256) / 256, 256>>>(part, bsum, rowptr, cursor);           // 6
    fill_kernel<<<eBlocks, 256>>>(src, dst, cursor, csrc);                     // 7

    // ===== Layer 0 (agg + BN) =====
    gat_agg_kernel<<<nodeWarpBlocks, 256>>>(rowptr, csrc, h, als, ald, b0, skip, agg, bns0);
    bn_apply_kernel<<<512, 256>>>(agg, bns0, g0, be0, ah, als, ald);  // clears als/ald

    // ===== Layer 1 =====
    hgemm_f16<<<gemm512, 256, SMEM_GEMM>>>(ah, b1h, sb1, h, skip,
                                           as1, ad1, als, ald, NN, HC, 512, HC, HC);
    gat_agg_kernel<<<nodeWarpBlocks, 256>>>(rowptr, csrc, h, als, ald, b1, skip, agg, bns1);
    bn_apply_kernel<<<512, 256>>>(agg, bns1, g1, be1, ah, als, ald);

    // ===== Layer 2 =====
    hgemm_f16<<<gemm256, 256, SMEM_GEMM>>>(ah, b2h, sb2, h, skip,
                                           nullptr, nullptr, als, ald,
                                           NN, HC, NP2, L2OUT, NCLS);
    al_kernel<<<alBlocks, 256>>>(h, as2, ad2, als, ald, NCLS);
    gat_agg47_fused<<<nodeWarpBlocks, 256>>>(rowptr, csrc, h, (const float4*)als,
                                             (const float4*)ald, b2, skip, (float*)d_out);
}

// round 13
// speedup vs baseline: 1.5422x; 1.0510x over previous
#include <cuda_runtime.h>
#include <cuda_bf16.h>
#include <cuda_fp16.h>
#include <cstdint>
#include <math.h>

#define NN 30000
#define EE 480000
#define F_IN 100
#define HID 64
#define HEADS 4
#define NCLS 47
#define HC 256           // HEADS*HID
#define L2OUT 188        // HEADS*NCLS
#define NP2 256          // padded pack width layer2 (188 + 47 -> 256)
#define K0P 128          // padded K for layer 0 (100 -> 128)
#define NBLK 118         // ceil(NN/256)

// ---------------- scratch ----------------
__device__ __align__(16) __half g_h[(size_t)NN * HC];    // GAT-branch GEMM out (fp16)
__device__ __align__(16) __half g_skip[(size_t)NN * HC]; // skip branch (fp16)
__device__ __align__(16) __half g_agg[(size_t)NN * HC];  // pre-BN (fp16; stats exact fp32)
__device__ __align__(16) float g_als[(size_t)NN * HEADS];
__device__ __align__(16) float g_ald[(size_t)NN * HEADS];
__device__ float g_bnsum0[2 * HC];
__device__ float g_bnsum1[2 * HC];
// fp16 activations (A-side)
__device__ __align__(16) __half g_xh[(size_t)NN * K0P];
__device__ __align__(16) __half g_ah[(size_t)NN * HC];
// fp16 transposed weights [n][k]
__device__ __align__(16) __half g_b0h[512 * K0P];
__device__ __align__(16) __half g_b1h[512 * HC];
__device__ __align__(16) __half g_b2h[NP2 * HC];
// CSR
__device__ int g_cnt[NN];
__device__ int g_part[NN];
__device__ int g_bsum[NBLK];
__device__ int g_rowptr[NN + 1];
__device__ int g_cursor[NN];
__device__ int g_csrc[EE];

__device__ __forceinline__ float lrelu(float x) { return x > 0.f ? x : 0.2f * x; }

// ---------------- prep: convert x, pack weights, zero cnt/als/ald/bnsum ------
__global__ void prep_kernel(const float* __restrict__ x, __half* __restrict__ xh,
                            const float* __restrict__ w0, const float* __restrict__ sw0,
                            const float* __restrict__ w1, const float* __restrict__ sw1,
                            const float* __restrict__ w2, const float* __restrict__ sw2,
                            __half* __restrict__ b0h, __half* __restrict__ b1h,
                            __half* __restrict__ b2h,
                            int* __restrict__ cnt, float* __restrict__ als,
                            float* __restrict__ ald, float* __restrict__ bns0,
                            float* __restrict__ bns1)
{
    int idx = blockIdx.x * 256 + threadIdx.x;   // grid covers NN*K0P = 3.84M
    if (idx < NN * K0P) {
        int n = idx >> 7, c = idx & (K0P - 1);
        float v = (c < F_IN) ? x[n * F_IN + c] : 0.f;
        xh[idx] = __float2half_rn(v);
    }
    if (idx < 512 * K0P) {
        int n = idx >> 7, k = idx & (K0P - 1);
        float v = 0.f;
        if (k < F_IN) v = (n < HC) ? w0[k * HC + n] : sw0[k * HC + (n - HC)];
        b0h[idx] = __float2half_rn(v);
    }
    if (idx < 512 * HC) {
        int n = idx >> 8, k = idx & (HC - 1);
        float v = (n < HC) ? w1[k * HC + n] : sw1[k * HC + (n - HC)];
        b1h[idx] = __float2half_rn(v);
    }
    if (idx < NP2 * HC) {
        int n = idx >> 8, k = idx & (HC - 1);
        float v = 0.f;
        if (n < L2OUT) v = w2[k * L2OUT + n];
        else if (n < L2OUT + NCLS) v = sw2[k * NCLS + (n - L2OUT)];
        b2h[idx] = __float2half_rn(v);
    }
    if (idx < NN) cnt[idx] = 0;
    if (idx < NN * HEADS) { als[idx] = 0.f; ald[idx] = 0.f; }
    if (idx < 2 * HC) { bns0[idx] = 0.f; bns1[idx] = 0.f; }
}

// ---------------- CSR build ----------------
__global__ void count_kernel(const int* __restrict__ dst, int* __restrict__ cnt)
{
    int e = blockIdx.x * blockDim.x + threadIdx.x;
    if (e < EE) atomicAdd(&cnt[dst[e]], 1);
}

__global__ void scan_blocks(const int* __restrict__ cnt, int* __restrict__ part,
                            int* __restrict__ bsum)
{
    int t = threadIdx.x;
    int i = blockIdx.x * 256 + t;
    int lane = t & 31, wid = t >> 5;
    int v = (i < NN) ? cnt[i] : 0;
    int x = v;
#pragma unroll
    for (int off = 1; off < 32; off <<= 1) {
        int y = __shfl_up_sync(0xffffffffu, x, off);
        if (lane >= off) x += y;
    }
    __shared__ int wsum[8];
    if (lane == 31) wsum[wid] = x;
    __syncthreads();
    if (wid == 0 && lane < 8) {
        int w = wsum[lane];
#pragma unroll
        for (int off = 1; off < 8; off <<= 1) {
            int y = __shfl_up_sync(0xffu, w, off);
            if (lane >= off) w += y;
        }
        wsum[lane] = w;
    }
    __syncthreads();
    int base = (wid > 0) ? wsum[wid - 1] : 0;
    int incl = x + base;
    if (i < NN) part[i] = incl - v;
    if (t == 255) bsum[blockIdx.x] = incl;   // raw per-block total
}

// scan_add now also computes the block-prefix of bsum itself (scan_totals removed)
__global__ void scan_add(const int* __restrict__ part, const int* __restrict__ bsum,
                         int* __restrict__ rowptr, int* __restrict__ cursor)
{
    __shared__ int red[256];
    int b = blockIdx.x;
    int t = threadIdx.x;
    int acc = 0;
    for (int j = t; j < b; j += 256) acc += bsum[j];
    red[t] = acc;
    __syncthreads();
#pragma unroll
    for (int s = 128; s > 0; s >>= 1) {
        if (t < s) red[t] += red[t + s];
        __syncthreads();
    }
    int off = red[0];
    int i = b * 256 + t;
    if (i < NN) {
        int r = part[i] + off;
        rowptr[i] = r;
        cursor[i] = r;
    }
    if (i == NN) rowptr[NN] = EE;
}

__global__ void fill_kernel(const int* __restrict__ src, const int* __restrict__ dst,
                            int* __restrict__ cursor, int* __restrict__ csrc)
{
    int e = blockIdx.x * blockDim.x + threadIdx.x;
    if (e >= EE) return;
    int d = dst[e];
    int pos = atomicAdd(&cursor[d], 1);
    csrc[pos] = src[e];
}

// ---------------- pure fp16 tensor-core GEMM, 3-stage pipeline ------
#define BM 128
#define BN 128
#define BKK 32
#define BKP 40          // padded K stride in halves (80B rows, conflict-free ldmatrix)
#define OBH 5120
#define STGH 10240      // halves per stage
#define NSTG 3
#define SMEM_GEMM (NSTG * STGH * 2)   // 61440 bytes

__device__ __forceinline__ void mma16816(float* d, const unsigned* a, const unsigned* b)
{
    asm volatile(
        "mma.sync.aligned.m16n8k16.row.col.f32.f16.f16.f32 "
        "{%0,%1,%2,%3}, {%4,%5,%6,%7}, {%8,%9}, {%0,%1,%2,%3};"
        : "+f"(d[0]), "+f"(d[1]), "+f"(d[2]), "+f"(d[3])
        : "r"(a[0]), "r"(a[1]), "r"(a[2]), "r"(a[3]), "r"(b[0]), "r"(b[1]));
}

__device__ __forceinline__ void cp16(unsigned dst, const void* src, int sz)
{
    asm volatile("cp.async.cg.shared.global [%0], [%1], 16, %2;"
                 :: "r"(dst), "l"(src), "r"(sz));
}

__device__ __forceinline__ void ldm4(unsigned addr, unsigned& r0, unsigned& r1,
                                     unsigned& r2, unsigned& r3)
{
    asm volatile("ldmatrix.sync.aligned.m8n8.x4.shared.b16 {%0,%1,%2,%3}, [%4];"
                 : "=r"(r0), "=r"(r1), "=r"(r2), "=r"(r3) : "r"(addr));
}

__device__ __forceinline__ void issue_stage(
    unsigned sb, const __half* Ah, const __half* Bh,
    int rowBlock, int colBlock, int M, int KA, int k0, int sr, int sk)
{
#pragma unroll
    for (int i = 0; i < 2; i++) {
        int row = sr + i * 64;
        int gr = rowBlock + row;
        int sz = (gr < M) ? 16 : 0;
        size_t off = (size_t)(sz ? gr : 0) * KA + k0 + sk;
        cp16(sb + (unsigned)(row * BKP + sk) * 2, Ah + off, sz);
        int gc = colBlock + row;                    // Npack padded: always valid
        size_t boff = (size_t)gc * KA + k0 + sk;
        cp16(sb + (unsigned)(OBH + row * BKP + sk) * 2, Bh + boff, 16);
    }
    asm volatile("cp.async.commit_group;");
}

__global__ __launch_bounds__(256, 2) void hgemm_f16(
    const __half* __restrict__ Ah, const __half* __restrict__ Bh,
    const float* __restrict__ sbias, __half* __restrict__ hOut, __half* __restrict__ skipOut,
    const float* __restrict__ aS, const float* __restrict__ aD,
    float* __restrict__ als, float* __restrict__ ald,
    int M, int KA, int Npack, int splitH, int splitS)
{
    extern __shared__ __half sm[];
    unsigned smB = (unsigned)__cvta_generic_to_shared(sm);

    int tid = threadIdx.x;
    int lane = tid & 31, wid = tid >> 5;
    int rowBlock = blockIdx.y * BM;
    int colBlock = blockIdx.x * BN;
    int wm = (wid & 1) * 64;
    int wn = (wid >> 1) * 32;
    int gID = lane >> 2, tig = lane & 3;

    float acc[4][4][4];
#pragma unroll
    for (int mt = 0; mt < 4; mt++)
#pragma unroll
        for (int nt = 0; nt < 4; nt++)
#pragma unroll
            for (int r = 0; r < 4; r++) acc[mt][nt][r] = 0.f;

    int kIters = KA >> 5;   // always >= 4 here
    int sr = tid >> 2;
    int sk = (tid & 3) * 8;

    int aRow = (lane & 15);
    int aCol = (lane & 16) >> 1;
    int bNrow = (lane & 7) + ((lane & 16) >> 1);
    int bCol = (lane & 8);

    issue_stage(smB, Ah, Bh, rowBlock, colBlock, M, KA, 0, sr, sk);
    issue_stage(smB + STGH * 2, Ah, Bh, rowBlock, colBlock, M, KA, BKK, sr, sk);

    int cur = 0;
    for (int it = 0; it < kIters; it++) {
        if (it + 1 < kIters) asm volatile("cp.async.wait_group 1;");
        else                 asm volatile("cp.async.wait_group 0;");
        __syncthreads();

        if (it + 2 < kIters) {
            int s2 = cur + 2; if (s2 >= NSTG) s2 -= NSTG;
            issue_stage(smB + (unsigned)s2 * STGH * 2, Ah, Bh,
                        rowBlock, colBlock, M, KA, (it + 2) * BKK, sr, sk);
        }

        unsigned aHb = smB + (unsigned)cur * STGH * 2;
        unsigned bHb = aHb + OBH * 2;

#pragma unroll
        for (int ks = 0; ks < 2; ks++) {
            int kk = ks * 16;
            unsigned bHf[8];
#pragma unroll
            for (int pair = 0; pair < 2; pair++) {
                int n = wn + pair * 16 + bNrow;
                unsigned off = (unsigned)(n * BKP + kk + bCol) * 2;
                ldm4(bHb + off, bHf[pair * 4 + 0], bHf[pair * 4 + 1],
                                bHf[pair * 4 + 2], bHf[pair * 4 + 3]);
            }
            unsigned aHf[4][4];
#pragma unroll
            for (int mt = 0; mt < 4; mt++) {
                int r = wm + mt * 16 + aRow;
                unsigned off = (unsigned)(r * BKP + kk + aCol) * 2;
                ldm4(aHb + off, aHf[mt][0], aHf[mt][1], aHf[mt][2], aHf[mt][3]);
            }
#pragma unroll
            for (int mt = 0; mt < 4; mt++)
#pragma unroll
                for (int nt = 0; nt < 4; nt++)
                    mma16816(acc[mt][nt], aHf[mt], &bHf[(nt >> 1) * 4 + (nt & 1) * 2]);
        }
        cur = (cur + 1 == NSTG) ? 0 : cur + 1;
    }

    // epilogue: route to hOut(fp16) / skipOut(fp16, +sbias)
    bool skipVec = ((splitS & 1) == 0);     // half2-safe row stride
#pragma unroll
    for (int mt = 0; mt < 4; mt++) {
        int gr0 = rowBlock + wm + mt * 16 + gID;
        int gr1 = gr0 + 8;
#pragma unroll
        for (int nt = 0; nt < 4; nt++) {
            int gc = colBlock + wn + nt * 8 + tig * 2;
#pragma unroll
            for (int half_ = 0; half_ < 2; half_++) {
                int gr = half_ ? gr1 : gr0;
                if (gr >= M) continue;
                float v0 = acc[mt][nt][half_ * 2 + 0];
                float v1 = acc[mt][nt][half_ * 2 + 1];
                if (gc < splitH) {        // pair aligned: both cols in region
                    *(__half2*)(hOut + (size_t)gr * splitH + gc) =
                        __floats2half2_rn(v0, v1);
                } else if (skipVec && gc + 1 < splitH + splitS) {
                    int sc = gc - splitH;
                    *(__half2*)(skipOut + (size_t)gr * splitS + sc) =
                        __floats2half2_rn(v0 + sbias[sc], v1 + sbias[sc + 1]);
                } else {
#pragma unroll
                    for (int j = 0; j < 2; j++) {
                        int c2 = gc + j;
                        if (c2 < splitH + splitS) {
                            int sc = c2 - splitH;
                            skipOut[(size_t)gr * splitS + sc] =
                                __float2half_rn((j ? v1 : v0) + sbias[sc]);
                        }
                    }
                }
            }
        }
    }

    // fused attention-logit partials (layers 0/1: heads are 64-wide, warp span
    // of 32 cols sits in exactly one head)
    if (aS != nullptr && colBlock < splitH) {
        int head = (colBlock + wn) >> 6;
        int base = (colBlock + wn) & 63;
        float cs[8], cd[8];
#pragma unroll
        for (int nt = 0; nt < 4; nt++)
#pragma unroll
            for (int j = 0; j < 2; j++) {
                int lc = base + nt * 8 + tig * 2 + j;
                cs[nt * 2 + j] = aS[head * HID + lc];
                cd[nt * 2 + j] = aD[head * HID + lc];
            }
#pragma unroll
        for (int mt = 0; mt < 4; mt++)
#pragma unroll
            for (int half_ = 0; half_ < 2; half_++) {
                int gr = rowBlock + wm + mt * 16 + gID + half_ * 8;
                float ps = 0.f, pd = 0.f;
#pragma unroll
                for (int k = 0; k < 8; k++) {
                    float v = acc[mt][k >> 1][half_ * 2 + (k & 1)];
                    ps = fmaf(v, cs[k], ps);
                    pd = fmaf(v, cd[k], pd);
                }
                ps += __shfl_xor_sync(0xffffffffu, ps, 1);
                ps += __shfl_xor_sync(0xffffffffu, ps, 2);
                pd += __shfl_xor_sync(0xffffffffu, pd, 1);
                pd += __shfl_xor_sync(0xffffffffu, pd, 2);
                if (tig == 0 && gr < M) {
                    atomicAdd(&als[gr * HEADS + head], ps);
                    atomicAdd(&ald[gr * HEADS + head], pd);
                }
            }
    }
}

// ---------------- attention logits (fp16 h) — layer 2 only ----------------
__global__ void al_kernel(const __half* __restrict__ h, const float* __restrict__ a_s,
                          const float* __restrict__ a_d, float* __restrict__ als,
                          float* __restrict__ ald, int C)
{
    int w = (blockIdx.x * blockDim.x + threadIdx.x) >> 5;
    int lane = threadIdx.x & 31;
    if (w >= NN * HEADS) return;
    int n = w >> 2, hd = w & 3;
    const __half* hp = h + (size_t)n * (HEADS * C) + hd * C;
    float ss = 0.f, sd = 0.f;
    for (int c = lane; c < C; c += 32) {
        float v = __half2float(hp[c]);
        ss = fmaf(v, a_s[hd * C + c], ss);
        sd = fmaf(v, a_d[hd * C + c], sd);
    }
#pragma unroll
    for (int o = 16; o; o >>= 1) {
        ss += __shfl_xor_sync(0xffffffffu, ss, o);
        sd += __shfl_xor_sync(0xffffffffu, sd, o);
    }
    if (lane == 0) { als[w] = ss; ald[w] = sd; }
}

__device__ __forceinline__ void haccum(float e, uint4 u, float* ac)
{
    const __half2* p = (const __half2*)&u;
#pragma unroll
    for (int j = 0; j < 4; j++) {
        float2 f = __half22float2(p[j]);
        ac[2 * j]     = fmaf(e, f.x, ac[2 * j]);
        ac[2 * j + 1] = fmaf(e, f.y, ac[2 * j + 1]);
    }
}

// ---------------- fused GAT agg + bias + skip + BN-stats (layers 0/1) --------
__global__ __launch_bounds__(256) void gat_agg_kernel(
    const int* __restrict__ rowptr, const int* __restrict__ csrc,
    const __half* __restrict__ h, const float* __restrict__ als,
    const float* __restrict__ ald, const float* __restrict__ bias,
    const __half* __restrict__ skip, __half* __restrict__ outp, float* __restrict__ sums)
{
    __shared__ float slabS[8][HC];
    __shared__ float slabQ[8][HC];
    int tid = threadIdx.x;
    int w = (blockIdx.x * 256 + tid) >> 5;
    int lane = tid & 31;
    int wid = tid >> 5;
    int head = lane >> 3;
    float ad = ald[w * 4 + head];
    int beg = rowptr[w], end = rowptr[w + 1];
    float ac[8];
#pragma unroll
    for (int j = 0; j < 8; j++) ac[j] = 0.f;
    float den = 0.f;
    int i = beg;
    for (; i + 4 <= end; i += 4) {
        int s0 = csrc[i], s1 = csrc[i + 1], s2 = csrc[i + 2], s3 = csrc[i + 3];
        float A0 = als[s0 * 4 + head], A1 = als[s1 * 4 + head];
        float A2 = als[s2 * 4 + head], A3 = als[s3 * 4 + head];
        uint4 u0 = ((const uint4*)(h + (size_t)s0 * HC))[lane];
        uint4 u1 = ((const uint4*)(h + (size_t)s1 * HC))[lane];
        uint4 u2 = ((const uint4*)(h + (size_t)s2 * HC))[lane];
        uint4 u3 = ((const uint4*)(h + (size_t)s3 * HC))[lane];
        float e0 = expf(lrelu(A0 + ad));
        float e1 = expf(lrelu(A1 + ad));
        float e2 = expf(lrelu(A2 + ad));
        float e3 = expf(lrelu(A3 + ad));
        den += (e0 + e1) + (e2 + e3);
        haccum(e0, u0, ac);
        haccum(e1, u1, ac);
        haccum(e2, u2, ac);
        haccum(e3, u3, ac);
    }
    for (; i < end; i++) {
        int s = csrc[i];
        float e = expf(lrelu(als[s * 4 + head] + ad));
        den += e;
        uint4 u = ((const uint4*)(h + (size_t)s * HC))[lane];
        haccum(e, u, ac);
    }
    float inv = 1.f / (den + 1e-16f);
    int cbase = lane * 8;
    size_t obase = (size_t)w * HC + cbase;
    const float4* bp = (const float4*)(bias + cbase);
    float4 b0 = bp[0], b1 = bp[1];
    uint4 su = *(const uint4*)(skip + obase);
    float sf[8];
    {
        const __half2* p = (const __half2*)&su;
#pragma unroll
        for (int j = 0; j < 4; j++) {
            float2 f = __half22float2(p[j]);
            sf[2 * j] = f.x; sf[2 * j + 1] = f.y;
        }
    }
    float o[8];
    o[0] = fmaf(ac[0], inv, b0.x + sf[0]); o[1] = fmaf(ac[1], inv, b0.y + sf[1]);
    o[2] = fmaf(ac[2], inv, b0.z + sf[2]); o[3] = fmaf(ac[3], inv, b0.w + sf[3]);
    o[4] = fmaf(ac[4], inv, b1.x + sf[4]); o[5] = fmaf(ac[5], inv, b1.y + sf[5]);
    o[6] = fmaf(ac[6], inv, b1.z + sf[6]); o[7] = fmaf(ac[7], inv, b1.w + sf[7]);
    // store pre-BN as fp16 (stats below remain exact fp32)
    uint4 st;
    __half2* stp = (__half2*)&st;
#pragma unroll
    for (int j = 0; j < 4; j++) stp[j] = __floats2half2_rn(o[2 * j], o[2 * j + 1]);
    *(uint4*)(outp + obase) = st;

    // BN partials: per-warp exclusive slabs (no atomics), then one block reduce
#pragma unroll
    for (int j = 0; j < 8; j++) {
        slabS[wid][cbase + j] = o[j];
        slabQ[wid][cbase + j] = o[j] * o[j];
    }
    __syncthreads();
    float s = 0.f, q = 0.f;
#pragma unroll
    for (int ww = 0; ww < 8; ww++) { s += slabS[ww][tid]; q += slabQ[ww][tid]; }
    atomicAdd(&sums[tid], s);
    atomicAdd(&sums[HC + tid], q);
}

// ---------------- layer 2: agg + mean heads + bias + skip + log_softmax ------
__global__ __launch_bounds__(256) void gat_agg47_fused(
    const int* __restrict__ rowptr, const int* __restrict__ csrc,
    const __half* __restrict__ h, const float4* __restrict__ als,
    const float4* __restrict__ ald, const float* __restrict__ b2,
    const __half* __restrict__ skip47, float* __restrict__ outp)
{
    int w = (blockIdx.x * blockDim.x + threadIdx.x) >> 5;
    int lane = threadIdx.x & 31;
    if (w >= NN) return;
    float4 ad = ald[w];
    int beg = rowptr[w], end = rowptr[w + 1];
    float a0 = 0.f, a1 = 0.f, a2 = 0.f, a3 = 0.f;
    float c0 = 0.f, c1 = 0.f, c2 = 0.f, c3 = 0.f;
    float d0 = 0.f, d1 = 0.f, d2 = 0.f, d3 = 0.f;
    bool has2 = (lane + 32) < NCLS;
    for (int i = beg; i < end; i++) {
        int s = csrc[i];
        float4 as4 = als[s];
        float e0 = expf(lrelu(as4.x + ad.x));
        float e1 = expf(lrelu(as4.y + ad.y));
        float e2 = expf(lrelu(as4.z + ad.z));
        float e3 = expf(lrelu(as4.w + ad.w));
        d0 += e0; d1 += e1; d2 += e2; d3 += e3;
        const __half* hs = h + (size_t)s * L2OUT;
        a0 = fmaf(e0, __half2float(hs[lane]), a0);
        a1 = fmaf(e1, __half2float(hs[NCLS + lane]), a1);
        a2 = fmaf(e2, __half2float(hs[2 * NCLS + lane]), a2);
        a3 = fmaf(e3, __half2float(hs[3 * NCLS + lane]), a3);
        if (has2) {
            int c = lane + 32;
            c0 = fmaf(e0, __half2float(hs[c]), c0);
            c1 = fmaf(e1, __half2float(hs[NCLS + c]), c1);
            c2 = fmaf(e2, __half2float(hs[2 * NCLS + c]), c2);
            c3 = fmaf(e3, __half2float(hs[3 * NCLS + c]), c3);
        }
    }
    float i0 = 1.f / (d0 + 1e-16f), i1 = 1.f / (d1 + 1e-16f);
    float i2 = 1.f / (d2 + 1e-16f), i3 = 1.f / (d3 + 1e-16f);
    float v0 = 0.25f * (a0 * i0 + a1 * i1 + a2 * i2 + a3 * i3)
             + b2[lane] + __half2float(skip47[(size_t)w * NCLS + lane]);
    float v1 = -1e30f;
    if (has2) {
        int c = lane + 32;
        v1 = 0.25f * (c0 * i0 + c1 * i1 + c2 * i2 + c3 * i3)
           + b2[c] + __half2float(skip47[(size_t)w * NCLS + c]);
    }
    float m = fmaxf(v0, v1);
#pragma unroll
    for (int o = 16; o; o >>= 1) m = fmaxf(m, __shfl_xor_sync(0xffffffffu, m, o));
    float s = expf(v0 - m) + (has2 ? expf(v1 - m) : 0.f);
#pragma unroll
    for (int o = 16; o; o >>= 1) s += __shfl_xor_sync(0xffffffffu, s, o);
    float lse = m + logf(s);
    outp[(size_t)w * NCLS + lane] = v0 - lse;
    if (has2) outp[(size_t)w * NCLS + lane + 32] = v1 - lse;
}

// ---------------- BN apply + ELU -> fp16 (also clears als/ald for next layer) -
__global__ void bn_apply_kernel(const __half* __restrict__ pre, const float* __restrict__ sums,
                                const float* __restrict__ gamma, const float* __restrict__ beta,
                                __half* __restrict__ oh,
                                float* __restrict__ als, float* __restrict__ ald)
{
    int c = threadIdx.x;
    int t = blockIdx.x * 256 + c;             // grid 512 -> 131072 >= NN*HEADS
    if (t < NN * HEADS) { als[t] = 0.f; ald[t] = 0.f; }
    float mu = sums[c] * (1.f / NN);
    float var = sums[HC + c] * (1.f / NN) - mu * mu;
    float rstd = rsqrtf(var + 1e-5f);
    float g = gamma[c] * rstd;
    float b = beta[c] - mu * g;
    for (int r = blockIdx.x; r < NN; r += gridDim.x) {
        size_t idx = (size_t)r * HC + c;
        float v = fmaf(__half2float(pre[idx]), g, b);
        float o = v > 0.f ? v : expf(v) - 1.f;
        oh[idx] = __float2half_rn(o);
    }
}

// ---------------- host orchestration ----------------
extern "C" void kernel_launch(void* const* d_in, const int* in_sizes, int n_in,
                              void* d_out, int out_size)
{
    const float* x   = (const float*)d_in[0];
    const int*   ei  = (const int*)d_in[1];
    const float* w0  = (const float*)d_in[2];
    const float* as0 = (const float*)d_in[3];
    const float* ad0 = (const float*)d_in[4];
    const float* b0  = (const float*)d_in[5];
    const float* sw0 = (const float*)d_in[6];
    const float* sb0 = (const float*)d_in[7];
    const float* g0  = (const float*)d_in[8];
    const float* be0 = (const float*)d_in[9];
    const float* w1  = (const float*)d_in[10];
    const float* as1 = (const float*)d_in[11];
    const float* ad1 = (const float*)d_in[12];
    const float* b1  = (const float*)d_in[13];
    const float* sw1 = (const float*)d_in[14];
    const float* sb1 = (const float*)d_in[15];
    const float* g1  = (const float*)d_in[16];
    const float* be1 = (const float*)d_in[17];
    const float* w2  = (const float*)d_in[18];
    const float* as2 = (const float*)d_in[19];
    const float* ad2 = (const float*)d_in[20];
    const float* b2  = (const float*)d_in[21];
    const float* sw2 = (const float*)d_in[22];
    const float* sb2 = (const float*)d_in[23];

    const int* src = ei;
    const int* dst = ei + EE;

    float *als, *ald, *bns0, *bns1;
    __half *h, *skip, *agg, *xh, *ah, *b0h, *b1h, *b2h;
    int *cnt, *part, *bsum, *rowptr, *cursor, *csrc;
    cudaGetSymbolAddress((void**)&h, g_h);
    cudaGetSymbolAddress((void**)&skip, g_skip);
    cudaGetSymbolAddress((void**)&agg, g_agg);
    cudaGetSymbolAddress((void**)&als, g_als);
    cudaGetSymbolAddress((void**)&ald, g_ald);
    cudaGetSymbolAddress((void**)&bns0, g_bnsum0);
    cudaGetSymbolAddress((void**)&bns1, g_bnsum1);
    cudaGetSymbolAddress((void**)&xh, g_xh);
    cudaGetSymbolAddress((void**)&ah, g_ah);
    cudaGetSymbolAddress((void**)&b0h, g_b0h);
    cudaGetSymbolAddress((void**)&b1h, g_b1h);
    cudaGetSymbolAddress((void**)&b2h, g_b2h);
    cudaGetSymbolAddress((void**)&cnt, g_cnt);
    cudaGetSymbolAddress((void**)&part, g_part);
    cudaGetSymbolAddress((void**)&bsum, g_bsum);
    cudaGetSymbolAddress((void**)&rowptr, g_rowptr);
    cudaGetSymbolAddress((void**)&cursor, g_cursor);
    cudaGetSymbolAddress((void**)&csrc, g_csrc);

    cudaFuncSetAttribute(hgemm_f16, cudaFuncAttributeMaxDynamicSharedMemorySize, SMEM_GEMM);

    dim3 gemm512(4, (NN + BM - 1) / BM);
    dim3 gemm256(2, (NN + BM - 1) / BM);
    int alBlocks = (NN * HEADS * 32 + 255) / 256;
    int nodeWarpBlocks = (NN * 32) / 256;
    int eBlocks = (EE + 255) / 256;

    // launch order keeps hgemm layer-0 as the 5th launch (profiler target)
    prep_kernel<<<(NN * K0P + 255) / 256, 256>>>(x, xh, w0, sw0, w1, sw1, w2, sw2,
                                                 b0h, b1h, b2h, cnt, als, ald,
                                                 bns0, bns1);                  // 1
    count_kernel<<<eBlocks, 256>>>(dst, cnt);                                  // 2
    scan_blocks<<<NBLK, 256>>>(cnt, part, bsum);                               // 3
    scan_add<<<(NN + 256) / 256, 256>>>(part, bsum, rowptr, cursor);           // 4
    hgemm_f16<<<gemm512, 256, SMEM_GEMM>>>(xh, b0h, sb0, h, skip,
                                           as0, ad0, als, ald,
                                           NN, K0P, 512, HC, HC);              // 5
    fill_kernel<<<eBlocks, 256>>>(src, dst, cursor, csrc);                     // 6

    // ===== Layer 0 (agg + BN) =====
    gat_agg_kernel<<<nodeWarpBlocks, 256>>>(rowptr, csrc, h, als, ald, b0, skip, agg, bns0);
    bn_apply_kernel<<<512, 256>>>(agg, bns0, g0, be0, ah, als, ald);  // clears als/ald

    // ===== Layer 1 =====
    hgemm_f16<<<gemm512, 256, SMEM_GEMM>>>(ah, b1h, sb1, h, skip,
                                           as1, ad1, als, ald, NN, HC, 512, HC, HC);
    gat_agg_kernel<<<nodeWarpBlocks, 256>>>(rowptr, csrc, h, als, ald, b1, skip, agg, bns1);
    bn_apply_kernel<<<512, 256>>>(agg, bns1, g1, be1, ah, als, ald);

    // ===== Layer 2 =====
    hgemm_f16<<<gemm256, 256, SMEM_GEMM>>>(ah, b2h, sb2, h, skip,
                                           nullptr, nullptr, als, ald,
                                           NN, HC, NP2, L2OUT, NCLS);
    al_kernel<<<alBlocks, 256>>>(h, as2, ad2, als, ald, NCLS);
    gat_agg47_fused<<<nodeWarpBlocks, 256>>>(rowptr, csrc, h, (const float4*)als,
                                             (const float4*)ald, b2, skip, (float*)d_out);
}

// round 14
// speedup vs baseline: 1.5667x; 1.0159x over previous
#include <cuda_runtime.h>
#include <cuda_bf16.h>
#include <cuda_fp16.h>
#include <cstdint>
#include <math.h>

#define NN 30000
#define EE 480000
#define F_IN 100
#define HID 64
#define HEADS 4
#define NCLS 47
#define HC 256           // HEADS*HID
#define L2OUT 188        // HEADS*NCLS
#define NP2 256          // padded pack width layer2 (188 + 47 -> 256)
#define K0P 128          // padded K for layer 0 (100 -> 128)
#define NBLK 118         // ceil(NN/256)

// ---------------- scratch ----------------
__device__ __align__(16) __half g_h[(size_t)NN * HC];    // GAT-branch GEMM out (fp16)
__device__ __align__(16) __half g_skip[(size_t)NN * HC]; // skip branch (fp16)
__device__ __align__(16) __half g_agg[(size_t)NN * HC];  // pre-BN (fp16; stats exact fp32)
__device__ __align__(16) float g_als[(size_t)NN * HEADS];
__device__ __align__(16) float g_ald[(size_t)NN * HEADS];
__device__ float g_bnsum0[2 * HC];
__device__ float g_bnsum1[2 * HC];
// fp16 activations (A-side)
__device__ __align__(16) __half g_xh[(size_t)NN * K0P];
__device__ __align__(16) __half g_ah[(size_t)NN * HC];
// fp16 transposed weights [n][k]
__device__ __align__(16) __half g_b0h[512 * K0P];
__device__ __align__(16) __half g_b1h[512 * HC];
__device__ __align__(16) __half g_b2h[NP2 * HC];
// CSR
__device__ int g_cnt[NN];
__device__ int g_part[NN];
__device__ int g_bsum[NBLK];
__device__ int g_rowptr[NN + 1];
__device__ int g_cursor[NN];
__device__ int g_csrc[EE];

__device__ __forceinline__ float lrelu(float x) { return x > 0.f ? x : 0.2f * x; }

// ---------------- prep: convert x, pack weights, zero cnt/als/ald/bnsum ------
__global__ void prep_kernel(const float* __restrict__ x, __half* __restrict__ xh,
                            const float* __restrict__ w0, const float* __restrict__ sw0,
                            const float* __restrict__ w1, const float* __restrict__ sw1,
                            const float* __restrict__ w2, const float* __restrict__ sw2,
                            __half* __restrict__ b0h, __half* __restrict__ b1h,
                            __half* __restrict__ b2h,
                            int* __restrict__ cnt, float* __restrict__ als,
                            float* __restrict__ ald, float* __restrict__ bns0,
                            float* __restrict__ bns1)
{
    int idx = blockIdx.x * 256 + threadIdx.x;   // grid covers NN*K0P = 3.84M
    if (idx < NN * K0P) {
        int n = idx >> 7, c = idx & (K0P - 1);
        float v = (c < F_IN) ? x[n * F_IN + c] : 0.f;
        xh[idx] = __float2half_rn(v);
    }
    if (idx < 512 * K0P) {
        int n = idx >> 7, k = idx & (K0P - 1);
        float v = 0.f;
        if (k < F_IN) v = (n < HC) ? w0[k * HC + n] : sw0[k * HC + (n - HC)];
        b0h[idx] = __float2half_rn(v);
    }
    if (idx < 512 * HC) {
        int n = idx >> 8, k = idx & (HC - 1);
        float v = (n < HC) ? w1[k * HC + n] : sw1[k * HC + (n - HC)];
        b1h[idx] = __float2half_rn(v);
    }
    if (idx < NP2 * HC) {
        int n = idx >> 8, k = idx & (HC - 1);
        float v = 0.f;
        if (n < L2OUT) v = w2[k * L2OUT + n];
        else if (n < L2OUT + NCLS) v = sw2[k * NCLS + (n - L2OUT)];
        b2h[idx] = __float2half_rn(v);
    }
    if (idx < NN) cnt[idx] = 0;
    if (idx < NN * HEADS) { als[idx] = 0.f; ald[idx] = 0.f; }
    if (idx < 2 * HC) { bns0[idx] = 0.f; bns1[idx] = 0.f; }
}

// ---------------- CSR build ----------------
__global__ void count_kernel(const int* __restrict__ dst, int* __restrict__ cnt)
{
    int e = blockIdx.x * blockDim.x + threadIdx.x;
    if (e < EE) atomicAdd(&cnt[dst[e]], 1);
}

__global__ void scan_blocks(const int* __restrict__ cnt, int* __restrict__ part,
                            int* __restrict__ bsum)
{
    int t = threadIdx.x;
    int i = blockIdx.x * 256 + t;
    int lane = t & 31, wid = t >> 5;
    int v = (i < NN) ? cnt[i] : 0;
    int x = v;
#pragma unroll
    for (int off = 1; off < 32; off <<= 1) {
        int y = __shfl_up_sync(0xffffffffu, x, off);
        if (lane >= off) x += y;
    }
    __shared__ int wsum[8];
    if (lane == 31) wsum[wid] = x;
    __syncthreads();
    if (wid == 0 && lane < 8) {
        int w = wsum[lane];
#pragma unroll
        for (int off = 1; off < 8; off <<= 1) {
            int y = __shfl_up_sync(0xffu, w, off);
            if (lane >= off) w += y;
        }
        wsum[lane] = w;
    }
    __syncthreads();
    int base = (wid > 0) ? wsum[wid - 1] : 0;
    int incl = x + base;
    if (i < NN) part[i] = incl - v;
    if (t == 255) bsum[blockIdx.x] = incl;   // raw per-block total
}

// scan_add computes the block-prefix of bsum itself
__global__ void scan_add(const int* __restrict__ part, const int* __restrict__ bsum,
                         int* __restrict__ rowptr, int* __restrict__ cursor)
{
    __shared__ int red[256];
    int b = blockIdx.x;
    int t = threadIdx.x;
    int acc = 0;
    for (int j = t; j < b; j += 256) acc += bsum[j];
    red[t] = acc;
    __syncthreads();
#pragma unroll
    for (int s = 128; s > 0; s >>= 1) {
        if (t < s) red[t] += red[t + s];
        __syncthreads();
    }
    int off = red[0];
    int i = b * 256 + t;
    if (i < NN) {
        int r = part[i] + off;
        rowptr[i] = r;
        cursor[i] = r;
    }
    if (i == NN) rowptr[NN] = EE;
}

__global__ void fill_kernel(const int* __restrict__ src, const int* __restrict__ dst,
                            int* __restrict__ cursor, int* __restrict__ csrc)
{
    int e = blockIdx.x * blockDim.x + threadIdx.x;
    if (e >= EE) return;
    int d = dst[e];
    int pos = atomicAdd(&cursor[d], 1);
    csrc[pos] = src[e];
}

// ---------------- pure fp16 tensor-core GEMM, 4-stage pipeline ------
#define BM 128
#define BN 128
#define BKK 32
#define BKP 40          // padded K stride in halves (80B rows, conflict-free ldmatrix)
#define OBH 5120
#define STGH 10240      // halves per stage
#define NSTG 4
#define SMEM_GEMM (NSTG * STGH * 2)   // 81920 bytes

__device__ __forceinline__ void mma16816(float* d, const unsigned* a, const unsigned* b)
{
    asm volatile(
        "mma.sync.aligned.m16n8k16.row.col.f32.f16.f16.f32 "
        "{%0,%1,%2,%3}, {%4,%5,%6,%7}, {%8,%9}, {%0,%1,%2,%3};"
        : "+f"(d[0]), "+f"(d[1]), "+f"(d[2]), "+f"(d[3])
        : "r"(a[0]), "r"(a[1]), "r"(a[2]), "r"(a[3]), "r"(b[0]), "r"(b[1]));
}

__device__ __forceinline__ void cp16(unsigned dst, const void* src, int sz)
{
    asm volatile("cp.async.cg.shared.global [%0], [%1], 16, %2;"
                 :: "r"(dst), "l"(src), "r"(sz));
}

__device__ __forceinline__ void ldm4(unsigned addr, unsigned& r0, unsigned& r1,
                                     unsigned& r2, unsigned& r3)
{
    asm volatile("ldmatrix.sync.aligned.m8n8.x4.shared.b16 {%0,%1,%2,%3}, [%4];"
                 : "=r"(r0), "=r"(r1), "=r"(r2), "=r"(r3) : "r"(addr));
}

__device__ __forceinline__ void issue_stage(
    unsigned sb, const __half* Ah, const __half* Bh,
    int rowBlock, int colBlock, int M, int KA, int k0, int sr, int sk)
{
#pragma unroll
    for (int i = 0; i < 2; i++) {
        int row = sr + i * 64;
        int gr = rowBlock + row;
        int sz = (gr < M) ? 16 : 0;
        size_t off = (size_t)(sz ? gr : 0) * KA + k0 + sk;
        cp16(sb + (unsigned)(row * BKP + sk) * 2, Ah + off, sz);
        int gc = colBlock + row;                    // Npack padded: always valid
        size_t boff = (size_t)gc * KA + k0 + sk;
        cp16(sb + (unsigned)(OBH + row * BKP + sk) * 2, Bh + boff, 16);
    }
    asm volatile("cp.async.commit_group;");
}

__global__ __launch_bounds__(256, 2) void hgemm_f16(
    const __half* __restrict__ Ah, const __half* __restrict__ Bh,
    const float* __restrict__ sbias, __half* __restrict__ hOut, __half* __restrict__ skipOut,
    const float* __restrict__ aS, const float* __restrict__ aD,
    float* __restrict__ als, float* __restrict__ ald,
    int M, int KA, int Npack, int splitH, int splitS)
{
    extern __shared__ __half sm[];
    unsigned smB = (unsigned)__cvta_generic_to_shared(sm);

    int tid = threadIdx.x;
    int lane = tid & 31, wid = tid >> 5;
    int rowBlock = blockIdx.y * BM;
    int colBlock = blockIdx.x * BN;
    int wm = (wid & 1) * 64;
    int wn = (wid >> 1) * 32;
    int gID = lane >> 2, tig = lane & 3;

    float acc[4][4][4];
#pragma unroll
    for (int mt = 0; mt < 4; mt++)
#pragma unroll
        for (int nt = 0; nt < 4; nt++)
#pragma unroll
            for (int r = 0; r < 4; r++) acc[mt][nt][r] = 0.f;

    int kIters = KA >> 5;   // always >= 4 here
    int sr = tid >> 2;
    int sk = (tid & 3) * 8;

    int aRow = (lane & 15);
    int aCol = (lane & 16) >> 1;
    int bNrow = (lane & 7) + ((lane & 16) >> 1);
    int bCol = (lane & 8);

    issue_stage(smB, Ah, Bh, rowBlock, colBlock, M, KA, 0, sr, sk);
    issue_stage(smB + 1u * STGH * 2, Ah, Bh, rowBlock, colBlock, M, KA, BKK, sr, sk);
    issue_stage(smB + 2u * STGH * 2, Ah, Bh, rowBlock, colBlock, M, KA, 2 * BKK, sr, sk);

    int cur = 0;
    for (int it = 0; it < kIters; it++) {
        int rem = kIters - 1 - it;
        if (rem >= 2)      asm volatile("cp.async.wait_group 2;");
        else if (rem == 1) asm volatile("cp.async.wait_group 1;");
        else               asm volatile("cp.async.wait_group 0;");
        __syncthreads();

        if (it + 3 < kIters) {
            int s3 = cur + 3; if (s3 >= NSTG) s3 -= NSTG;
            issue_stage(smB + (unsigned)s3 * STGH * 2, Ah, Bh,
                        rowBlock, colBlock, M, KA, (it + 3) * BKK, sr, sk);
        }

        unsigned aHb = smB + (unsigned)cur * STGH * 2;
        unsigned bHb = aHb + OBH * 2;

#pragma unroll
        for (int ks = 0; ks < 2; ks++) {
            int kk = ks * 16;
            unsigned bHf[8];
#pragma unroll
            for (int pair = 0; pair < 2; pair++) {
                int n = wn + pair * 16 + bNrow;
                unsigned off = (unsigned)(n * BKP + kk + bCol) * 2;
                ldm4(bHb + off, bHf[pair * 4 + 0], bHf[pair * 4 + 1],
                                bHf[pair * 4 + 2], bHf[pair * 4 + 3]);
            }
            unsigned aHf[4][4];
#pragma unroll
            for (int mt = 0; mt < 4; mt++) {
                int r = wm + mt * 16 + aRow;
                unsigned off = (unsigned)(r * BKP + kk + aCol) * 2;
                ldm4(aHb + off, aHf[mt][0], aHf[mt][1], aHf[mt][2], aHf[mt][3]);
            }
#pragma unroll
            for (int mt = 0; mt < 4; mt++)
#pragma unroll
                for (int nt = 0; nt < 4; nt++)
                    mma16816(acc[mt][nt], aHf[mt], &bHf[(nt >> 1) * 4 + (nt & 1) * 2]);
        }
        cur = (cur + 1 == NSTG) ? 0 : cur + 1;
    }

    // epilogue: route to hOut(fp16) / skipOut(fp16, +sbias)
    bool skipVec = ((splitS & 1) == 0);     // half2-safe row stride
#pragma unroll
    for (int mt = 0; mt < 4; mt++) {
        int gr0 = rowBlock + wm + mt * 16 + gID;
        int gr1 = gr0 + 8;
#pragma unroll
        for (int nt = 0; nt < 4; nt++) {
            int gc = colBlock + wn + nt * 8 + tig * 2;
#pragma unroll
            for (int half_ = 0; half_ < 2; half_++) {
                int gr = half_ ? gr1 : gr0;
                if (gr >= M) continue;
                float v0 = acc[mt][nt][half_ * 2 + 0];
                float v1 = acc[mt][nt][half_ * 2 + 1];
                if (gc < splitH) {        // pair aligned: both cols in region
                    *(__half2*)(hOut + (size_t)gr * splitH + gc) =
                        __floats2half2_rn(v0, v1);
                } else if (skipVec && gc + 1 < splitH + splitS) {
                    int sc = gc - splitH;
                    *(__half2*)(skipOut + (size_t)gr * splitS + sc) =
                        __floats2half2_rn(v0 + sbias[sc], v1 + sbias[sc + 1]);
                } else {
#pragma unroll
                    for (int j = 0; j < 2; j++) {
                        int c2 = gc + j;
                        if (c2 < splitH + splitS) {
                            int sc = c2 - splitH;
                            skipOut[(size_t)gr * splitS + sc] =
                                __float2half_rn((j ? v1 : v0) + sbias[sc]);
                        }
                    }
                }
            }
        }
    }

    // fused attention-logit partials (layers 0/1)
    if (aS != nullptr && colBlock < splitH) {
        int head = (colBlock + wn) >> 6;
        int base = (colBlock + wn) & 63;
        float cs[8], cd[8];
#pragma unroll
        for (int nt = 0; nt < 4; nt++)
#pragma unroll
            for (int j = 0; j < 2; j++) {
                int lc = base + nt * 8 + tig * 2 + j;
                cs[nt * 2 + j] = aS[head * HID + lc];
                cd[nt * 2 + j] = aD[head * HID + lc];
            }
#pragma unroll
        for (int mt = 0; mt < 4; mt++)
#pragma unroll
            for (int half_ = 0; half_ < 2; half_++) {
                int gr = rowBlock + wm + mt * 16 + gID + half_ * 8;
                float ps = 0.f, pd = 0.f;
#pragma unroll
                for (int k = 0; k < 8; k++) {
                    float v = acc[mt][k >> 1][half_ * 2 + (k & 1)];
                    ps = fmaf(v, cs[k], ps);
                    pd = fmaf(v, cd[k], pd);
                }
                ps += __shfl_xor_sync(0xffffffffu, ps, 1);
                ps += __shfl_xor_sync(0xffffffffu, ps, 2);
                pd += __shfl_xor_sync(0xffffffffu, pd, 1);
                pd += __shfl_xor_sync(0xffffffffu, pd, 2);
                if (tig == 0 && gr < M) {
                    atomicAdd(&als[gr * HEADS + head], ps);
                    atomicAdd(&ald[gr * HEADS + head], pd);
                }
            }
    }
}

// ---------------- attention logits (fp16 h) — layer 2 only ----------------
__global__ void al_kernel(const __half* __restrict__ h, const float* __restrict__ a_s,
                          const float* __restrict__ a_d, float* __restrict__ als,
                          float* __restrict__ ald, int C)
{
    int w = (blockIdx.x * blockDim.x + threadIdx.x) >> 5;
    int lane = threadIdx.x & 31;
    if (w >= NN * HEADS) return;
    int n = w >> 2, hd = w & 3;
    const __half* hp = h + (size_t)n * (HEADS * C) + hd * C;
    float ss = 0.f, sd = 0.f;
    for (int c = lane; c < C; c += 32) {
        float v = __half2float(hp[c]);
        ss = fmaf(v, a_s[hd * C + c], ss);
        sd = fmaf(v, a_d[hd * C + c], sd);
    }
#pragma unroll
    for (int o = 16; o; o >>= 1) {
        ss += __shfl_xor_sync(0xffffffffu, ss, o);
        sd += __shfl_xor_sync(0xffffffffu, sd, o);
    }
    if (lane == 0) { als[w] = ss; ald[w] = sd; }
}

__device__ __forceinline__ void haccum(float e, uint4 u, float* ac)
{
    const __half2* p = (const __half2*)&u;
#pragma unroll
    for (int j = 0; j < 4; j++) {
        float2 f = __half22float2(p[j]);
        ac[2 * j]     = fmaf(e, f.x, ac[2 * j]);
        ac[2 * j + 1] = fmaf(e, f.y, ac[2 * j + 1]);
    }
}

// ---------------- fused GAT agg + bias + skip + BN-stats (layers 0/1) --------
__global__ __launch_bounds__(256) void gat_agg_kernel(
    const int* __restrict__ rowptr, const int* __restrict__ csrc,
    const __half* __restrict__ h, const float* __restrict__ als,
    const float* __restrict__ ald, const float* __restrict__ bias,
    const __half* __restrict__ skip, __half* __restrict__ outp, float* __restrict__ sums)
{
    __shared__ float slabS[8][HC];
    __shared__ float slabQ[8][HC];
    int tid = threadIdx.x;
    int w = (blockIdx.x * 256 + tid) >> 5;
    int lane = tid & 31;
    int wid = tid >> 5;
    int head = lane >> 3;
    float ad = ald[w * 4 + head];
    int beg = rowptr[w], end = rowptr[w + 1];
    float ac[8];
#pragma unroll
    for (int j = 0; j < 8; j++) ac[j] = 0.f;
    float den = 0.f;
    int i = beg;
    for (; i + 4 <= end; i += 4) {
        int s0 = csrc[i], s1 = csrc[i + 1], s2 = csrc[i + 2], s3 = csrc[i + 3];
        float A0 = als[s0 * 4 + head], A1 = als[s1 * 4 + head];
        float A2 = als[s2 * 4 + head], A3 = als[s3 * 4 + head];
        uint4 u0 = ((const uint4*)(h + (size_t)s0 * HC))[lane];
        uint4 u1 = ((const uint4*)(h + (size_t)s1 * HC))[lane];
        uint4 u2 = ((const uint4*)(h + (size_t)s2 * HC))[lane];
        uint4 u3 = ((const uint4*)(h + (size_t)s3 * HC))[lane];
        float e0 = expf(lrelu(A0 + ad));
        float e1 = expf(lrelu(A1 + ad));
        float e2 = expf(lrelu(A2 + ad));
        float e3 = expf(lrelu(A3 + ad));
        den += (e0 + e1) + (e2 + e3);
        haccum(e0, u0, ac);
        haccum(e1, u1, ac);
        haccum(e2, u2, ac);
        haccum(e3, u3, ac);
    }
    for (; i < end; i++) {
        int s = csrc[i];
        float e = expf(lrelu(als[s * 4 + head] + ad));
        den += e;
        uint4 u = ((const uint4*)(h + (size_t)s * HC))[lane];
        haccum(e, u, ac);
    }
    float inv = 1.f / (den + 1e-16f);
    int cbase = lane * 8;
    size_t obase = (size_t)w * HC + cbase;
    const float4* bp = (const float4*)(bias + cbase);
    float4 b0 = bp[0], b1 = bp[1];
    uint4 su = *(const uint4*)(skip + obase);
    float sf[8];
    {
        const __half2* p = (const __half2*)&su;
#pragma unroll
        for (int j = 0; j < 4; j++) {
            float2 f = __half22float2(p[j]);
            sf[2 * j] = f.x; sf[2 * j + 1] = f.y;
        }
    }
    float o[8];
    o[0] = fmaf(ac[0], inv, b0.x + sf[0]); o[1] = fmaf(ac[1], inv, b0.y + sf[1]);
    o[2] = fmaf(ac[2], inv, b0.z + sf[2]); o[3] = fmaf(ac[3], inv, b0.w + sf[3]);
    o[4] = fmaf(ac[4], inv, b1.x + sf[4]); o[5] = fmaf(ac[5], inv, b1.y + sf[5]);
    o[6] = fmaf(ac[6], inv, b1.z + sf[6]); o[7] = fmaf(ac[7], inv, b1.w + sf[7]);
    uint4 st;
    __half2* stp = (__half2*)&st;
#pragma unroll
    for (int j = 0; j < 4; j++) stp[j] = __floats2half2_rn(o[2 * j], o[2 * j + 1]);
    *(uint4*)(outp + obase) = st;

#pragma unroll
    for (int j = 0; j < 8; j++) {
        slabS[wid][cbase + j] = o[j];
        slabQ[wid][cbase + j] = o[j] * o[j];
    }
    __syncthreads();
    float s = 0.f, q = 0.f;
#pragma unroll
    for (int ww = 0; ww < 8; ww++) { s += slabS[ww][tid]; q += slabQ[ww][tid]; }
    atomicAdd(&sums[tid], s);
    atomicAdd(&sums[HC + tid], q);
}

// ---------------- layer 2: agg + mean heads + bias + skip + log_softmax ------
__global__ __launch_bounds__(256) void gat_agg47_fused(
    const int* __restrict__ rowptr, const int* __restrict__ csrc,
    const __half* __restrict__ h, const float4* __restrict__ als,
    const float4* __restrict__ ald, const float* __restrict__ b2,
    const __half* __restrict__ skip47, float* __restrict__ outp)
{
    int w = (blockIdx.x * blockDim.x + threadIdx.x) >> 5;
    int lane = threadIdx.x & 31;
    if (w >= NN) return;
    float4 ad = ald[w];
    int beg = rowptr[w], end = rowptr[w + 1];
    float a0 = 0.f, a1 = 0.f, a2 = 0.f, a3 = 0.f;
    float c0 = 0.f, c1 = 0.f, c2 = 0.f, c3 = 0.f;
    float d0 = 0.f, d1 = 0.f, d2 = 0.f, d3 = 0.f;
    bool has2 = (lane + 32) < NCLS;
    for (int i = beg; i < end; i++) {
        int s = csrc[i];
        float4 as4 = als[s];
        float e0 = expf(lrelu(as4.x + ad.x));
        float e1 = expf(lrelu(as4.y + ad.y));
        float e2 = expf(lrelu(as4.z + ad.z));
        float e3 = expf(lrelu(as4.w + ad.w));
        d0 += e0; d1 += e1; d2 += e2; d3 += e3;
        const __half* hs = h + (size_t)s * L2OUT;
        a0 = fmaf(e0, __half2float(hs[lane]), a0);
        a1 = fmaf(e1, __half2float(hs[NCLS + lane]), a1);
        a2 = fmaf(e2, __half2float(hs[2 * NCLS + lane]), a2);
        a3 = fmaf(e3, __half2float(hs[3 * NCLS + lane]), a3);
        if (has2) {
            int c = lane + 32;
            c0 = fmaf(e0, __half2float(hs[c]), c0);
            c1 = fmaf(e1, __half2float(hs[NCLS + c]), c1);
            c2 = fmaf(e2, __half2float(hs[2 * NCLS + c]), c2);
            c3 = fmaf(e3, __half2float(hs[3 * NCLS + c]), c3);
        }
    }
    float i0 = 1.f / (d0 + 1e-16f), i1 = 1.f / (d1 + 1e-16f);
    float i2 = 1.f / (d2 + 1e-16f), i3 = 1.f / (d3 + 1e-16f);
    float v0 = 0.25f * (a0 * i0 + a1 * i1 + a2 * i2 + a3 * i3)
             + b2[lane] + __half2float(skip47[(size_t)w * NCLS + lane]);
    float v1 = -1e30f;
    if (has2) {
        int c = lane + 32;
        v1 = 0.25f * (c0 * i0 + c1 * i1 + c2 * i2 + c3 * i3)
           + b2[c] + __half2float(skip47[(size_t)w * NCLS + c]);
    }
    float m = fmaxf(v0, v1);
#pragma unroll
    for (int o = 16; o; o >>= 1) m = fmaxf(m, __shfl_xor_sync(0xffffffffu, m, o));
    float s = expf(v0 - m) + (has2 ? expf(v1 - m) : 0.f);
#pragma unroll
    for (int o = 16; o; o >>= 1) s += __shfl_xor_sync(0xffffffffu, s, o);
    float lse = m + logf(s);
    outp[(size_t)w * NCLS + lane] = v0 - lse;
    if (has2) outp[(size_t)w * NCLS + lane + 32] = v1 - lse;
}

// ---------------- BN apply + ELU -> fp16 (also clears als/ald for next layer) -
__global__ void bn_apply_kernel(const __half* __restrict__ pre, const float* __restrict__ sums,
                                const float* __restrict__ gamma, const float* __restrict__ beta,
                                __half* __restrict__ oh,
                                float* __restrict__ als, float* __restrict__ ald)
{
    int c = threadIdx.x;
    int t = blockIdx.x * 256 + c;             // grid 512 -> 131072 >= NN*HEADS
    if (t < NN * HEADS) { als[t] = 0.f; ald[t] = 0.f; }
    float mu = sums[c] * (1.f / NN);
    float var = sums[HC + c] * (1.f / NN) - mu * mu;
    float rstd = rsqrtf(var + 1e-5f);
    float g = gamma[c] * rstd;
    float b = beta[c] - mu * g;
    for (int r = blockIdx.x; r < NN; r += gridDim.x) {
        size_t idx = (size_t)r * HC + c;
        float v = fmaf(__half2float(pre[idx]), g, b);
        float o = v > 0.f ? v : expf(v) - 1.f;
        oh[idx] = __float2half_rn(o);
    }
}

// ---------------- host orchestration ----------------
extern "C" void kernel_launch(void* const* d_in, const int* in_sizes, int n_in,
                              void* d_out, int out_size)
{
    const float* x   = (const float*)d_in[0];
    const int*   ei  = (const int*)d_in[1];
    const float* w0  = (const float*)d_in[2];
    const float* as0 = (const float*)d_in[3];
    const float* ad0 = (const float*)d_in[4];
    const float* b0  = (const float*)d_in[5];
    const float* sw0 = (const float*)d_in[6];
    const float* sb0 = (const float*)d_in[7];
    const float* g0  = (const float*)d_in[8];
    const float* be0 = (const float*)d_in[9];
    const float* w1  = (const float*)d_in[10];
    const float* as1 = (const float*)d_in[11];
    const float* ad1 = (const float*)d_in[12];
    const float* b1  = (const float*)d_in[13];
    const float* sw1 = (const float*)d_in[14];
    const float* sb1 = (const float*)d_in[15];
    const float* g1  = (const float*)d_in[16];
    const float* be1 = (const float*)d_in[17];
    const float* w2  = (const float*)d_in[18];
    const float* as2 = (const float*)d_in[19];
    const float* ad2 = (const float*)d_in[20];
    const float* b2  = (const float*)d_in[21];
    const float* sw2 = (const float*)d_in[22];
    const float* sb2 = (const float*)d_in[23];

    const int* src = ei;
    const int* dst = ei + EE;

    float *als, *ald, *bns0, *bns1;
    __half *h, *skip, *agg, *xh, *ah, *b0h, *b1h, *b2h;
    int *cnt, *part, *bsum, *rowptr, *cursor, *csrc;
    cudaGetSymbolAddress((void**)&h, g_h);
    cudaGetSymbolAddress((void**)&skip, g_skip);
    cudaGetSymbolAddress((void**)&agg, g_agg);
    cudaGetSymbolAddress((void**)&als, g_als);
    cudaGetSymbolAddress((void**)&ald, g_ald);
    cudaGetSymbolAddress((void**)&bns0, g_bnsum0);
    cudaGetSymbolAddress((void**)&bns1, g_bnsum1);
    cudaGetSymbolAddress((void**)&xh, g_xh);
    cudaGetSymbolAddress((void**)&ah, g_ah);
    cudaGetSymbolAddress((void**)&b0h, g_b0h);
    cudaGetSymbolAddress((void**)&b1h, g_b1h);
    cudaGetSymbolAddress((void**)&b2h, g_b2h);
    cudaGetSymbolAddress((void**)&cnt, g_cnt);
    cudaGetSymbolAddress((void**)&part, g_part);
    cudaGetSymbolAddress((void**)&bsum, g_bsum);
    cudaGetSymbolAddress((void**)&rowptr, g_rowptr);
    cudaGetSymbolAddress((void**)&cursor, g_cursor);
    cudaGetSymbolAddress((void**)&csrc, g_csrc);

    cudaFuncSetAttribute(hgemm_f16, cudaFuncAttributeMaxDynamicSharedMemorySize, SMEM_GEMM);

    // one-time side stream + events (created on the pre-capture correctness call;
    // the captured work is identical on every call)
    static cudaStream_t s2 = nullptr;
    static cudaEvent_t evF = nullptr, evJ = nullptr;
    if (s2 == nullptr) {
        cudaStreamCreateWithFlags(&s2, cudaStreamNonBlocking);
        cudaEventCreateWithFlags(&evF, cudaEventDisableTiming);
        cudaEventCreateWithFlags(&evJ, cudaEventDisableTiming);
    }

    dim3 gemm512(4, (NN + BM - 1) / BM);
    dim3 gemm256(2, (NN + BM - 1) / BM);
    int alBlocks = (NN * HEADS * 32 + 255) / 256;
    int nodeWarpBlocks = (NN * 32) / 256;
    int eBlocks = (EE + 255) / 256;

    prep_kernel<<<(NN * K0P + 255) / 256, 256>>>(x, xh, w0, sw0, w1, sw1, w2, sw2,
                                                 b0h, b1h, b2h, cnt, als, ald,
                                                 bns0, bns1);
    // fork: CSR build overlaps layer-0 GEMM
    cudaEventRecord(evF, 0);
    cudaStreamWaitEvent(s2, evF, 0);
    count_kernel<<<eBlocks, 256, 0, s2>>>(dst, cnt);
    scan_blocks<<<NBLK, 256, 0, s2>>>(cnt, part, bsum);
    scan_add<<<(NN + 256) / 256, 256, 0, s2>>>(part, bsum, rowptr, cursor);
    fill_kernel<<<eBlocks, 256, 0, s2>>>(src, dst, cursor, csrc);
    cudaEventRecord(evJ, s2);

    hgemm_f16<<<gemm512, 256, SMEM_GEMM>>>(xh, b0h, sb0, h, skip,
                                           as0, ad0, als, ald,
                                           NN, K0P, 512, HC, HC);
    cudaStreamWaitEvent(0, evJ, 0);   // join before aggregation

    // ===== Layer 0 (agg + BN) =====
    gat_agg_kernel<<<nodeWarpBlocks, 256>>>(rowptr, csrc, h, als, ald, b0, skip, agg, bns0);
    bn_apply_kernel<<<512, 256>>>(agg, bns0, g0, be0, ah, als, ald);  // clears als/ald

    // ===== Layer 1 =====
    hgemm_f16<<<gemm512, 256, SMEM_GEMM>>>(ah, b1h, sb1, h, skip,
                                           as1, ad1, als, ald, NN, HC, 512, HC, HC);
    gat_agg_kernel<<<nodeWarpBlocks, 256>>>(rowptr, csrc, h, als, ald, b1, skip, agg, bns1);
    bn_apply_kernel<<<512, 256>>>(agg, bns1, g1, be1, ah, als, ald);

    // ===== Layer 2 =====
    hgemm_f16<<<gemm256, 256, SMEM_GEMM>>>(ah, b2h, sb2, h, skip,
                                           nullptr, nullptr, als, ald,
                                           NN, HC, NP2, L2OUT, NCLS);
    al_kernel<<<alBlocks, 256>>>(h, as2, ad2, als, ald, NCLS);
    gat_agg47_fused<<<nodeWarpBlocks, 256>>>(rowptr, csrc, h, (const float4*)als,
                                             (const float4*)ald, b2, skip, (float*)d_out);
}

// round 15
// speedup vs baseline: 1.6381x; 1.0455x over previous
#include <cuda_runtime.h>
#include <cuda_bf16.h>
#include <cuda_fp16.h>
#include <cstdint>
#include <math.h>

#define NN 30000
#define EE 480000
#define F_IN 100
#define HID 64
#define HEADS 4
#define NCLS 47
#define HC 256           // HEADS*HID
#define L2OUT 188        // HEADS*NCLS
#define NP2 256          // padded pack width layer2 (188 + 47 -> 256)
#define K0P 128          // padded K for layer 0 (100 -> 128)
#define NBLK 118         // ceil(NN/256)

// ---------------- scratch ----------------
__device__ __align__(16) __half g_h[(size_t)NN * HC];    // GAT-branch GEMM out (fp16)
__device__ __align__(16) __half g_skip[(size_t)NN * HC]; // skip branch (fp16)
__device__ __align__(16) __half g_agg[(size_t)NN * HC];  // pre-BN (fp16; stats exact fp32)
__device__ __align__(16) float g_als[(size_t)NN * HEADS];
__device__ __align__(16) float g_ald[(size_t)NN * HEADS];
__device__ float g_bnsum0[2 * HC];
__device__ float g_bnsum1[2 * HC];
// fp16 activations (A-side)
__device__ __align__(16) __half g_xh[(size_t)NN * K0P];
__device__ __align__(16) __half g_ah[(size_t)NN * HC];
// fp16 transposed weights [n][k]
__device__ __align__(16) __half g_b0h[512 * K0P];
__device__ __align__(16) __half g_b1h[512 * HC];
__device__ __align__(16) __half g_b2h[NP2 * HC];
// CSR
__device__ int g_cnt[NN];
__device__ int g_part[NN];
__device__ int g_bsum[NBLK];
__device__ int g_rowptr[NN + 1];
__device__ int g_cursor[NN];
__device__ int g_csrc[EE];

__device__ __forceinline__ float lrelu(float x) { return x > 0.f ? x : 0.2f * x; }

// ---------------- prep: convert x, pack weights, zero cnt/als/ald/bnsum ------
__global__ void prep_kernel(const float* __restrict__ x, __half* __restrict__ xh,
                            const float* __restrict__ w0, const float* __restrict__ sw0,
                            const float* __restrict__ w1, const float* __restrict__ sw1,
                            const float* __restrict__ w2, const float* __restrict__ sw2,
                            __half* __restrict__ b0h, __half* __restrict__ b1h,
                            __half* __restrict__ b2h,
                            int* __restrict__ cnt, float* __restrict__ als,
                            float* __restrict__ ald, float* __restrict__ bns0,
                            float* __restrict__ bns1)
{
    int idx = blockIdx.x * 256 + threadIdx.x;   // grid covers NN*K0P = 3.84M
    if (idx < NN * K0P) {
        int n = idx >> 7, c = idx & (K0P - 1);
        float v = (c < F_IN) ? x[n * F_IN + c] : 0.f;
        xh[idx] = __float2half_rn(v);
    }
    if (idx < 512 * K0P) {
        int n = idx >> 7, k = idx & (K0P - 1);
        float v = 0.f;
        if (k < F_IN) v = (n < HC) ? w0[k * HC + n] : sw0[k * HC + (n - HC)];
        b0h[idx] = __float2half_rn(v);
    }
    if (idx < 512 * HC) {
        int n = idx >> 8, k = idx & (HC - 1);
        float v = (n < HC) ? w1[k * HC + n] : sw1[k * HC + (n - HC)];
        b1h[idx] = __float2half_rn(v);
    }
    if (idx < NP2 * HC) {
        int n = idx >> 8, k = idx & (HC - 1);
        float v = 0.f;
        if (n < L2OUT) v = w2[k * L2OUT + n];
        else if (n < L2OUT + NCLS) v = sw2[k * NCLS + (n - L2OUT)];
        b2h[idx] = __float2half_rn(v);
    }
    if (idx < NN) cnt[idx] = 0;
    if (idx < NN * HEADS) { als[idx] = 0.f; ald[idx] = 0.f; }
    if (idx < 2 * HC) { bns0[idx] = 0.f; bns1[idx] = 0.f; }
}

// ---------------- CSR build ----------------
__global__ void count_kernel(const int* __restrict__ dst, int* __restrict__ cnt)
{
    int e = blockIdx.x * blockDim.x + threadIdx.x;
    if (e < EE) atomicAdd(&cnt[dst[e]], 1);
}

__global__ void scan_blocks(const int* __restrict__ cnt, int* __restrict__ part,
                            int* __restrict__ bsum)
{
    int t = threadIdx.x;
    int i = blockIdx.x * 256 + t;
    int lane = t & 31, wid = t >> 5;
    int v = (i < NN) ? cnt[i] : 0;
    int x = v;
#pragma unroll
    for (int off = 1; off < 32; off <<= 1) {
        int y = __shfl_up_sync(0xffffffffu, x, off);
        if (lane >= off) x += y;
    }
    __shared__ int wsum[8];
    if (lane == 31) wsum[wid] = x;
    __syncthreads();
    if (wid == 0 && lane < 8) {
        int w = wsum[lane];
#pragma unroll
        for (int off = 1; off < 8; off <<= 1) {
            int y = __shfl_up_sync(0xffu, w, off);
            if (lane >= off) w += y;
        }
        wsum[lane] = w;
    }
    __syncthreads();
    int base = (wid > 0) ? wsum[wid - 1] : 0;
    int incl = x + base;
    if (i < NN) part[i] = incl - v;
    if (t == 255) bsum[blockIdx.x] = incl;   // raw per-block total
}

__global__ void scan_add(const int* __restrict__ part, const int* __restrict__ bsum,
                         int* __restrict__ rowptr, int* __restrict__ cursor)
{
    __shared__ int red[256];
    int b = blockIdx.x;
    int t = threadIdx.x;
    int acc = 0;
    for (int j = t; j < b; j += 256) acc += bsum[j];
    red[t] = acc;
    __syncthreads();
#pragma unroll
    for (int s = 128; s > 0; s >>= 1) {
        if (t < s) red[t] += red[t + s];
        __syncthreads();
    }
    int off = red[0];
    int i = b * 256 + t;
    if (i < NN) {
        int r = part[i] + off;
        rowptr[i] = r;
        cursor[i] = r;
    }
    if (i == NN) rowptr[NN] = EE;
}

__global__ void fill_kernel(const int* __restrict__ src, const int* __restrict__ dst,
                            int* __restrict__ cursor, int* __restrict__ csrc)
{
    int e = blockIdx.x * blockDim.x + threadIdx.x;
    if (e >= EE) return;
    int d = dst[e];
    int pos = atomicAdd(&cursor[d], 1);
    csrc[pos] = src[e];
}

// ---------------- pure fp16 tensor-core GEMM, 4-stage pipeline ------
#define BM 128
#define BN 128
#define BKK 32
#define BKP 40          // padded K stride in halves (80B rows, conflict-free ldmatrix)
#define OBH 5120
#define STGH 10240      // halves per stage
#define NSTG 4
#define SMEM_GEMM (NSTG * STGH * 2)   // 81920 bytes

__device__ __forceinline__ void mma16816(float* d, const unsigned* a, const unsigned* b)
{
    asm volatile(
        "mma.sync.aligned.m16n8k16.row.col.f32.f16.f16.f32 "
        "{%0,%1,%2,%3}, {%4,%5,%6,%7}, {%8,%9}, {%0,%1,%2,%3};"
        : "+f"(d[0]), "+f"(d[1]), "+f"(d[2]), "+f"(d[3])
        : "r"(a[0]), "r"(a[1]), "r"(a[2]), "r"(a[3]), "r"(b[0]), "r"(b[1]));
}

__device__ __forceinline__ void cp16(unsigned dst, const void* src, int sz)
{
    asm volatile("cp.async.cg.shared.global [%0], [%1], 16, %2;"
                 :: "r"(dst), "l"(src), "r"(sz));
}

__device__ __forceinline__ void ldm4(unsigned addr, unsigned& r0, unsigned& r1,
                                     unsigned& r2, unsigned& r3)
{
    asm volatile("ldmatrix.sync.aligned.m8n8.x4.shared.b16 {%0,%1,%2,%3}, [%4];"
                 : "=r"(r0), "=r"(r1), "=r"(r2), "=r"(r3) : "r"(addr));
}

__device__ __forceinline__ void issue_stage(
    unsigned sb, const __half* Ah, const __half* Bh,
    int rowBlock, int colBlock, int M, int KA, int k0, int sr, int sk)
{
#pragma unroll
    for (int i = 0; i < 2; i++) {
        int row = sr + i * 64;
        int gr = rowBlock + row;
        int sz = (gr < M) ? 16 : 0;
        size_t off = (size_t)(sz ? gr : 0) * KA + k0 + sk;
        cp16(sb + (unsigned)(row * BKP + sk) * 2, Ah + off, sz);
        int gc = colBlock + row;                    // Npack padded: always valid
        size_t boff = (size_t)gc * KA + k0 + sk;
        cp16(sb + (unsigned)(OBH + row * BKP + sk) * 2, Bh + boff, 16);
    }
    asm volatile("cp.async.commit_group;");
}

// headW: 64 for layers 0/1 (HID), 47 for layer 2 (NCLS); aS/aD stride = headW
__global__ __launch_bounds__(256, 2) void hgemm_f16(
    const __half* __restrict__ Ah, const __half* __restrict__ Bh,
    const float* __restrict__ sbias, __half* __restrict__ hOut, __half* __restrict__ skipOut,
    const float* __restrict__ aS, const float* __restrict__ aD,
    float* __restrict__ als, float* __restrict__ ald,
    int M, int KA, int Npack, int splitH, int splitS, int headW)
{
    extern __shared__ __half sm[];
    unsigned smB = (unsigned)__cvta_generic_to_shared(sm);

    int tid = threadIdx.x;
    int lane = tid & 31, wid = tid >> 5;
    int rowBlock = blockIdx.y * BM;
    int colBlock = blockIdx.x * BN;
    int wm = (wid & 1) * 64;
    int wn = (wid >> 1) * 32;
    int gID = lane >> 2, tig = lane & 3;

    float acc[4][4][4];
#pragma unroll
    for (int mt = 0; mt < 4; mt++)
#pragma unroll
        for (int nt = 0; nt < 4; nt++)
#pragma unroll
            for (int r = 0; r < 4; r++) acc[mt][nt][r] = 0.f;

    int kIters = KA >> 5;
    int sr = tid >> 2;
    int sk = (tid & 3) * 8;

    int aRow = (lane & 15);
    int aCol = (lane & 16) >> 1;
    int bNrow = (lane & 7) + ((lane & 16) >> 1);
    int bCol = (lane & 8);

    issue_stage(smB, Ah, Bh, rowBlock, colBlock, M, KA, 0, sr, sk);
    issue_stage(smB + 1u * STGH * 2, Ah, Bh, rowBlock, colBlock, M, KA, BKK, sr, sk);
    issue_stage(smB + 2u * STGH * 2, Ah, Bh, rowBlock, colBlock, M, KA, 2 * BKK, sr, sk);

    int cur = 0;
    for (int it = 0; it < kIters; it++) {
        int rem = kIters - 1 - it;
        if (rem >= 2)      asm volatile("cp.async.wait_group 2;");
        else if (rem == 1) asm volatile("cp.async.wait_group 1;");
        else               asm volatile("cp.async.wait_group 0;");
        __syncthreads();

        if (it + 3 < kIters) {
            int s3 = cur + 3; if (s3 >= NSTG) s3 -= NSTG;
            issue_stage(smB + (unsigned)s3 * STGH * 2, Ah, Bh,
                        rowBlock, colBlock, M, KA, (it + 3) * BKK, sr, sk);
        }

        unsigned aHb = smB + (unsigned)cur * STGH * 2;
        unsigned bHb = aHb + OBH * 2;

#pragma unroll
        for (int ks = 0; ks < 2; ks++) {
            int kk = ks * 16;
            unsigned bHf[8];
#pragma unroll
            for (int pair = 0; pair < 2; pair++) {
                int n = wn + pair * 16 + bNrow;
                unsigned off = (unsigned)(n * BKP + kk + bCol) * 2;
                ldm4(bHb + off, bHf[pair * 4 + 0], bHf[pair * 4 + 1],
                                bHf[pair * 4 + 2], bHf[pair * 4 + 3]);
            }
            unsigned aHf[4][4];
#pragma unroll
            for (int mt = 0; mt < 4; mt++) {
                int r = wm + mt * 16 + aRow;
                unsigned off = (unsigned)(r * BKP + kk + aCol) * 2;
                ldm4(aHb + off, aHf[mt][0], aHf[mt][1], aHf[mt][2], aHf[mt][3]);
            }
#pragma unroll
            for (int mt = 0; mt < 4; mt++)
#pragma unroll
                for (int nt = 0; nt < 4; nt++)
                    mma16816(acc[mt][nt], aHf[mt], &bHf[(nt >> 1) * 4 + (nt & 1) * 2]);
        }
        cur = (cur + 1 == NSTG) ? 0 : cur + 1;
    }

    // epilogue: route to hOut(fp16) / skipOut(fp16, +sbias)
    bool skipVec = ((splitS & 1) == 0);
#pragma unroll
    for (int mt = 0; mt < 4; mt++) {
        int gr0 = rowBlock + wm + mt * 16 + gID;
        int gr1 = gr0 + 8;
#pragma unroll
        for (int nt = 0; nt < 4; nt++) {
            int gc = colBlock + wn + nt * 8 + tig * 2;
#pragma unroll
            for (int half_ = 0; half_ < 2; half_++) {
                int gr = half_ ? gr1 : gr0;
                if (gr >= M) continue;
                float v0 = acc[mt][nt][half_ * 2 + 0];
                float v1 = acc[mt][nt][half_ * 2 + 1];
                if (gc < splitH) {
                    *(__half2*)(hOut + (size_t)gr * splitH + gc) =
                        __floats2half2_rn(v0, v1);
                } else if (skipVec && gc + 1 < splitH + splitS) {
                    int sc = gc - splitH;
                    *(__half2*)(skipOut + (size_t)gr * splitS + sc) =
                        __floats2half2_rn(v0 + sbias[sc], v1 + sbias[sc + 1]);
                } else {
#pragma unroll
                    for (int j = 0; j < 2; j++) {
                        int c2 = gc + j;
                        if (c2 < splitH + splitS) {
                            int sc = c2 - splitH;
                            skipOut[(size_t)gr * splitS + sc] =
                                __float2half_rn((j ? v1 : v0) + sbias[sc]);
                        }
                    }
                }
            }
        }
    }

    // fused attention-logit partials. A warp's 32-col window spans at most
    // two heads (headW >= 32); hA/hB are quad-uniform.
    int base = colBlock + wn;
    if (aS != nullptr && base < splitH) {
        int hA = base / headW;
        int lastC = base + 31; if (lastC > splitH - 1) lastC = splitH - 1;
        int hB = lastC / headW;
        float cs[8], cd[8];
        int hd[8];
#pragma unroll
        for (int nt = 0; nt < 4; nt++)
#pragma unroll
            for (int j = 0; j < 2; j++) {
                int c = base + nt * 8 + tig * 2 + j;
                int k = nt * 2 + j;
                if (c < splitH) {
                    int hh = c / headW;
                    int lc = c - hh * headW;
                    cs[k] = aS[hh * headW + lc];
                    cd[k] = aD[hh * headW + lc];
                    hd[k] = hh;
                } else { cs[k] = 0.f; cd[k] = 0.f; hd[k] = hA; }
            }
#pragma unroll
        for (int mt = 0; mt < 4; mt++)
#pragma unroll
            for (int half_ = 0; half_ < 2; half_++) {
                int gr = rowBlock + wm + mt * 16 + gID + half_ * 8;
                float psA = 0.f, pdA = 0.f, psB = 0.f, pdB = 0.f;
#pragma unroll
                for (int k = 0; k < 8; k++) {
                    float v = acc[mt][k >> 1][half_ * 2 + (k & 1)];
                    float ts = v * cs[k];
                    float td = v * cd[k];
                    if (hd[k] == hA) { psA += ts; pdA += td; }
                    else             { psB += ts; pdB += td; }
                }
                psA += __shfl_xor_sync(0xffffffffu, psA, 1);
                psA += __shfl_xor_sync(0xffffffffu, psA, 2);
                pdA += __shfl_xor_sync(0xffffffffu, pdA, 1);
                pdA += __shfl_xor_sync(0xffffffffu, pdA, 2);
                if (hB != hA) {
                    psB += __shfl_xor_sync(0xffffffffu, psB, 1);
                    psB += __shfl_xor_sync(0xffffffffu, psB, 2);
                    pdB += __shfl_xor_sync(0xffffffffu, pdB, 1);
                    pdB += __shfl_xor_sync(0xffffffffu, pdB, 2);
                }
                if (tig == 0 && gr < M) {
                    atomicAdd(&als[gr * HEADS + hA], psA);
                    atomicAdd(&ald[gr * HEADS + hA], pdA);
                    if (hB != hA) {
                        atomicAdd(&als[gr * HEADS + hB], psB);
                        atomicAdd(&ald[gr * HEADS + hB], pdB);
                    }
                }
            }
    }
}

__device__ __forceinline__ void haccum(float e, uint4 u, float* ac)
{
    const __half2* p = (const __half2*)&u;
#pragma unroll
    for (int j = 0; j < 4; j++) {
        float2 f = __half22float2(p[j]);
        ac[2 * j]     = fmaf(e, f.x, ac[2 * j]);
        ac[2 * j + 1] = fmaf(e, f.y, ac[2 * j + 1]);
    }
}

// ---------------- fused GAT agg + bias + skip + BN-stats (layers 0/1) --------
__global__ __launch_bounds__(256) void gat_agg_kernel(
    const int* __restrict__ rowptr, const int* __restrict__ csrc,
    const __half* __restrict__ h, const float* __restrict__ als,
    const float* __restrict__ ald, const float* __restrict__ bias,
    const __half* __restrict__ skip, __half* __restrict__ outp, float* __restrict__ sums)
{
    __shared__ float slabS[8][HC];
    __shared__ float slabQ[8][HC];
    int tid = threadIdx.x;
    int w = (blockIdx.x * 256 + tid) >> 5;
    int lane = tid & 31;
    int wid = tid >> 5;
    int head = lane >> 3;
    float ad = ald[w * 4 + head];
    int beg = rowptr[w], end = rowptr[w + 1];
    float ac[8];
#pragma unroll
    for (int j = 0; j < 8; j++) ac[j] = 0.f;
    float den = 0.f;
    int i = beg;
    for (; i + 4 <= end; i += 4) {
        int s0 = csrc[i], s1 = csrc[i + 1], s2 = csrc[i + 2], s3 = csrc[i + 3];
        float A0 = als[s0 * 4 + head], A1 = als[s1 * 4 + head];
        float A2 = als[s2 * 4 + head], A3 = als[s3 * 4 + head];
        uint4 u0 = ((const uint4*)(h + (size_t)s0 * HC))[lane];
        uint4 u1 = ((const uint4*)(h + (size_t)s1 * HC))[lane];
        uint4 u2 = ((const uint4*)(h + (size_t)s2 * HC))[lane];
        uint4 u3 = ((const uint4*)(h + (size_t)s3 * HC))[lane];
        float e0 = expf(lrelu(A0 + ad));
        float e1 = expf(lrelu(A1 + ad));
        float e2 = expf(lrelu(A2 + ad));
        float e3 = expf(lrelu(A3 + ad));
        den += (e0 + e1) + (e2 + e3);
        haccum(e0, u0, ac);
        haccum(e1, u1, ac);
        haccum(e2, u2, ac);
        haccum(e3, u3, ac);
    }
    for (; i < end; i++) {
        int s = csrc[i];
        float e = expf(lrelu(als[s * 4 + head] + ad));
        den += e;
        uint4 u = ((const uint4*)(h + (size_t)s * HC))[lane];
        haccum(e, u, ac);
    }
    float inv = 1.f / (den + 1e-16f);
    int cbase = lane * 8;
    size_t obase = (size_t)w * HC + cbase;
    const float4* bp = (const float4*)(bias + cbase);
    float4 b0 = bp[0], b1 = bp[1];
    uint4 su = *(const uint4*)(skip + obase);
    float sf[8];
    {
        const __half2* p = (const __half2*)&su;
#pragma unroll
        for (int j = 0; j < 4; j++) {
            float2 f = __half22float2(p[j]);
            sf[2 * j] = f.x; sf[2 * j + 1] = f.y;
        }
    }
    float o[8];
    o[0] = fmaf(ac[0], inv, b0.x + sf[0]); o[1] = fmaf(ac[1], inv, b0.y + sf[1]);
    o[2] = fmaf(ac[2], inv, b0.z + sf[2]); o[3] = fmaf(ac[3], inv, b0.w + sf[3]);
    o[4] = fmaf(ac[4], inv, b1.x + sf[4]); o[5] = fmaf(ac[5], inv, b1.y + sf[5]);
    o[6] = fmaf(ac[6], inv, b1.z + sf[6]); o[7] = fmaf(ac[7], inv, b1.w + sf[7]);
    uint4 st;
    __half2* stp = (__half2*)&st;
#pragma unroll
    for (int j = 0; j < 4; j++) stp[j] = __floats2half2_rn(o[2 * j], o[2 * j + 1]);
    *(uint4*)(outp + obase) = st;

#pragma unroll
    for (int j = 0; j < 8; j++) {
        slabS[wid][cbase + j] = o[j];
        slabQ[wid][cbase + j] = o[j] * o[j];
    }
    __syncthreads();
    float s = 0.f, q = 0.f;
#pragma unroll
    for (int ww = 0; ww < 8; ww++) { s += slabS[ww][tid]; q += slabQ[ww][tid]; }
    atomicAdd(&sums[tid], s);
    atomicAdd(&sums[HC + tid], q);
}

// ---------------- layer 2: agg + mean heads + bias + skip + log_softmax ------
__global__ __launch_bounds__(256) void gat_agg47_fused(
    const int* __restrict__ rowptr, const int* __restrict__ csrc,
    const __half* __restrict__ h, const float4* __restrict__ als,
    const float4* __restrict__ ald, const float* __restrict__ b2,
    const __half* __restrict__ skip47, float* __restrict__ outp)
{
    int w = (blockIdx.x * blockDim.x + threadIdx.x) >> 5;
    int lane = threadIdx.x & 31;
    if (w >= NN) return;
    float4 ad = ald[w];
    int beg = rowptr[w], end = rowptr[w + 1];
    float a0 = 0.f, a1 = 0.f, a2 = 0.f, a3 = 0.f;
    float c0 = 0.f, c1 = 0.f, c2 = 0.f, c3 = 0.f;
    float d0 = 0.f, d1 = 0.f, d2 = 0.f, d3 = 0.f;
    bool has2 = (lane + 32) < NCLS;
    for (int i = beg; i < end; i++) {
        int s = csrc[i];
        float4 as4 = als[s];
        float e0 = expf(lrelu(as4.x + ad.x));
        float e1 = expf(lrelu(as4.y + ad.y));
        float e2 = expf(lrelu(as4.z + ad.z));
        float e3 = expf(lrelu(as4.w + ad.w));
        d0 += e0; d1 += e1; d2 += e2; d3 += e3;
        const __half* hs = h + (size_t)s * L2OUT;
        a0 = fmaf(e0, __half2float(hs[lane]), a0);
        a1 = fmaf(e1, __half2float(hs[NCLS + lane]), a1);
        a2 = fmaf(e2, __half2float(hs[2 * NCLS + lane]), a2);
        a3 = fmaf(e3, __half2float(hs[3 * NCLS + lane]), a3);
        if (has2) {
            int c = lane + 32;
            c0 = fmaf(e0, __half2float(hs[c]), c0);
            c1 = fmaf(e1, __half2float(hs[NCLS + c]), c1);
            c2 = fmaf(e2, __half2float(hs[2 * NCLS + c]), c2);
            c3 = fmaf(e3, __half2float(hs[3 * NCLS + c]), c3);
        }
    }
    float i0 = 1.f / (d0 + 1e-16f), i1 = 1.f / (d1 + 1e-16f);
    float i2 = 1.f / (d2 + 1e-16f), i3 = 1.f / (d3 + 1e-16f);
    float v0 = 0.25f * (a0 * i0 + a1 * i1 + a2 * i2 + a3 * i3)
             + b2[lane] + __half2float(skip47[(size_t)w * NCLS + lane]);
    float v1 = -1e30f;
    if (has2) {
        int c = lane + 32;
        v1 = 0.25f * (c0 * i0 + c1 * i1 + c2 * i2 + c3 * i3)
           + b2[c] + __half2float(skip47[(size_t)w * NCLS + c]);
    }
    float m = fmaxf(v0, v1);
#pragma unroll
    for (int o = 16; o; o >>= 1) m = fmaxf(m, __shfl_xor_sync(0xffffffffu, m, o));
    float s = expf(v0 - m) + (has2 ? expf(v1 - m) : 0.f);
#pragma unroll
    for (int o = 16; o; o >>= 1) s += __shfl_xor_sync(0xffffffffu, s, o);
    float lse = m + logf(s);
    outp[(size_t)w * NCLS + lane] = v0 - lse;
    if (has2) outp[(size_t)w * NCLS + lane + 32] = v1 - lse;
}

// ---------------- BN apply + ELU -> fp16 (also clears als/ald for next layer) -
__global__ void bn_apply_kernel(const __half* __restrict__ pre, const float* __restrict__ sums,
                                const float* __restrict__ gamma, const float* __restrict__ beta,
                                __half* __restrict__ oh,
                                float* __restrict__ als, float* __restrict__ ald)
{
    int c = threadIdx.x;
    int t = blockIdx.x * 256 + c;             // grid 512 -> 131072 >= NN*HEADS
    if (t < NN * HEADS) { als[t] = 0.f; ald[t] = 0.f; }
    float mu = sums[c] * (1.f / NN);
    float var = sums[HC + c] * (1.f / NN) - mu * mu;
    float rstd = rsqrtf(var + 1e-5f);
    float g = gamma[c] * rstd;
    float b = beta[c] - mu * g;
    for (int r = blockIdx.x; r < NN; r += gridDim.x) {
        size_t idx = (size_t)r * HC + c;
        float v = fmaf(__half2float(pre[idx]), g, b);
        float o = v > 0.f ? v : expf(v) - 1.f;
        oh[idx] = __float2half_rn(o);
    }
}

// ---------------- host orchestration ----------------
extern "C" void kernel_launch(void* const* d_in, const int* in_sizes, int n_in,
                              void* d_out, int out_size)
{
    const float* x   = (const float*)d_in[0];
    const int*   ei  = (const int*)d_in[1];
    const float* w0  = (const float*)d_in[2];
    const float* as0 = (const float*)d_in[3];
    const float* ad0 = (const float*)d_in[4];
    const float* b0  = (const float*)d_in[5];
    const float* sw0 = (const float*)d_in[6];
    const float* sb0 = (const float*)d_in[7];
    const float* g0  = (const float*)d_in[8];
    const float* be0 = (const float*)d_in[9];
    const float* w1  = (const float*)d_in[10];
    const float* as1 = (const float*)d_in[11];
    const float* ad1 = (const float*)d_in[12];
    const float* b1  = (const float*)d_in[13];
    const float* sw1 = (const float*)d_in[14];
    const float* sb1 = (const float*)d_in[15];
    const float* g1  = (const float*)d_in[16];
    const float* be1 = (const float*)d_in[17];
    const float* w2  = (const float*)d_in[18];
    const float* as2 = (const float*)d_in[19];
    const float* ad2 = (const float*)d_in[20];
    const float* b2  = (const float*)d_in[21];
    const float* sw2 = (const float*)d_in[22];
    const float* sb2 = (const float*)d_in[23];

    const int* src = ei;
    const int* dst = ei + EE;

    float *als, *ald, *bns0, *bns1;
    __half *h, *skip, *agg, *xh, *ah, *b0h, *b1h, *b2h;
    int *cnt, *part, *bsum, *rowptr, *cursor, *csrc;
    cudaGetSymbolAddress((void**)&h, g_h);
    cudaGetSymbolAddress((void**)&skip, g_skip);
    cudaGetSymbolAddress((void**)&agg, g_agg);
    cudaGetSymbolAddress((void**)&als, g_als);
    cudaGetSymbolAddress((void**)&ald, g_ald);
    cudaGetSymbolAddress((void**)&bns0, g_bnsum0);
    cudaGetSymbolAddress((void**)&bns1, g_bnsum1);
    cudaGetSymbolAddress((void**)&xh, g_xh);
    cudaGetSymbolAddress((void**)&ah, g_ah);
    cudaGetSymbolAddress((void**)&b0h, g_b0h);
    cudaGetSymbolAddress((void**)&b1h, g_b1h);
    cudaGetSymbolAddress((void**)&b2h, g_b2h);
    cudaGetSymbolAddress((void**)&cnt, g_cnt);
    cudaGetSymbolAddress((void**)&part, g_part);
    cudaGetSymbolAddress((void**)&bsum, g_bsum);
    cudaGetSymbolAddress((void**)&rowptr, g_rowptr);
    cudaGetSymbolAddress((void**)&cursor, g_cursor);
    cudaGetSymbolAddress((void**)&csrc, g_csrc);

    cudaFuncSetAttribute(hgemm_f16, cudaFuncAttributeMaxDynamicSharedMemorySize, SMEM_GEMM);

    static cudaStream_t s2 = nullptr;
    static cudaEvent_t evF = nullptr, evJ = nullptr;
    if (s2 == nullptr) {
        cudaStreamCreateWithFlags(&s2, cudaStreamNonBlocking);
        cudaEventCreateWithFlags(&evF, cudaEventDisableTiming);
        cudaEventCreateWithFlags(&evJ, cudaEventDisableTiming);
    }

    dim3 gemm512(4, (NN + BM - 1) / BM);
    dim3 gemm256(2, (NN + BM - 1) / BM);
    int nodeWarpBlocks = (NN * 32) / 256;
    int eBlocks = (EE + 255) / 256;

    prep_kernel<<<(NN * K0P + 255) / 256, 256>>>(x, xh, w0, sw0, w1, sw1, w2, sw2,
                                                 b0h, b1h, b2h, cnt, als, ald,
                                                 bns0, bns1);
    // fork: CSR build overlaps layer-0 GEMM
    cudaEventRecord(evF, 0);
    cudaStreamWaitEvent(s2, evF, 0);
    count_kernel<<<eBlocks, 256, 0, s2>>>(dst, cnt);
    scan_blocks<<<NBLK, 256, 0, s2>>>(cnt, part, bsum);
    scan_add<<<(NN + 256) / 256, 256, 0, s2>>>(part, bsum, rowptr, cursor);
    fill_kernel<<<eBlocks, 256, 0, s2>>>(src, dst, cursor, csrc);
    cudaEventRecord(evJ, s2);

    hgemm_f16<<<gemm512, 256, SMEM_GEMM>>>(xh, b0h, sb0, h, skip,
                                           as0, ad0, als, ald,
                                           NN, K0P, 512, HC, HC, HID);
    cudaStreamWaitEvent(0, evJ, 0);   // join before aggregation

    // ===== Layer 0 (agg + BN) =====
    gat_agg_kernel<<<nodeWarpBlocks, 256>>>(rowptr, csrc, h, als, ald, b0, skip, agg, bns0);
    bn_apply_kernel<<<512, 256>>>(agg, bns0, g0, be0, ah, als, ald);  // clears als/ald

    // ===== Layer 1 =====
    hgemm_f16<<<gemm512, 256, SMEM_GEMM>>>(ah, b1h, sb1, h, skip,
                                           as1, ad1, als, ald, NN, HC, 512, HC, HC, HID);
    gat_agg_kernel<<<nodeWarpBlocks, 256>>>(rowptr, csrc, h, als, ald, b1, skip, agg, bns1);
    bn_apply_kernel<<<512, 256>>>(agg, bns1, g1, be1, ah, als, ald);

    // ===== Layer 2 (logits fused into GEMM epilogue; al_kernel removed) =====
    hgemm_f16<<<gemm256, 256, SMEM_GEMM>>>(ah, b2h, sb2, h, skip,
                                           as2, ad2, als, ald,
                                           NN, HC, NP2, L2OUT, NCLS, NCLS);
    gat_agg47_fused<<<nodeWarpBlocks, 256>>>(rowptr, csrc, h, (const float4*)als,
                                             (const float4*)ald, b2, skip, (float*)d_out);
}

// round 16
// speedup vs baseline: 1.7408x; 1.0627x over previous
#include <cuda_runtime.h>
#include <cuda_bf16.h>
#include <cuda_fp16.h>
#include <cstdint>
#include <math.h>

#define NN 30000
#define EE 480000
#define F_IN 100
#define HID 64
#define HEADS 4
#define NCLS 47
#define HC 256           // HEADS*HID
#define L2OUT 188        // HEADS*NCLS
#define NP2 256          // padded pack width layer2 (188 + 47 -> 256)
#define K0P 128          // padded K for layer 0 (100 -> 128)
#define NBLK 118         // ceil(NN/256)

// ---------------- scratch ----------------
__device__ __align__(16) __half g_h[(size_t)NN * HC];    // GAT-branch GEMM out (fp16)
__device__ __align__(16) __half g_skip[(size_t)NN * HC]; // skip branch (fp16)
__device__ __align__(16) __half g_agg[(size_t)NN * HC];  // pre-BN (fp16; stats exact fp32)
__device__ __align__(16) float g_als[(size_t)NN * HEADS];
__device__ __align__(16) float g_ald[(size_t)NN * HEADS];
__device__ float g_bnsum0[2 * HC];
__device__ float g_bnsum1[2 * HC];
// fp16 activations (A-side)
__device__ __align__(16) __half g_xh[(size_t)NN * K0P];
__device__ __align__(16) __half g_ah[(size_t)NN * HC];
// fp16 transposed weights [n][k]
__device__ __align__(16) __half g_b0h[512 * K0P];
__device__ __align__(16) __half g_b1h[512 * HC];
__device__ __align__(16) __half g_b2h[NP2 * HC];
// CSR
__device__ int g_cnt[NN];
__device__ int g_part[NN];
__device__ int g_bsum[NBLK];
__device__ int g_rowptr[NN + 1];
__device__ int g_cursor[NN];
__device__ int g_csrc[EE];

__device__ __forceinline__ float lrelu(float x) { return x > 0.f ? x : 0.2f * x; }

// ---------------- prep A: convert x (vectorized), pack b0, zero buffers ------
__global__ void prep_a_kernel(const float* __restrict__ x, __half* __restrict__ xh,
                              const float* __restrict__ w0, const float* __restrict__ sw0,
                              __half* __restrict__ b0h,
                              int* __restrict__ cnt, float* __restrict__ als,
                              float* __restrict__ ald, float* __restrict__ bns0,
                              float* __restrict__ bns1)
{
    int idx4 = blockIdx.x * 256 + threadIdx.x;   // grid covers NN*K0P/4 = 960000
    if (idx4 < NN * (K0P / 4)) {
        int n = idx4 >> 5;                       // K0P/4 = 32 groups per row
        int c0 = (idx4 & 31) * 4;
        const float* xr = x + (size_t)n * F_IN;
        float v0 = (c0 + 0 < F_IN) ? xr[c0 + 0] : 0.f;
        float v1 = (c0 + 1 < F_IN) ? xr[c0 + 1] : 0.f;
        float v2 = (c0 + 2 < F_IN) ? xr[c0 + 2] : 0.f;
        float v3 = (c0 + 3 < F_IN) ? xr[c0 + 3] : 0.f;
        __half2 h0 = __floats2half2_rn(v0, v1);
        __half2 h1 = __floats2half2_rn(v2, v3);
        uint2 st = make_uint2(*(unsigned*)&h0, *(unsigned*)&h1);
        *(uint2*)(xh + (size_t)n * K0P + c0) = st;
    }
    int idx = idx4;
    if (idx < 512 * K0P) {
        int n = idx >> 7, k = idx & (K0P - 1);
        float v = 0.f;
        if (k < F_IN) v = (n < HC) ? w0[k * HC + n] : sw0[k * HC + (n - HC)];
        b0h[idx] = __float2half_rn(v);
    }
    if (idx < NN) cnt[idx] = 0;
    if (idx < NN * HEADS) { als[idx] = 0.f; ald[idx] = 0.f; }
    if (idx < 2 * HC) { bns0[idx] = 0.f; bns1[idx] = 0.f; }
}

// ---------------- prep B: pack b1/b2 (runs on side stream, overlapped) -------
__global__ void prep_b_kernel(const float* __restrict__ w1, const float* __restrict__ sw1,
                              const float* __restrict__ w2, const float* __restrict__ sw2,
                              __half* __restrict__ b1h, __half* __restrict__ b2h)
{
    int idx = blockIdx.x * 256 + threadIdx.x;    // grid covers 512*HC = 131072
    if (idx < 512 * HC) {
        int n = idx >> 8, k = idx & (HC - 1);
        float v = (n < HC) ? w1[k * HC + n] : sw1[k * HC + (n - HC)];
        b1h[idx] = __float2half_rn(v);
    }
    if (idx < NP2 * HC) {
        int n = idx >> 8, k = idx & (HC - 1);
        float v = 0.f;
        if (n < L2OUT) v = w2[k * L2OUT + n];
        else if (n < L2OUT + NCLS) v = sw2[k * NCLS + (n - L2OUT)];
        b2h[idx] = __float2half_rn(v);
    }
}

// ---------------- CSR build ----------------
__global__ void count_kernel(const int* __restrict__ dst, int* __restrict__ cnt)
{
    int e = blockIdx.x * blockDim.x + threadIdx.x;
    if (e < EE) atomicAdd(&cnt[dst[e]], 1);
}

__global__ void scan_blocks(const int* __restrict__ cnt, int* __restrict__ part,
                            int* __restrict__ bsum)
{
    int t = threadIdx.x;
    int i = blockIdx.x * 256 + t;
    int lane = t & 31, wid = t >> 5;
    int v = (i < NN) ? cnt[i] : 0;
    int x = v;
#pragma unroll
    for (int off = 1; off < 32; off <<= 1) {
        int y = __shfl_up_sync(0xffffffffu, x, off);
        if (lane >= off) x += y;
    }
    __shared__ int wsum[8];
    if (lane == 31) wsum[wid] = x;
    __syncthreads();
    if (wid == 0 && lane < 8) {
        int w = wsum[lane];
#pragma unroll
        for (int off = 1; off < 8; off <<= 1) {
            int y = __shfl_up_sync(0xffu, w, off);
            if (lane >= off) w += y;
        }
        wsum[lane] = w;
    }
    __syncthreads();
    int base = (wid > 0) ? wsum[wid - 1] : 0;
    int incl = x + base;
    if (i < NN) part[i] = incl - v;
    if (t == 255) bsum[blockIdx.x] = incl;
}

__global__ void scan_add(const int* __restrict__ part, const int* __restrict__ bsum,
                         int* __restrict__ rowptr, int* __restrict__ cursor)
{
    __shared__ int red[256];
    int b = blockIdx.x;
    int t = threadIdx.x;
    int acc = 0;
    for (int j = t; j < b; j += 256) acc += bsum[j];
    red[t] = acc;
    __syncthreads();
#pragma unroll
    for (int s = 128; s > 0; s >>= 1) {
        if (t < s) red[t] += red[t + s];
        __syncthreads();
    }
    int off = red[0];
    int i = b * 256 + t;
    if (i < NN) {
        int r = part[i] + off;
        rowptr[i] = r;
        cursor[i] = r;
    }
    if (i == NN) rowptr[NN] = EE;
}

__global__ void fill_kernel(const int* __restrict__ src, const int* __restrict__ dst,
                            int* __restrict__ cursor, int* __restrict__ csrc)
{
    int e = blockIdx.x * blockDim.x + threadIdx.x;
    if (e >= EE) return;
    int d = dst[e];
    int pos = atomicAdd(&cursor[d], 1);
    csrc[pos] = src[e];
}

// ---------------- pure fp16 tensor-core GEMM, 4-stage pipeline ------
#define BM 128
#define BN 128
#define BKK 32
#define BKP 40          // padded K stride in halves (80B rows, conflict-free ldmatrix)
#define OBH 5120
#define STGH 10240      // halves per stage
#define NSTG 4
#define SMEM_GEMM (NSTG * STGH * 2)   // 81920 bytes

__device__ __forceinline__ void mma16816(float* d, const unsigned* a, const unsigned* b)
{
    asm volatile(
        "mma.sync.aligned.m16n8k16.row.col.f32.f16.f16.f32 "
        "{%0,%1,%2,%3}, {%4,%5,%6,%7}, {%8,%9}, {%0,%1,%2,%3};"
        : "+f"(d[0]), "+f"(d[1]), "+f"(d[2]), "+f"(d[3])
        : "r"(a[0]), "r"(a[1]), "r"(a[2]), "r"(a[3]), "r"(b[0]), "r"(b[1]));
}

__device__ __forceinline__ void cp16(unsigned dst, const void* src, int sz)
{
    asm volatile("cp.async.cg.shared.global [%0], [%1], 16, %2;"
                 :: "r"(dst), "l"(src), "r"(sz));
}

__device__ __forceinline__ void ldm4(unsigned addr, unsigned& r0, unsigned& r1,
                                     unsigned& r2, unsigned& r3)
{
    asm volatile("ldmatrix.sync.aligned.m8n8.x4.shared.b16 {%0,%1,%2,%3}, [%4];"
                 : "=r"(r0), "=r"(r1), "=r"(r2), "=r"(r3) : "r"(addr));
}

__device__ __forceinline__ void issue_stage(
    unsigned sb, const __half* Ah, const __half* Bh,
    int rowBlock, int colBlock, int M, int KA, int k0, int sr, int sk)
{
#pragma unroll
    for (int i = 0; i < 2; i++) {
        int row = sr + i * 64;
        int gr = rowBlock + row;
        int sz = (gr < M) ? 16 : 0;
        size_t off = (size_t)(sz ? gr : 0) * KA + k0 + sk;
        cp16(sb + (unsigned)(row * BKP + sk) * 2, Ah + off, sz);
        int gc = colBlock + row;
        size_t boff = (size_t)gc * KA + k0 + sk;
        cp16(sb + (unsigned)(OBH + row * BKP + sk) * 2, Bh + boff, 16);
    }
    asm volatile("cp.async.commit_group;");
}

// headW: 64 for layers 0/1 (HID), 47 for layer 2 (NCLS); aS/aD stride = headW
__global__ __launch_bounds__(256, 2) void hgemm_f16(
    const __half* __restrict__ Ah, const __half* __restrict__ Bh,
    const float* __restrict__ sbias, __half* __restrict__ hOut, __half* __restrict__ skipOut,
    const float* __restrict__ aS, const float* __restrict__ aD,
    float* __restrict__ als, float* __restrict__ ald,
    int M, int KA, int Npack, int splitH, int splitS, int headW)
{
    extern __shared__ __half sm[];
    unsigned smB = (unsigned)__cvta_generic_to_shared(sm);

    int tid = threadIdx.x;
    int lane = tid & 31, wid = tid >> 5;
    int rowBlock = blockIdx.y * BM;
    int colBlock = blockIdx.x * BN;
    int wm = (wid & 1) * 64;
    int wn = (wid >> 1) * 32;
    int gID = lane >> 2, tig = lane & 3;

    float acc[4][4][4];
#pragma unroll
    for (int mt = 0; mt < 4; mt++)
#pragma unroll
        for (int nt = 0; nt < 4; nt++)
#pragma unroll
            for (int r = 0; r < 4; r++) acc[mt][nt][r] = 0.f;

    int kIters = KA >> 5;
    int sr = tid >> 2;
    int sk = (tid & 3) * 8;

    int aRow = (lane & 15);
    int aCol = (lane & 16) >> 1;
    int bNrow = (lane & 7) + ((lane & 16) >> 1);
    int bCol = (lane & 8);

    issue_stage(smB, Ah, Bh, rowBlock, colBlock, M, KA, 0, sr, sk);
    issue_stage(smB + 1u * STGH * 2, Ah, Bh, rowBlock, colBlock, M, KA, BKK, sr, sk);
    issue_stage(smB + 2u * STGH * 2, Ah, Bh, rowBlock, colBlock, M, KA, 2 * BKK, sr, sk);

    int cur = 0;
    for (int it = 0; it < kIters; it++) {
        int rem = kIters - 1 - it;
        if (rem >= 2)      asm volatile("cp.async.wait_group 2;");
        else if (rem == 1) asm volatile("cp.async.wait_group 1;");
        else               asm volatile("cp.async.wait_group 0;");
        __syncthreads();

        if (it + 3 < kIters) {
            int s3 = cur + 3; if (s3 >= NSTG) s3 -= NSTG;
            issue_stage(smB + (unsigned)s3 * STGH * 2, Ah, Bh,
                        rowBlock, colBlock, M, KA, (it + 3) * BKK, sr, sk);
        }

        unsigned aHb = smB + (unsigned)cur * STGH * 2;
        unsigned bHb = aHb + OBH * 2;

#pragma unroll
        for (int ks = 0; ks < 2; ks++) {
            int kk = ks * 16;
            unsigned bHf[8];
#pragma unroll
            for (int pair = 0; pair < 2; pair++) {
                int n = wn + pair * 16 + bNrow;
                unsigned off = (unsigned)(n * BKP + kk + bCol) * 2;
                ldm4(bHb + off, bHf[pair * 4 + 0], bHf[pair * 4 + 1],
                                bHf[pair * 4 + 2], bHf[pair * 4 + 3]);
            }
            unsigned aHf[4][4];
#pragma unroll
            for (int mt = 0; mt < 4; mt++) {
                int r = wm + mt * 16 + aRow;
                unsigned off = (unsigned)(r * BKP + kk + aCol) * 2;
                ldm4(aHb + off, aHf[mt][0], aHf[mt][1], aHf[mt][2], aHf[mt][3]);
            }
#pragma unroll
            for (int mt = 0; mt < 4; mt++)
#pragma unroll
                for (int nt = 0; nt < 4; nt++)
                    mma16816(acc[mt][nt], aHf[mt], &bHf[(nt >> 1) * 4 + (nt & 1) * 2]);
        }
        cur = (cur + 1 == NSTG) ? 0 : cur + 1;
    }

    // epilogue: route to hOut(fp16) / skipOut(fp16, +sbias)
    bool skipVec = ((splitS & 1) == 0);
#pragma unroll
    for (int mt = 0; mt < 4; mt++) {
        int gr0 = rowBlock + wm + mt * 16 + gID;
        int gr1 = gr0 + 8;
#pragma unroll
        for (int nt = 0; nt < 4; nt++) {
            int gc = colBlock + wn + nt * 8 + tig * 2;
#pragma unroll
            for (int half_ = 0; half_ < 2; half_++) {
                int gr = half_ ? gr1 : gr0;
                if (gr >= M) continue;
                float v0 = acc[mt][nt][half_ * 2 + 0];
                float v1 = acc[mt][nt][half_ * 2 + 1];
                if (gc < splitH) {
                    *(__half2*)(hOut + (size_t)gr * splitH + gc) =
                        __floats2half2_rn(v0, v1);
                } else if (skipVec && gc + 1 < splitH + splitS) {
                    int sc = gc - splitH;
                    *(__half2*)(skipOut + (size_t)gr * splitS + sc) =
                        __floats2half2_rn(v0 + sbias[sc], v1 + sbias[sc + 1]);
                } else {
#pragma unroll
                    for (int j = 0; j < 2; j++) {
                        int c2 = gc + j;
                        if (c2 < splitH + splitS) {
                            int sc = c2 - splitH;
                            skipOut[(size_t)gr * splitS + sc] =
                                __float2half_rn((j ? v1 : v0) + sbias[sc]);
                        }
                    }
                }
            }
        }
    }

    // fused attention-logit partials (window spans at most two heads)
    int base = colBlock + wn;
    if (aS != nullptr && base < splitH) {
        int hA = base / headW;
        int lastC = base + 31; if (lastC > splitH - 1) lastC = splitH - 1;
        int hB = lastC / headW;
        float cs[8], cd[8];
        int hd[8];
#pragma unroll
        for (int nt = 0; nt < 4; nt++)
#pragma unroll
            for (int j = 0; j < 2; j++) {
                int c = base + nt * 8 + tig * 2 + j;
                int k = nt * 2 + j;
                if (c < splitH) {
                    int hh = c / headW;
                    int lc = c - hh * headW;
                    cs[k] = aS[hh * headW + lc];
                    cd[k] = aD[hh * headW + lc];
                    hd[k] = hh;
                } else { cs[k] = 0.f; cd[k] = 0.f; hd[k] = hA; }
            }
#pragma unroll
        for (int mt = 0; mt < 4; mt++)
#pragma unroll
            for (int half_ = 0; half_ < 2; half_++) {
                int gr = rowBlock + wm + mt * 16 + gID + half_ * 8;
                float psA = 0.f, pdA = 0.f, psB = 0.f, pdB = 0.f;
#pragma unroll
                for (int k = 0; k < 8; k++) {
                    float v = acc[mt][k >> 1][half_ * 2 + (k & 1)];
                    float ts = v * cs[k];
                    float td = v * cd[k];
                    if (hd[k] == hA) { psA += ts; pdA += td; }
                    else             { psB += ts; pdB += td; }
                }
                psA += __shfl_xor_sync(0xffffffffu, psA, 1);
                psA += __shfl_xor_sync(0xffffffffu, psA, 2);
                pdA += __shfl_xor_sync(0xffffffffu, pdA, 1);
                pdA += __shfl_xor_sync(0xffffffffu, pdA, 2);
                if (hB != hA) {
                    psB += __shfl_xor_sync(0xffffffffu, psB, 1);
                    psB += __shfl_xor_sync(0xffffffffu, psB, 2);
                    pdB += __shfl_xor_sync(0xffffffffu, pdB, 1);
                    pdB += __shfl_xor_sync(0xffffffffu, pdB, 2);
                }
                if (tig == 0 && gr < M) {
                    atomicAdd(&als[gr * HEADS + hA], psA);
                    atomicAdd(&ald[gr * HEADS + hA], pdA);
                    if (hB != hA) {
                        atomicAdd(&als[gr * HEADS + hB], psB);
                        atomicAdd(&ald[gr * HEADS + hB], pdB);
                    }
                }
            }
    }
}

__device__ __forceinline__ void haccum(float e, uint4 u, float* ac)
{
    const __half2* p = (const __half2*)&u;
#pragma unroll
    for (int j = 0; j < 4; j++) {
        float2 f = __half22float2(p[j]);
        ac[2 * j]     = fmaf(e, f.x, ac[2 * j]);
        ac[2 * j + 1] = fmaf(e, f.y, ac[2 * j + 1]);
    }
}

// ---------------- fused GAT agg + bias + skip + BN-stats (layers 0/1) --------
__global__ __launch_bounds__(256) void gat_agg_kernel(
    const int* __restrict__ rowptr, const int* __restrict__ csrc,
    const __half* __restrict__ h, const float* __restrict__ als,
    const float* __restrict__ ald, const float* __restrict__ bias,
    const __half* __restrict__ skip, __half* __restrict__ outp, float* __restrict__ sums)
{
    __shared__ float slabS[8][HC];
    __shared__ float slabQ[8][HC];
    int tid = threadIdx.x;
    int w = (blockIdx.x * 256 + tid) >> 5;
    int lane = tid & 31;
    int wid = tid >> 5;
    int head = lane >> 3;
    float ad = ald[w * 4 + head];
    int beg = rowptr[w], end = rowptr[w + 1];
    float ac[8];
#pragma unroll
    for (int j = 0; j < 8; j++) ac[j] = 0.f;
    float den = 0.f;
    int i = beg;
    for (; i + 4 <= end; i += 4) {
        int s0 = csrc[i], s1 = csrc[i + 1], s2 = csrc[i + 2], s3 = csrc[i + 3];
        float A0 = als[s0 * 4 + head], A1 = als[s1 * 4 + head];
        float A2 = als[s2 * 4 + head], A3 = als[s3 * 4 + head];
        uint4 u0 = ((const uint4*)(h + (size_t)s0 * HC))[lane];
        uint4 u1 = ((const uint4*)(h + (size_t)s1 * HC))[lane];
        uint4 u2 = ((const uint4*)(h + (size_t)s2 * HC))[lane];
        uint4 u3 = ((const uint4*)(h + (size_t)s3 * HC))[lane];
        float e0 = expf(lrelu(A0 + ad));
        float e1 = expf(lrelu(A1 + ad));
        float e2 = expf(lrelu(A2 + ad));
        float e3 = expf(lrelu(A3 + ad));
        den += (e0 + e1) + (e2 + e3);
        haccum(e0, u0, ac);
        haccum(e1, u1, ac);
        haccum(e2, u2, ac);
        haccum(e3, u3, ac);
    }
    for (; i < end; i++) {
        int s = csrc[i];
        float e = expf(lrelu(als[s * 4 + head] + ad));
        den += e;
        uint4 u = ((const uint4*)(h + (size_t)s * HC))[lane];
        haccum(e, u, ac);
    }
    float inv = 1.f / (den + 1e-16f);
    int cbase = lane * 8;
    size_t obase = (size_t)w * HC + cbase;
    const float4* bp = (const float4*)(bias + cbase);
    float4 b0 = bp[0], b1 = bp[1];
    uint4 su = *(const uint4*)(skip + obase);
    float sf[8];
    {
        const __half2* p = (const __half2*)&su;
#pragma unroll
        for (int j = 0; j < 4; j++) {
            float2 f = __half22float2(p[j]);
            sf[2 * j] = f.x; sf[2 * j + 1] = f.y;
        }
    }
    float o[8];
    o[0] = fmaf(ac[0], inv, b0.x + sf[0]); o[1] = fmaf(ac[1], inv, b0.y + sf[1]);
    o[2] = fmaf(ac[2], inv, b0.z + sf[2]); o[3] = fmaf(ac[3], inv, b0.w + sf[3]);
    o[4] = fmaf(ac[4], inv, b1.x + sf[4]); o[5] = fmaf(ac[5], inv, b1.y + sf[5]);
    o[6] = fmaf(ac[6], inv, b1.z + sf[6]); o[7] = fmaf(ac[7], inv, b1.w + sf[7]);
    uint4 st;
    __half2* stp = (__half2*)&st;
#pragma unroll
    for (int j = 0; j < 4; j++) stp[j] = __floats2half2_rn(o[2 * j], o[2 * j + 1]);
    *(uint4*)(outp + obase) = st;

#pragma unroll
    for (int j = 0; j < 8; j++) {
        slabS[wid][cbase + j] = o[j];
        slabQ[wid][cbase + j] = o[j] * o[j];
    }
    __syncthreads();
    float s = 0.f, q = 0.f;
#pragma unroll
    for (int ww = 0; ww < 8; ww++) { s += slabS[ww][tid]; q += slabQ[ww][tid]; }
    atomicAdd(&sums[tid], s);
    atomicAdd(&sums[HC + tid], q);
}

// ---------------- layer 2: agg + mean heads + bias + skip + log_softmax ------
__global__ __launch_bounds__(256) void gat_agg47_fused(
    const int* __restrict__ rowptr, const int* __restrict__ csrc,
    const __half* __restrict__ h, const float4* __restrict__ als,
    const float4* __restrict__ ald, const float* __restrict__ b2,
    const __half* __restrict__ skip47, float* __restrict__ outp)
{
    int w = (blockIdx.x * blockDim.x + threadIdx.x) >> 5;
    int lane = threadIdx.x & 31;
    if (w >= NN) return;
    float4 ad = ald[w];
    int beg = rowptr[w], end = rowptr[w + 1];
    float a0 = 0.f, a1 = 0.f, a2 = 0.f, a3 = 0.f;
    float c0 = 0.f, c1 = 0.f, c2 = 0.f, c3 = 0.f;
    float d0 = 0.f, d1 = 0.f, d2 = 0.f, d3 = 0.f;
    bool has2 = (lane + 32) < NCLS;
    for (int i = beg; i < end; i++) {
        int s = csrc[i];
        float4 as4 = als[s];
        float e0 = expf(lrelu(as4.x + ad.x));
        float e1 = expf(lrelu(as4.y + ad.y));
        float e2 = expf(lrelu(as4.z + ad.z));
        float e3 = expf(lrelu(as4.w + ad.w));
        d0 += e0; d1 += e1; d2 += e2; d3 += e3;
        const __half* hs = h + (size_t)s * L2OUT;
        a0 = fmaf(e0, __half2float(hs[lane]), a0);
        a1 = fmaf(e1, __half2float(hs[NCLS + lane]), a1);
        a2 = fmaf(e2, __half2float(hs[2 * NCLS + lane]), a2);
        a3 = fmaf(e3, __half2float(hs[3 * NCLS + lane]), a3);
        if (has2) {
            int c = lane + 32;
            c0 = fmaf(e0, __half2float(hs[c]), c0);
            c1 = fmaf(e1, __half2float(hs[NCLS + c]), c1);
            c2 = fmaf(e2, __half2float(hs[2 * NCLS + c]), c2);
            c3 = fmaf(e3, __half2float(hs[3 * NCLS + c]), c3);
        }
    }
    float i0 = 1.f / (d0 + 1e-16f), i1 = 1.f / (d1 + 1e-16f);
    float i2 = 1.f / (d2 + 1e-16f), i3 = 1.f / (d3 + 1e-16f);
    float v0 = 0.25f * (a0 * i0 + a1 * i1 + a2 * i2 + a3 * i3)
             + b2[lane] + __half2float(skip47[(size_t)w * NCLS + lane]);
    float v1 = -1e30f;
    if (has2) {
        int c = lane + 32;
        v1 = 0.25f * (c0 * i0 + c1 * i1 + c2 * i2 + c3 * i3)
           + b2[c] + __half2float(skip47[(size_t)w * NCLS + c]);
    }
    float m = fmaxf(v0, v1);
#pragma unroll
    for (int o = 16; o; o >>= 1) m = fmaxf(m, __shfl_xor_sync(0xffffffffu, m, o));
    float s = expf(v0 - m) + (has2 ? expf(v1 - m) : 0.f);
#pragma unroll
    for (int o = 16; o; o >>= 1) s += __shfl_xor_sync(0xffffffffu, s, o);
    float lse = m + logf(s);
    outp[(size_t)w * NCLS + lane] = v0 - lse;
    if (has2) outp[(size_t)w * NCLS + lane + 32] = v1 - lse;
}

// ---------------- BN apply + ELU -> fp16 (also clears als/ald for next layer) -
__global__ void bn_apply_kernel(const __half* __restrict__ pre, const float* __restrict__ sums,
                                const float* __restrict__ gamma, const float* __restrict__ beta,
                                __half* __restrict__ oh,
                                float* __restrict__ als, float* __restrict__ ald)
{
    int c = threadIdx.x;
    int t = blockIdx.x * 256 + c;             // grid 1024 -> covers NN*HEADS
    if (t < NN * HEADS) { als[t] = 0.f; ald[t] = 0.f; }
    float mu = sums[c] * (1.f / NN);
    float var = sums[HC + c] * (1.f / NN) - mu * mu;
    float rstd = rsqrtf(var + 1e-5f);
    float g = gamma[c] * rstd;
    float b = beta[c] - mu * g;
    for (int r = blockIdx.x; r < NN; r += gridDim.x) {
        size_t idx = (size_t)r * HC + c;
        float v = fmaf(__half2float(pre[idx]), g, b);
        float o = v > 0.f ? v : expf(v) - 1.f;
        oh[idx] = __float2half_rn(o);
    }
}

// ---------------- host orchestration ----------------
extern "C" void kernel_launch(void* const* d_in, const int* in_sizes, int n_in,
                              void* d_out, int out_size)
{
    const float* x   = (const float*)d_in[0];
    const int*   ei  = (const int*)d_in[1];
    const float* w0  = (const float*)d_in[2];
    const float* as0 = (const float*)d_in[3];
    const float* ad0 = (const float*)d_in[4];
    const float* b0  = (const float*)d_in[5];
    const float* sw0 = (const float*)d_in[6];
    const float* sb0 = (const float*)d_in[7];
    const float* g0  = (const float*)d_in[8];
    const float* be0 = (const float*)d_in[9];
    const float* w1  = (const float*)d_in[10];
    const float* as1 = (const float*)d_in[11];
    const float* ad1 = (const float*)d_in[12];
    const float* b1  = (const float*)d_in[13];
    const float* sw1 = (const float*)d_in[14];
    const float* sb1 = (const float*)d_in[15];
    const float* g1  = (const float*)d_in[16];
    const float* be1 = (const float*)d_in[17];
    const float* w2  = (const float*)d_in[18];
    const float* as2 = (const float*)d_in[19];
    const float* ad2 = (const float*)d_in[20];
    const float* b2  = (const float*)d_in[21];
    const float* sw2 = (const float*)d_in[22];
    const float* sb2 = (const float*)d_in[23];

    const int* src = ei;
    const int* dst = ei + EE;

    float *als, *ald, *bns0, *bns1;
    __half *h, *skip, *agg, *xh, *ah, *b0h, *b1h, *b2h;
    int *cnt, *part, *bsum, *rowptr, *cursor, *csrc;
    cudaGetSymbolAddress((void**)&h, g_h);
    cudaGetSymbolAddress((void**)&skip, g_skip);
    cudaGetSymbolAddress((void**)&agg, g_agg);
    cudaGetSymbolAddress((void**)&als, g_als);
    cudaGetSymbolAddress((void**)&ald, g_ald);
    cudaGetSymbolAddress((void**)&bns0, g_bnsum0);
    cudaGetSymbolAddress((void**)&bns1, g_bnsum1);
    cudaGetSymbolAddress((void**)&xh, g_xh);
    cudaGetSymbolAddress((void**)&ah, g_ah);
    cudaGetSymbolAddress((void**)&b0h, g_b0h);
    cudaGetSymbolAddress((void**)&b1h, g_b1h);
    cudaGetSymbolAddress((void**)&b2h, g_b2h);
    cudaGetSymbolAddress((void**)&cnt, g_cnt);
    cudaGetSymbolAddress((void**)&part, g_part);
    cudaGetSymbolAddress((void**)&bsum, g_bsum);
    cudaGetSymbolAddress((void**)&rowptr, g_rowptr);
    cudaGetSymbolAddress((void**)&cursor, g_cursor);
    cudaGetSymbolAddress((void**)&csrc, g_csrc);

    cudaFuncSetAttribute(hgemm_f16, cudaFuncAttributeMaxDynamicSharedMemorySize, SMEM_GEMM);

    static cudaStream_t s2 = nullptr;
    static cudaEvent_t evF = nullptr, evJ = nullptr, evJ2 = nullptr;
    if (s2 == nullptr) {
        cudaStreamCreateWithFlags(&s2, cudaStreamNonBlocking);
        cudaEventCreateWithFlags(&evF, cudaEventDisableTiming);
        cudaEventCreateWithFlags(&evJ, cudaEventDisableTiming);
        cudaEventCreateWithFlags(&evJ2, cudaEventDisableTiming);
    }

    dim3 gemm512(4, (NN + BM - 1) / BM);
    dim3 gemm256(2, (NN + BM - 1) / BM);
    int nodeWarpBlocks = (NN * 32) / 256;
    int eBlocks = (EE + 255) / 256;

    prep_a_kernel<<<(NN * (K0P / 4) + 255) / 256, 256>>>(x, xh, w0, sw0, b0h,
                                                         cnt, als, ald, bns0, bns1);
    // fork: CSR build + b1/b2 packing overlap layer-0 GEMM / layer-0 agg
    cudaEventRecord(evF, 0);
    cudaStreamWaitEvent(s2, evF, 0);
    count_kernel<<<eBlocks, 256, 0, s2>>>(dst, cnt);
    scan_blocks<<<NBLK, 256, 0, s2>>>(cnt, part, bsum);
    scan_add<<<(NN + 256) / 256, 256, 0, s2>>>(part, bsum, rowptr, cursor);
    fill_kernel<<<eBlocks, 256, 0, s2>>>(src, dst, cursor, csrc);
    cudaEventRecord(evJ, s2);
    prep_b_kernel<<<512, 256, 0, s2>>>(w1, sw1, w2, sw2, b1h, b2h);
    cudaEventRecord(evJ2, s2);

    hgemm_f16<<<gemm512, 256, SMEM_GEMM>>>(xh, b0h, sb0, h, skip,
                                           as0, ad0, als, ald,
                                           NN, K0P, 512, HC, HC, HID);
    cudaStreamWaitEvent(0, evJ, 0);   // CSR ready before aggregation

    // ===== Layer 0 (agg + BN) =====
    gat_agg_kernel<<<nodeWarpBlocks, 256>>>(rowptr, csrc, h, als, ald, b0, skip, agg, bns0);
    bn_apply_kernel<<<1024, 256>>>(agg, bns0, g0, be0, ah, als, ald);  // clears als/ald

    // ===== Layer 1 =====
    cudaStreamWaitEvent(0, evJ2, 0);  // b1h/b2h ready
    hgemm_f16<<<gemm512, 256, SMEM_GEMM>>>(ah, b1h, sb1, h, skip,
                                           as1, ad1, als, ald, NN, HC, 512, HC, HC, HID);
    gat_agg_kernel<<<nodeWarpBlocks, 256>>>(rowptr, csrc, h, als, ald, b1, skip, agg, bns1);
    bn_apply_kernel<<<1024, 256>>>(agg, bns1, g1, be1, ah, als, ald);

    // ===== Layer 2 (logits fused into GEMM epilogue) =====
    hgemm_f16<<<gemm256, 256, SMEM_GEMM>>>(ah, b2h, sb2, h, skip,
                                           as2, ad2, als, ald,
                                           NN, HC, NP2, L2OUT, NCLS, NCLS);
    gat_agg47_fused<<<nodeWarpBlocks, 256>>>(rowptr, csrc, h, (const float4*)als,
                                             (const float4*)ald, b2, skip, (float*)d_out);
}